// round 2
// baseline (speedup 1.0000x reference)
#include <cuda_runtime.h>
#include <cstdint>

typedef unsigned long long ull;

#define B_  32
#define D_  1024
#define H_  1024
#define M_  2048
#define K3_ 3072

// ---------------- scratch (static device globals; no allocation) ----------------
__device__ float g_xT[D_ * B_];             // x transposed [k][b]
__device__ float g_comb[K3_ * B_];          // combined, [k][b]: rows 0..1023 = z, 1024..2047 = m_t, 2048..3071 = prev_h
__device__ float g_zinv[B_];                // 1/||z|| per batch row
__device__ float g_encp[4 * H_ * B_];       // enc GEMM split-K partials
__device__ float g_simp[4 * M_ * B_];       // sim dot partials per h-split
__device__ float g_ssp[4 * M_];             // eff_mem sumsq partials per h-split
__device__ float g_attn[M_ * B_];           // attn transposed [m][b]
__device__ float g_mtp[16 * H_ * B_];       // m_t split-M partials
__device__ float g_intp[8 * K3_ * B_];      // W_int GEMM split-K partials
__device__ float g_hid[K3_ * B_];           // hidden, [n][b]
__device__ float g_outp[16 * H_ * B_];      // W_out GEMM split-K partials

// ---------------- helpers ----------------
__device__ __forceinline__ ull pack2(float w) {
    ull r; asm("mov.b64 %0, {%1, %1};" : "=l"(r) : "f"(w)); return r;
}
__device__ __forceinline__ void fma2(ull& d, ull a, ull b) {
    asm("fma.rn.f32x2 %0, %1, %2, %0;" : "+l"(d) : "l"(a), "l"(b));
}
__device__ __forceinline__ float hadd2(ull a) {
    float2 f = *reinterpret_cast<float2*>(&a); return f.x + f.y;
}

__device__ __forceinline__ float bsum256(float v, float* sb) {
    int tx = threadIdx.x;
#pragma unroll
    for (int o = 16; o > 0; o >>= 1) v += __shfl_xor_sync(0xffffffffu, v, o);
    if ((tx & 31) == 0) sb[tx >> 5] = v;
    __syncthreads();
    float r = (tx < 8) ? sb[tx] : 0.f;
    if (tx < 32) {
#pragma unroll
        for (int o = 4; o > 0; o >>= 1) r += __shfl_xor_sync(0xffffffffu, r, o);
        if (tx == 0) sb[0] = r;
    }
    __syncthreads();
    r = sb[0];
    __syncthreads();
    return r;
}
__device__ __forceinline__ float bmax256(float v, float* sb) {
    int tx = threadIdx.x;
#pragma unroll
    for (int o = 16; o > 0; o >>= 1) v = fmaxf(v, __shfl_xor_sync(0xffffffffu, v, o));
    if ((tx & 31) == 0) sb[tx >> 5] = v;
    __syncthreads();
    float r = (tx < 8) ? sb[tx] : -3.0e38f;
    if (tx < 32) {
#pragma unroll
        for (int o = 4; o > 0; o >>= 1) r = fmaxf(r, __shfl_xor_sync(0xffffffffu, r, o));
        if (tx == 0) sb[0] = r;
    }
    __syncthreads();
    r = sb[0];
    __syncthreads();
    return r;
}

// jax threefry2x32, key = (0, 42). Partitionable scheme: per element e,
// counter = (hi32(e), lo32(e)) = (0, e) since e < 2^32; bits = o0 ^ o1.
__device__ __forceinline__ uint32_t rotl32(uint32_t x, int r) { return (x << r) | (x >> (32 - r)); }
__device__ __forceinline__ uint32_t threefry_xor(uint32_t c0, uint32_t c1) {
    const uint32_t ks0 = 0u, ks1 = 42u, ks2 = 0u ^ 42u ^ 0x1BD11BDAu;
    uint32_t x0 = c0 + ks0, x1 = c1 + ks1;
#define TF_R4(a,b,c,d) \
    x0 += x1; x1 = rotl32(x1,a); x1 ^= x0; \
    x0 += x1; x1 = rotl32(x1,b); x1 ^= x0; \
    x0 += x1; x1 = rotl32(x1,c); x1 ^= x0; \
    x0 += x1; x1 = rotl32(x1,d); x1 ^= x0;
    TF_R4(13,15,26,6)  x0 += ks1; x1 += ks2 + 1u;
    TF_R4(17,29,16,24) x0 += ks2; x1 += ks0 + 2u;
    TF_R4(13,15,26,6)  x0 += ks0; x1 += ks1 + 3u;
    TF_R4(17,29,16,24) x0 += ks1; x1 += ks2 + 4u;
    TF_R4(13,15,26,6)  x0 += ks2; x1 += ks0 + 5u;
#undef TF_R4
    return x0 ^ x1;
}
// jax: uniform in [nextafter(-1,0), 1), then sqrt(2)*erfinv(u)
__device__ __forceinline__ float bits2normal(uint32_t bits) {
    uint32_t fb = (bits >> 9) | 0x3F800000u;
    float u01 = __uint_as_float(fb) - 1.0f;
    const float lo = -0.99999994f;
    float u = fmaf(u01, 1.99999994f, lo);
    u = fmaxf(lo, u);
    return 1.4142135623730951f * erfinvf(u);
}

// ---------------- kernels ----------------

// x [32][1024] -> g_xT [k][b]
__global__ void k_transpose(const float* __restrict__ x) {
    int idx = blockIdx.x * 256 + threadIdx.x;         // 32768 total
    int b = idx >> 10, k = idx & 1023;
    g_xT[k * B_ + b] = x[idx];
}

// generic split-K GEMM: P[ksplit][n][b] = sum_{k in split} A[k][b] * W[k][n]
__global__ void k_gemmT(const float* __restrict__ A, const float* __restrict__ W,
                        float* __restrict__ P, int N, int Kper, int kchunk) {
    __shared__ float as[128 * B_];
    int n = blockIdx.x * 128 + threadIdx.x;
    int k0 = blockIdx.y * Kper;
    ull acc[16];
#pragma unroll
    for (int j = 0; j < 16; ++j) acc[j] = 0ull;

    for (int kc = 0; kc < Kper; kc += kchunk) {
        int kn = min(kchunk, Kper - kc);
        for (int i = threadIdx.x; i < kn * B_; i += 128)
            as[i] = A[(k0 + kc) * B_ + i];
        __syncthreads();
#pragma unroll 2
        for (int kk = 0; kk < kn; ++kk) {
            float w = W[(size_t)(k0 + kc + kk) * N + n];
            ull w2 = pack2(w);
            const ulonglong2* ap = reinterpret_cast<const ulonglong2*>(&as[kk * B_]);
#pragma unroll
            for (int j = 0; j < 8; ++j) {
                ulonglong2 a2 = ap[j];
                fma2(acc[2 * j], a2.x, w2);
                fma2(acc[2 * j + 1], a2.y, w2);
            }
        }
        __syncthreads();
    }
    ull* dst = reinterpret_cast<ull*>(P + ((size_t)blockIdx.y * N + n) * B_);
#pragma unroll
    for (int j = 0; j < 16; ++j) dst[j] = acc[j];
}

// sum enc partials + bias, relu, layernorm -> z into comb rows [0,1024); also prev_h -> rows [2048,3072); zinv
__global__ void k_encfin(const float* __restrict__ b_enc, const float* __restrict__ gamma1,
                         const float* __restrict__ beta1, const float* __restrict__ prev_h) {
    __shared__ float sb[8];
    int b = blockIdx.x, tx = threadIdx.x;
    float v[4], ls = 0.f, lss = 0.f;
#pragma unroll
    for (int j = 0; j < 4; ++j) {
        int h = tx + j * 256;
        float s = b_enc[h];
#pragma unroll
        for (int p = 0; p < 4; ++p) s += g_encp[p * (H_ * B_) + h * B_ + b];
        s = fmaxf(s, 0.f);
        v[j] = s; ls += s; lss += s * s;
    }
    float mean = bsum256(ls, sb) * (1.0f / H_);
    float msq  = bsum256(lss, sb) * (1.0f / H_);
    float rstd = rsqrtf(msq - mean * mean + 1e-6f);
    float zss = 0.f;
#pragma unroll
    for (int j = 0; j < 4; ++j) {
        int h = tx + j * 256;
        float z = (v[j] - mean) * rstd * gamma1[h] + beta1[h];
        g_comb[h * B_ + b] = z;
        zss += z * z;
        g_comb[(2048 + h) * B_ + b] = prev_h[b * H_ + h];
    }
    float zs = bsum256(zss, sb);
    if (tx == 0) g_zinv[b] = rsqrtf(fmaxf(zs, 1e-12f));
}

// cosine-sim partials: per h-slice of 256, per m: dot with all 32 z rows + eff_mem sumsq
__global__ void k_sim(const float* __restrict__ bank, const float* __restrict__ trace) {
    __shared__ float zs[256 * B_];
    __shared__ float red[8][32];
    __shared__ float red_ss[8];
    int hs = blockIdx.x;            // 0..3
    int mb = blockIdx.y;            // 0..31
    int tx = threadIdx.x, w = tx >> 5, lane = tx & 31;

    for (int i = tx; i < 256 * B_; i += 256) zs[i] = g_comb[hs * 256 * B_ + i];
    __syncthreads();

    int hbase = hs * 256 + w * 32;
    for (int mi = 0; mi < 64; ++mi) {
        int m = mb * 64 + mi;
        float bv = bank[(size_t)m * H_ + hbase + lane];
        float tv = trace[(size_t)m * H_ + hbase + lane];
        float em = bv + 0.5f * tv;
        float d0 = 0.f, d1 = 0.f;
#pragma unroll
        for (int i = 0; i < 32; i += 2) {
            float e0 = __shfl_sync(0xffffffffu, em, i);
            float e1 = __shfl_sync(0xffffffffu, em, i + 1);
            d0 = fmaf(e0, zs[(w * 32 + i) * B_ + lane], d0);
            d1 = fmaf(e1, zs[(w * 32 + i + 1) * B_ + lane], d1);
        }
        float ss = em * em;
#pragma unroll
        for (int o = 16; o > 0; o >>= 1) ss += __shfl_xor_sync(0xffffffffu, ss, o);
        red[w][lane] = d0 + d1;
        if (lane == 0) red_ss[w] = ss;
        __syncthreads();
        if (tx < 32) {
            float dot = 0.f, sst = 0.f;
#pragma unroll
            for (int ww = 0; ww < 8; ++ww) { dot += red[ww][tx]; sst += red_ss[ww]; }
            g_simp[hs * (M_ * B_) + m * B_ + tx] = dot;
            if (tx == 0) g_ssp[hs * M_ + m] = sst;
        }
        __syncthreads();
    }
}

// softmax over M per batch row; writes attn transposed [m][b]
__global__ void k_softmax() {
    __shared__ float sb[8];
    int b = blockIdx.x, tx = threadIdx.x;
    float zi = g_zinv[b];
    float s[8];
    float mx = -3.0e38f;
#pragma unroll
    for (int j = 0; j < 8; ++j) {
        int m = tx + j * 256;
        float dot = g_simp[0 * (M_ * B_) + m * B_ + b] + g_simp[1 * (M_ * B_) + m * B_ + b]
                  + g_simp[2 * (M_ * B_) + m * B_ + b] + g_simp[3 * (M_ * B_) + m * B_ + b];
        float ss = g_ssp[m] + g_ssp[M_ + m] + g_ssp[2 * M_ + m] + g_ssp[3 * M_ + m];
        float v = dot * zi * rsqrtf(fmaxf(ss, 1e-12f)) * (1.0f / 0.75f);
        s[j] = v; mx = fmaxf(mx, v);
    }
    mx = bmax256(mx, sb);
    float sum = 0.f;
#pragma unroll
    for (int j = 0; j < 8; ++j) { s[j] = expf(s[j] - mx); sum += s[j]; }
    sum = bsum256(sum, sb);
    float inv = 1.0f / sum;
#pragma unroll
    for (int j = 0; j < 8; ++j) g_attn[(tx + j * 256) * B_ + b] = s[j] * inv;
}

// m_t split-M partials: P[ms][h][b] = sum_{m in split} attn[m][b] * eff_mem[m][h]
__global__ void k_mt(const float* __restrict__ bank, const float* __restrict__ trace) {
    __shared__ float as[128 * B_];
    int h = blockIdx.x * 128 + threadIdx.x;
    int m0 = blockIdx.y * 128;
    ull acc[16];
#pragma unroll
    for (int j = 0; j < 16; ++j) acc[j] = 0ull;
    for (int i = threadIdx.x; i < 128 * B_; i += 128) as[i] = g_attn[m0 * B_ + i];
    __syncthreads();
#pragma unroll 2
    for (int k = 0; k < 128; ++k) {
        int m = m0 + k;
        float em = bank[(size_t)m * H_ + h] + 0.5f * trace[(size_t)m * H_ + h];
        ull w2 = pack2(em);
        const ulonglong2* ap = reinterpret_cast<const ulonglong2*>(&as[k * B_]);
#pragma unroll
        for (int j = 0; j < 8; ++j) {
            ulonglong2 a2 = ap[j];
            fma2(acc[2 * j], a2.x, w2);
            fma2(acc[2 * j + 1], a2.y, w2);
        }
    }
    ull* dst = reinterpret_cast<ull*>(&g_mtp[(size_t)blockIdx.y * (H_ * B_) + h * B_]);
#pragma unroll
    for (int j = 0; j < 16; ++j) dst[j] = acc[j];
}

// reduce m_t partials into comb rows [1024,2048)
__global__ void k_combmt() {
    int idx = blockIdx.x * 256 + threadIdx.x;  // 32768
    float s = 0.f;
#pragma unroll
    for (int p = 0; p < 16; ++p) s += g_mtp[p * (H_ * B_) + idx];
    g_comb[H_ * B_ + idx] = s;
}

// reduce W_int partials + bias, relu -> hidden [n][b]
__global__ void k_intfin(const float* __restrict__ b_int) {
    int idx = blockIdx.x * 256 + threadIdx.x;  // 98304
    int n = idx >> 5;
    float s = b_int[n];
#pragma unroll
    for (int p = 0; p < 8; ++p) s += g_intp[p * (K3_ * B_) + idx];
    g_hid[idx] = fmaxf(s, 0.f);
}

// reduce W_out partials + bias, relu, layernorm -> h_t into d_out[0..32768)
__global__ void k_outfin(const float* __restrict__ b_out, const float* __restrict__ gamma2,
                         const float* __restrict__ beta2, float* __restrict__ out) {
    __shared__ float sb[8];
    int b = blockIdx.x, tx = threadIdx.x;
    float v[4], ls = 0.f, lss = 0.f;
#pragma unroll
    for (int j = 0; j < 4; ++j) {
        int h = tx + j * 256;
        float s = b_out[h];
#pragma unroll
        for (int p = 0; p < 16; ++p) s += g_outp[p * (H_ * B_) + h * B_ + b];
        s = fmaxf(s, 0.f);
        v[j] = s; ls += s; lss += s * s;
    }
    float mean = bsum256(ls, sb) * (1.0f / H_);
    float msq  = bsum256(lss, sb) * (1.0f / H_);
    float rstd = rsqrtf(msq - mean * mean + 1e-6f);
#pragma unroll
    for (int j = 0; j < 4; ++j) {
        int h = tx + j * 256;
        out[b * H_ + h] = (v[j] - mean) * rstd * gamma2[h] + beta2[h];
    }
}

// Hebbian trace update + jax threefry noise (partitionable); writes d_out[32768 ..)
__global__ void k_trace(const float* __restrict__ trace, float* __restrict__ out) {
    __shared__ float as[16 * B_];
    int tx = threadIdx.x;                  // 128
    int h = blockIdx.x * 128 + tx;
    int m0 = blockIdx.y * 8;               // m0 < 1024
    for (int i = tx; i < 16 * B_; i += 128) {
        int r = i >> 5, b = i & 31;
        int m = (r < 8) ? (m0 + r) : (1024 + m0 + r - 8);
        as[i] = g_attn[m * B_ + b];
    }
    __syncthreads();
    ull z2[16];
    const ull* zp = reinterpret_cast<const ull*>(&g_comb[h * B_]);
#pragma unroll
    for (int j = 0; j < 16; ++j) z2[j] = zp[j];

    for (int mi = 0; mi < 8; ++mi) {
        int m = m0 + mi;
        ull a0 = 0ull, a1 = 0ull;
        const ull* ap0 = reinterpret_cast<const ull*>(&as[mi * B_]);
        const ull* ap1 = reinterpret_cast<const ull*>(&as[(8 + mi) * B_]);
#pragma unroll
        for (int j = 0; j < 16; ++j) { fma2(a0, ap0[j], z2[j]); fma2(a1, ap1[j], z2[j]); }
        float s0 = hadd2(a0), s1 = hadd2(a1);

        uint32_t e0 = (uint32_t)(m * 1024 + h);          // element index, first half
        uint32_t e1 = e0 + 1048576u;                      // (m+1024)*1024 + h
        float n0 = bits2normal(threefry_xor(0u, e0)) * 0.001f;
        float n1 = bits2normal(threefry_xor(0u, e1)) * 0.001f;

        float t0 = trace[(size_t)m * H_ + h];
        float t1 = trace[(size_t)(m + 1024) * H_ + h];
        float r0 = t0 * 0.95f + 0.05f * (s0 * (1.0f / 32.0f) + n0);
        float r1 = t1 * 0.95f + 0.05f * (s1 * (1.0f / 32.0f) + n1);
        out[32768 + m * 1024 + h] = fminf(fmaxf(r0, -0.1f), 0.1f);
        out[32768 + (m + 1024) * 1024 + h] = fminf(fmaxf(r1, -0.1f), 0.1f);
    }
}

// ---------------- launch ----------------
extern "C" void kernel_launch(void* const* d_in, const int* in_sizes, int n_in,
                              void* d_out, int out_size) {
    const float* x      = (const float*)d_in[0];
    const float* prev_h = (const float*)d_in[1];
    const float* trace  = (const float*)d_in[2];
    const float* bank   = (const float*)d_in[3];
    const float* W_enc  = (const float*)d_in[4];
    const float* b_enc  = (const float*)d_in[5];
    const float* gamma1 = (const float*)d_in[6];
    const float* beta1  = (const float*)d_in[7];
    const float* W_int  = (const float*)d_in[8];
    const float* b_int  = (const float*)d_in[9];
    const float* W_out  = (const float*)d_in[10];
    const float* b_out  = (const float*)d_in[11];
    const float* gamma2 = (const float*)d_in[12];
    const float* beta2  = (const float*)d_in[13];
    float* out = (float*)d_out;

    float *p_xT, *p_comb, *p_encp, *p_intp, *p_outp, *p_hid;
    cudaGetSymbolAddress((void**)&p_xT,   g_xT);
    cudaGetSymbolAddress((void**)&p_comb, g_comb);
    cudaGetSymbolAddress((void**)&p_encp, g_encp);
    cudaGetSymbolAddress((void**)&p_intp, g_intp);
    cudaGetSymbolAddress((void**)&p_outp, g_outp);
    cudaGetSymbolAddress((void**)&p_hid,  g_hid);

    k_transpose<<<128, 256>>>(x);
    k_gemmT<<<dim3(8, 4), 128>>>(p_xT, W_enc, p_encp, 1024, 256, 128);
    k_encfin<<<32, 256>>>(b_enc, gamma1, beta1, prev_h);
    k_sim<<<dim3(4, 32), 256>>>(bank, trace);
    k_softmax<<<32, 256>>>();
    k_mt<<<dim3(8, 16), 128>>>(bank, trace);
    k_combmt<<<128, 256>>>();
    k_gemmT<<<dim3(24, 8), 128>>>(p_comb, W_int, p_intp, 3072, 384, 128);
    k_intfin<<<384, 256>>>(b_int);
    k_gemmT<<<dim3(8, 16), 128>>>(p_hid, W_out, p_outp, 1024, 192, 96);
    k_outfin<<<32, 256>>>(b_out, gamma2, beta2, out);
    k_trace<<<dim3(8, 128), 128>>>(trace, out);
}

// round 3
// speedup vs baseline: 1.6450x; 1.6450x over previous
#include <cuda_runtime.h>
#include <cstdint>

typedef unsigned long long ull;

#define B_  32
#define D_  1024
#define H_  1024
#define M_  2048
#define K3_ 3072

#define KS_ENC 16
#define KS_SIM 8
#define KS_INT 12
#define KS_OUT 24
#define MS_MT  16

// ---------------- scratch (static device globals; no allocation) ----------------
__device__ float g_xT[D_ * B_];                 // x transposed [k][b]
__device__ float g_comb[K3_ * B_];              // combined [k][b]: 0..1023=z, 1024..2047=m_t, 2048..3071=prev_h
__device__ float g_zinv[B_];                    // 1/||z|| per batch row
__device__ float g_encp[KS_ENC * H_ * B_];      // enc GEMM split-K partials
__device__ float g_emT[H_ * M_];                // eff_mem transposed [h][m]
__device__ float g_ssqp[32 * M_];               // per h-tile sumsq partials
__device__ float g_rss[M_];                     // 1/||em[m]||
__device__ float g_simp[KS_SIM * M_ * B_];      // sim gemm partials
__device__ float g_attn[M_ * B_];               // attn transposed [m][b]
__device__ float g_mtp[MS_MT * H_ * B_];        // m_t split-M partials
__device__ float g_intp[KS_INT * K3_ * B_];     // W_int GEMM split-K partials
__device__ float g_hid[K3_ * B_];               // hidden [n][b]
__device__ float g_outp[KS_OUT * H_ * B_];      // W_out GEMM split-K partials

// ---------------- helpers ----------------
__device__ __forceinline__ ull pack2(float w) {
    ull r; asm("mov.b64 %0, {%1, %1};" : "=l"(r) : "f"(w)); return r;
}
__device__ __forceinline__ void fma2(ull& d, ull a, ull b) {
    asm("fma.rn.f32x2 %0, %1, %2, %0;" : "+l"(d) : "l"(a), "l"(b));
}
__device__ __forceinline__ float hadd2(ull a) {
    float2 f = *reinterpret_cast<float2*>(&a); return f.x + f.y;
}

__device__ __forceinline__ float bsum256(float v, float* sb) {
    int tx = threadIdx.x;
#pragma unroll
    for (int o = 16; o > 0; o >>= 1) v += __shfl_xor_sync(0xffffffffu, v, o);
    if ((tx & 31) == 0) sb[tx >> 5] = v;
    __syncthreads();
    float r = (tx < 8) ? sb[tx] : 0.f;
    if (tx < 32) {
#pragma unroll
        for (int o = 4; o > 0; o >>= 1) r += __shfl_xor_sync(0xffffffffu, r, o);
        if (tx == 0) sb[0] = r;
    }
    __syncthreads();
    r = sb[0];
    __syncthreads();
    return r;
}
__device__ __forceinline__ float bmax256(float v, float* sb) {
    int tx = threadIdx.x;
#pragma unroll
    for (int o = 16; o > 0; o >>= 1) v = fmaxf(v, __shfl_xor_sync(0xffffffffu, v, o));
    if ((tx & 31) == 0) sb[tx >> 5] = v;
    __syncthreads();
    float r = (tx < 8) ? sb[tx] : -3.0e38f;
    if (tx < 32) {
#pragma unroll
        for (int o = 4; o > 0; o >>= 1) r = fmaxf(r, __shfl_xor_sync(0xffffffffu, r, o));
        if (tx == 0) sb[0] = r;
    }
    __syncthreads();
    r = sb[0];
    __syncthreads();
    return r;
}

// jax threefry2x32, key=(0,42), partitionable: counter=(0,e), bits = o0^o1
__device__ __forceinline__ uint32_t rotl32(uint32_t x, int r) { return (x << r) | (x >> (32 - r)); }
__device__ __forceinline__ uint32_t threefry_xor(uint32_t c0, uint32_t c1) {
    const uint32_t ks0 = 0u, ks1 = 42u, ks2 = 0u ^ 42u ^ 0x1BD11BDAu;
    uint32_t x0 = c0 + ks0, x1 = c1 + ks1;
#define TF_R4(a,b,c,d) \
    x0 += x1; x1 = rotl32(x1,a); x1 ^= x0; \
    x0 += x1; x1 = rotl32(x1,b); x1 ^= x0; \
    x0 += x1; x1 = rotl32(x1,c); x1 ^= x0; \
    x0 += x1; x1 = rotl32(x1,d); x1 ^= x0;
    TF_R4(13,15,26,6)  x0 += ks1; x1 += ks2 + 1u;
    TF_R4(17,29,16,24) x0 += ks2; x1 += ks0 + 2u;
    TF_R4(13,15,26,6)  x0 += ks0; x1 += ks1 + 3u;
    TF_R4(17,29,16,24) x0 += ks1; x1 += ks2 + 4u;
    TF_R4(13,15,26,6)  x0 += ks2; x1 += ks0 + 5u;
#undef TF_R4
    return x0 ^ x1;
}
__device__ __forceinline__ float bits2normal(uint32_t bits) {
    uint32_t fb = (bits >> 9) | 0x3F800000u;
    float u01 = __uint_as_float(fb) - 1.0f;
    const float lo = -0.99999994f;
    float u = fmaf(u01, 1.99999994f, lo);
    u = fmaxf(lo, u);
    return 1.4142135623730951f * erfinvf(u);
}

// ---------------- kernels ----------------

// x [32][1024] -> g_xT [k][b], smem-tiled
__global__ void k_transpose(const float* __restrict__ x) {
    __shared__ float s[32][33];
    int k0 = blockIdx.x * 32;
    int t = threadIdx.x;
    int r = t >> 3, c4 = (t & 7) * 4;
    float4 v = *reinterpret_cast<const float4*>(x + r * D_ + k0 + c4);
    s[r][c4] = v.x; s[r][c4 + 1] = v.y; s[r][c4 + 2] = v.z; s[r][c4 + 3] = v.w;
    __syncthreads();
    float4 o;
    o.x = s[c4 + 0][r]; o.y = s[c4 + 1][r]; o.z = s[c4 + 2][r]; o.w = s[c4 + 3][r];
    *reinterpret_cast<float4*>(&g_xT[(k0 + r) * B_ + c4]) = o;
}

// emT[h][m] = bank[m][h] + 0.5*trace[m][h], tiled transpose; also ssq partials per (h-tile, m)
__global__ void k_emT(const float* __restrict__ bank, const float* __restrict__ trace) {
    __shared__ float s[32][33];
    int m0 = blockIdx.x * 32;       // 64
    int h0 = blockIdx.y * 32;       // 32
    int t = threadIdx.x;            // 256
    int r = t >> 3, c4 = (t & 7) * 4;
    size_t base = (size_t)(m0 + r) * H_ + h0 + c4;
    float4 bv = *reinterpret_cast<const float4*>(bank + base);
    float4 tv = *reinterpret_cast<const float4*>(trace + base);
    float4 em;
    em.x = fmaf(0.5f, tv.x, bv.x);
    em.y = fmaf(0.5f, tv.y, bv.y);
    em.z = fmaf(0.5f, tv.z, bv.z);
    em.w = fmaf(0.5f, tv.w, bv.w);
    s[r][c4] = em.x; s[r][c4 + 1] = em.y; s[r][c4 + 2] = em.z; s[r][c4 + 3] = em.w;
    float ss = em.x * em.x + em.y * em.y + em.z * em.z + em.w * em.w;
#pragma unroll
    for (int o = 4; o > 0; o >>= 1) ss += __shfl_down_sync(0xffffffffu, ss, o, 8);
    if ((t & 7) == 0) g_ssqp[blockIdx.y * M_ + m0 + r] = ss;
    __syncthreads();
    float4 o4;
    o4.x = s[c4 + 0][r]; o4.y = s[c4 + 1][r]; o4.z = s[c4 + 2][r]; o4.w = s[c4 + 3][r];
    *reinterpret_cast<float4*>(&g_emT[(size_t)(h0 + r) * M_ + m0 + c4]) = o4;
}

// reduce ssq partials -> g_rss[m]
__global__ void k_ssqred() {
    int m = blockIdx.x * 256 + threadIdx.x;
    float s = 0.f;
#pragma unroll
    for (int j = 0; j < 32; ++j) s += g_ssqp[j * M_ + m];
    g_rss[m] = rsqrtf(fmaxf(s, 1e-12f));
}

// generic split-K GEMM: P[ksplit][n][b] = sum_{k in split} A[k][b] * W[k][n]
__global__ void k_gemmT(const float* __restrict__ A, const float* __restrict__ W,
                        float* __restrict__ P, int N, int Kper, int kchunk) {
    __shared__ float as[128 * B_];
    int n = blockIdx.x * 128 + threadIdx.x;
    int k0 = blockIdx.y * Kper;
    ull acc[16];
#pragma unroll
    for (int j = 0; j < 16; ++j) acc[j] = 0ull;

    for (int kc = 0; kc < Kper; kc += kchunk) {
        int kn = min(kchunk, Kper - kc);
        const float4* Ap = reinterpret_cast<const float4*>(A + (k0 + kc) * B_);
        float4* asp = reinterpret_cast<float4*>(as);
        for (int i = threadIdx.x; i < kn * 8; i += 128) asp[i] = Ap[i];
        __syncthreads();
#pragma unroll 4
        for (int kk = 0; kk < kn; ++kk) {
            float w = W[(size_t)(k0 + kc + kk) * N + n];
            ull w2 = pack2(w);
            const ulonglong2* ap = reinterpret_cast<const ulonglong2*>(&as[kk * B_]);
#pragma unroll
            for (int j = 0; j < 8; ++j) {
                ulonglong2 a2 = ap[j];
                fma2(acc[2 * j], a2.x, w2);
                fma2(acc[2 * j + 1], a2.y, w2);
            }
        }
        __syncthreads();
    }
    ull* dst = reinterpret_cast<ull*>(P + ((size_t)blockIdx.y * N + n) * B_);
#pragma unroll
    for (int j = 0; j < 16; ++j) dst[j] = acc[j];
}

// sum enc partials + bias, relu, layernorm -> z into comb rows [0,1024); prev_h -> rows [2048,3072); zinv
__global__ void k_encfin(const float* __restrict__ b_enc, const float* __restrict__ gamma1,
                         const float* __restrict__ beta1, const float* __restrict__ prev_h) {
    __shared__ float sb[8];
    int b = blockIdx.x, tx = threadIdx.x;
    float v[4], ls = 0.f, lss = 0.f;
#pragma unroll
    for (int j = 0; j < 4; ++j) {
        int h = tx + j * 256;
        float s = b_enc[h];
#pragma unroll
        for (int p = 0; p < KS_ENC; ++p) s += g_encp[p * (H_ * B_) + h * B_ + b];
        s = fmaxf(s, 0.f);
        v[j] = s; ls += s; lss += s * s;
    }
    float mean = bsum256(ls, sb) * (1.0f / H_);
    float msq  = bsum256(lss, sb) * (1.0f / H_);
    float rstd = rsqrtf(msq - mean * mean + 1e-6f);
    float zss = 0.f;
#pragma unroll
    for (int j = 0; j < 4; ++j) {
        int h = tx + j * 256;
        float z = (v[j] - mean) * rstd * gamma1[h] + beta1[h];
        g_comb[h * B_ + b] = z;
        zss += z * z;
        g_comb[(2048 + h) * B_ + b] = prev_h[b * H_ + h];
    }
    float zs = bsum256(zss, sb);
    if (tx == 0) g_zinv[b] = rsqrtf(fmaxf(zs, 1e-12f));
}

// softmax over M per batch row; writes attn transposed [m][b]
__global__ void k_softmax() {
    __shared__ float sb[8];
    int b = blockIdx.x, tx = threadIdx.x;
    float zi = g_zinv[b];
    float s[8];
    float mx = -3.0e38f;
#pragma unroll
    for (int j = 0; j < 8; ++j) {
        int m = tx + j * 256;
        float dot = 0.f;
#pragma unroll
        for (int p = 0; p < KS_SIM; ++p) dot += g_simp[p * (M_ * B_) + m * B_ + b];
        float v = dot * zi * g_rss[m] * (1.0f / 0.75f);
        s[j] = v; mx = fmaxf(mx, v);
    }
    mx = bmax256(mx, sb);
    float sum = 0.f;
#pragma unroll
    for (int j = 0; j < 8; ++j) { s[j] = expf(s[j] - mx); sum += s[j]; }
    sum = bsum256(sum, sb);
    float inv = 1.0f / sum;
#pragma unroll
    for (int j = 0; j < 8; ++j) g_attn[(tx + j * 256) * B_ + b] = s[j] * inv;
}

// m_t split-M partials: P[ms][h][b] = sum_{m in split} attn[m][b] * eff_mem[m][h]
__global__ void k_mt(const float* __restrict__ bank, const float* __restrict__ trace) {
    __shared__ float as[128 * B_];
    int h = blockIdx.x * 128 + threadIdx.x;
    int m0 = blockIdx.y * 128;
    ull acc[16];
#pragma unroll
    for (int j = 0; j < 16; ++j) acc[j] = 0ull;
    {
        const float4* Ap = reinterpret_cast<const float4*>(&g_attn[m0 * B_]);
        float4* asp = reinterpret_cast<float4*>(as);
        for (int i = threadIdx.x; i < 128 * 8; i += 128) asp[i] = Ap[i];
    }
    __syncthreads();
#pragma unroll 4
    for (int k = 0; k < 128; ++k) {
        int m = m0 + k;
        float em = fmaf(0.5f, trace[(size_t)m * H_ + h], bank[(size_t)m * H_ + h]);
        ull w2 = pack2(em);
        const ulonglong2* ap = reinterpret_cast<const ulonglong2*>(&as[k * B_]);
#pragma unroll
        for (int j = 0; j < 8; ++j) {
            ulonglong2 a2 = ap[j];
            fma2(acc[2 * j], a2.x, w2);
            fma2(acc[2 * j + 1], a2.y, w2);
        }
    }
    ull* dst = reinterpret_cast<ull*>(&g_mtp[(size_t)blockIdx.y * (H_ * B_) + h * B_]);
#pragma unroll
    for (int j = 0; j < 16; ++j) dst[j] = acc[j];
}

// reduce m_t partials into comb rows [1024,2048)
__global__ void k_combmt() {
    int idx = blockIdx.x * 256 + threadIdx.x;  // 32768
    float s = 0.f;
#pragma unroll
    for (int p = 0; p < MS_MT; ++p) s += g_mtp[p * (H_ * B_) + idx];
    g_comb[H_ * B_ + idx] = s;
}

// reduce W_int partials + bias, relu -> hidden [n][b]
__global__ void k_intfin(const float* __restrict__ b_int) {
    int idx = blockIdx.x * 256 + threadIdx.x;  // 98304
    int n = idx >> 5;
    float s = b_int[n];
#pragma unroll
    for (int p = 0; p < KS_INT; ++p) s += g_intp[p * (K3_ * B_) + idx];
    g_hid[idx] = fmaxf(s, 0.f);
}

// reduce W_out partials + bias, relu, layernorm -> h_t into d_out[0..32768)
__global__ void k_outfin(const float* __restrict__ b_out, const float* __restrict__ gamma2,
                         const float* __restrict__ beta2, float* __restrict__ out) {
    __shared__ float sb[8];
    int b = blockIdx.x, tx = threadIdx.x;
    float v[4], ls = 0.f, lss = 0.f;
#pragma unroll
    for (int j = 0; j < 4; ++j) {
        int h = tx + j * 256;
        float s = b_out[h];
#pragma unroll
        for (int p = 0; p < KS_OUT; ++p) s += g_outp[p * (H_ * B_) + h * B_ + b];
        s = fmaxf(s, 0.f);
        v[j] = s; ls += s; lss += s * s;
    }
    float mean = bsum256(ls, sb) * (1.0f / H_);
    float msq  = bsum256(lss, sb) * (1.0f / H_);
    float rstd = rsqrtf(msq - mean * mean + 1e-6f);
#pragma unroll
    for (int j = 0; j < 4; ++j) {
        int h = tx + j * 256;
        out[b * H_ + h] = (v[j] - mean) * rstd * gamma2[h] + beta2[h];
    }
}

// Hebbian trace update + jax threefry noise (partitionable); writes d_out[32768 ..)
__global__ void k_trace(const float* __restrict__ trace, float* __restrict__ out) {
    __shared__ float as[16 * B_];
    int tx = threadIdx.x;                  // 128
    int h = blockIdx.x * 128 + tx;
    int m0 = blockIdx.y * 8;               // m0 < 1024
    for (int i = tx; i < 16 * B_; i += 128) {
        int r = i >> 5, b = i & 31;
        int m = (r < 8) ? (m0 + r) : (1024 + m0 + r - 8);
        as[i] = g_attn[m * B_ + b];
    }
    __syncthreads();
    ull z2[16];
    const ull* zp = reinterpret_cast<const ull*>(&g_comb[h * B_]);
#pragma unroll
    for (int j = 0; j < 16; ++j) z2[j] = zp[j];

    for (int mi = 0; mi < 8; ++mi) {
        int m = m0 + mi;
        ull a0 = 0ull, a1 = 0ull;
        const ull* ap0 = reinterpret_cast<const ull*>(&as[mi * B_]);
        const ull* ap1 = reinterpret_cast<const ull*>(&as[(8 + mi) * B_]);
#pragma unroll
        for (int j = 0; j < 16; ++j) { fma2(a0, ap0[j], z2[j]); fma2(a1, ap1[j], z2[j]); }
        float s0 = hadd2(a0), s1 = hadd2(a1);

        uint32_t e0 = (uint32_t)(m * 1024 + h);
        uint32_t e1 = e0 + 1048576u;
        float n0 = bits2normal(threefry_xor(0u, e0)) * 0.001f;
        float n1 = bits2normal(threefry_xor(0u, e1)) * 0.001f;

        float t0 = trace[(size_t)m * H_ + h];
        float t1 = trace[(size_t)(m + 1024) * H_ + h];
        float r0 = t0 * 0.95f + 0.05f * (s0 * (1.0f / 32.0f) + n0);
        float r1 = t1 * 0.95f + 0.05f * (s1 * (1.0f / 32.0f) + n1);
        out[32768 + m * 1024 + h] = fminf(fmaxf(r0, -0.1f), 0.1f);
        out[32768 + (m + 1024) * 1024 + h] = fminf(fmaxf(r1, -0.1f), 0.1f);
    }
}

// ---------------- launch ----------------
extern "C" void kernel_launch(void* const* d_in, const int* in_sizes, int n_in,
                              void* d_out, int out_size) {
    const float* x      = (const float*)d_in[0];
    const float* prev_h = (const float*)d_in[1];
    const float* trace  = (const float*)d_in[2];
    const float* bank   = (const float*)d_in[3];
    const float* W_enc  = (const float*)d_in[4];
    const float* b_enc  = (const float*)d_in[5];
    const float* gamma1 = (const float*)d_in[6];
    const float* beta1  = (const float*)d_in[7];
    const float* W_int  = (const float*)d_in[8];
    const float* b_int  = (const float*)d_in[9];
    const float* W_out  = (const float*)d_in[10];
    const float* b_out  = (const float*)d_in[11];
    const float* gamma2 = (const float*)d_in[12];
    const float* beta2  = (const float*)d_in[13];
    float* out = (float*)d_out;

    float *p_xT, *p_comb, *p_encp, *p_emT, *p_simp, *p_intp, *p_outp, *p_hid;
    cudaGetSymbolAddress((void**)&p_xT,   g_xT);
    cudaGetSymbolAddress((void**)&p_comb, g_comb);
    cudaGetSymbolAddress((void**)&p_encp, g_encp);
    cudaGetSymbolAddress((void**)&p_emT,  g_emT);
    cudaGetSymbolAddress((void**)&p_simp, g_simp);
    cudaGetSymbolAddress((void**)&p_intp, g_intp);
    cudaGetSymbolAddress((void**)&p_outp, g_outp);
    cudaGetSymbolAddress((void**)&p_hid,  g_hid);

    k_transpose<<<32, 256>>>(x);                                    // x -> xT
    k_emT<<<dim3(64, 32), 256>>>(bank, trace);                      // em transpose + ssq partials
    k_gemmT<<<dim3(8, KS_ENC), 128>>>(p_xT, W_enc, p_encp, 1024, 1024 / KS_ENC, 64);
    k_ssqred<<<8, 256>>>();
    k_encfin<<<32, 256>>>(b_enc, gamma1, beta1, prev_h);
    k_gemmT<<<dim3(16, KS_SIM), 128>>>(p_comb, p_emT, p_simp, 2048, 1024 / KS_SIM, 128);
    k_softmax<<<32, 256>>>();
    k_mt<<<dim3(8, MS_MT), 128>>>(bank, trace);
    k_combmt<<<128, 256>>>();
    k_gemmT<<<dim3(24, KS_INT), 128>>>(p_comb, W_int, p_intp, 3072, 3072 / KS_INT, 128);
    k_intfin<<<384, 256>>>(b_int);
    k_gemmT<<<dim3(8, KS_OUT), 128>>>(p_hid, W_out, p_outp, 1024, 3072 / KS_OUT, 128);
    k_outfin<<<32, 256>>>(b_out, gamma2, beta2, out);
    k_trace<<<dim3(8, 128), 128>>>(trace, out);
}

// round 4
// speedup vs baseline: 2.0345x; 1.2368x over previous
#include <cuda_runtime.h>
#include <cstdint>

typedef unsigned long long ull;

#define B_  32
#define D_  1024
#define H_  1024
#define M_  2048
#define K3_ 3072

#define GRID_ 148

#define KS_ENC 32
#define KS_SIM 16
#define KS_INT 12
#define KS_OUT 32
#define MS_MT  16

// ---------------- scratch (static device globals; no allocation) ----------------
__device__ float g_xT[D_ * B_];
__device__ float g_comb[K3_ * B_];              // [k][b]: 0..1023=z, 1024..2047=m_t, 2048..3071=prev_h
__device__ float g_zinv[B_];
__device__ float g_encp[KS_ENC * H_ * B_];
__device__ float g_emT[H_ * M_];                // eff_mem transposed [h][m]
__device__ float g_ssqp[32 * M_];
__device__ float g_rss[M_];
__device__ float g_simp[KS_SIM * M_ * B_];
__device__ float g_attn[M_ * B_];
__device__ float g_mtp[MS_MT * H_ * B_];
__device__ float g_intp[KS_INT * K3_ * B_];
__device__ float g_hid[K3_ * B_];
__device__ float g_outp[KS_OUT * H_ * B_];

// barrier state
__device__ unsigned g_cnt = 0;
__device__ unsigned g_gen = 0;

// ---------------- helpers ----------------
__device__ __forceinline__ ull pack2(float w) {
    ull r; asm("mov.b64 %0, {%1, %1};" : "=l"(r) : "f"(w)); return r;
}
__device__ __forceinline__ void fma2(ull& d, ull a, ull b) {
    asm("fma.rn.f32x2 %0, %1, %2, %0;" : "+l"(d) : "l"(a), "l"(b));
}
__device__ __forceinline__ float hadd2(ull a) {
    float2 f = *reinterpret_cast<float2*>(&a); return f.x + f.y;
}

__device__ __forceinline__ void gbar() {
    __syncthreads();
    if (threadIdx.x == 0) {
        __threadfence();
        unsigned gen = *(volatile unsigned*)&g_gen;
        if (atomicAdd(&g_cnt, 1u) == (unsigned)(gridDim.x - 1)) {
            g_cnt = 0;
            __threadfence();
            atomicAdd(&g_gen, 1u);
        } else {
            while (*(volatile unsigned*)&g_gen == gen) { __nanosleep(64); }
            __threadfence();
        }
    }
    __syncthreads();
}

__device__ __forceinline__ float bsum256(float v, float* sb) {
    int tx = threadIdx.x;
#pragma unroll
    for (int o = 16; o > 0; o >>= 1) v += __shfl_xor_sync(0xffffffffu, v, o);
    if ((tx & 31) == 0) sb[tx >> 5] = v;
    __syncthreads();
    float r = (tx < 8) ? sb[tx] : 0.f;
    if (tx < 32) {
#pragma unroll
        for (int o = 4; o > 0; o >>= 1) r += __shfl_xor_sync(0xffffffffu, r, o);
        if (tx == 0) sb[0] = r;
    }
    __syncthreads();
    r = sb[0];
    __syncthreads();
    return r;
}
__device__ __forceinline__ float bmax256(float v, float* sb) {
    int tx = threadIdx.x;
#pragma unroll
    for (int o = 16; o > 0; o >>= 1) v = fmaxf(v, __shfl_xor_sync(0xffffffffu, v, o));
    if ((tx & 31) == 0) sb[tx >> 5] = v;
    __syncthreads();
    float r = (tx < 8) ? sb[tx] : -3.0e38f;
    if (tx < 32) {
#pragma unroll
        for (int o = 4; o > 0; o >>= 1) r = fmaxf(r, __shfl_xor_sync(0xffffffffu, r, o));
        if (tx == 0) sb[0] = r;
    }
    __syncthreads();
    r = sb[0];
    __syncthreads();
    return r;
}

// jax threefry2x32, key=(0,42), partitionable: counter=(0,e), bits = o0^o1
__device__ __forceinline__ uint32_t rotl32(uint32_t x, int r) { return (x << r) | (x >> (32 - r)); }
__device__ __forceinline__ uint32_t threefry_xor(uint32_t c0, uint32_t c1) {
    const uint32_t ks0 = 0u, ks1 = 42u, ks2 = 0u ^ 42u ^ 0x1BD11BDAu;
    uint32_t x0 = c0 + ks0, x1 = c1 + ks1;
#define TF_R4(a,b,c,d) \
    x0 += x1; x1 = rotl32(x1,a); x1 ^= x0; \
    x0 += x1; x1 = rotl32(x1,b); x1 ^= x0; \
    x0 += x1; x1 = rotl32(x1,c); x1 ^= x0; \
    x0 += x1; x1 = rotl32(x1,d); x1 ^= x0;
    TF_R4(13,15,26,6)  x0 += ks1; x1 += ks2 + 1u;
    TF_R4(17,29,16,24) x0 += ks2; x1 += ks0 + 2u;
    TF_R4(13,15,26,6)  x0 += ks0; x1 += ks1 + 3u;
    TF_R4(17,29,16,24) x0 += ks1; x1 += ks2 + 4u;
    TF_R4(13,15,26,6)  x0 += ks2; x1 += ks0 + 5u;
#undef TF_R4
    return x0 ^ x1;
}
__device__ __forceinline__ float bits2normal(uint32_t bits) {
    uint32_t fb = (bits >> 9) | 0x3F800000u;
    float u01 = __uint_as_float(fb) - 1.0f;
    const float lo = -0.99999994f;
    float u = fmaf(u01, 1.99999994f, lo);
    u = fmaxf(lo, u);
    return 1.4142135623730951f * erfinvf(u);
}

// split-K GEMM task: P[ks][n][b] += A[k][b]*W[k][n], 256 threads, n-tile=256
__device__ __forceinline__ void gemm_task(const float* __restrict__ A, const float* __restrict__ W,
                                          float* __restrict__ P, int N, int tile, int ks,
                                          int Kper, int kchunk, float* as) {
    int n = tile * 256 + threadIdx.x;
    int k0 = ks * Kper;
    ull acc[16];
#pragma unroll
    for (int j = 0; j < 16; ++j) acc[j] = 0ull;
    for (int kc = 0; kc < Kper; kc += kchunk) {
        const float4* Ap = reinterpret_cast<const float4*>(A + (k0 + kc) * B_);
        float4* asp = reinterpret_cast<float4*>(as);
        for (int i = threadIdx.x; i < kchunk * 8; i += 256) asp[i] = Ap[i];
        __syncthreads();
#pragma unroll 4
        for (int kk = 0; kk < kchunk; ++kk) {
            float w = W[(size_t)(k0 + kc + kk) * N + n];
            ull w2 = pack2(w);
            const ulonglong2* ap = reinterpret_cast<const ulonglong2*>(&as[kk * B_]);
#pragma unroll
            for (int j = 0; j < 8; ++j) {
                ulonglong2 a2 = ap[j];
                fma2(acc[2 * j], a2.x, w2);
                fma2(acc[2 * j + 1], a2.y, w2);
            }
        }
        __syncthreads();
    }
    ull* dst = reinterpret_cast<ull*>(P + ((size_t)ks * N + n) * B_);
#pragma unroll
    for (int j = 0; j < 16; ++j) dst[j] = acc[j];
}

// m_t variant: W computed on the fly from bank + 0.5*trace
__device__ __forceinline__ void mt_task(const float* __restrict__ bank, const float* __restrict__ trace,
                                        int tile, int ms, float* as) {
    int h = tile * 256 + threadIdx.x;
    int m0 = ms * 128;
    ull acc[16];
#pragma unroll
    for (int j = 0; j < 16; ++j) acc[j] = 0ull;
    for (int kc = 0; kc < 128; kc += 64) {
        const float4* Ap = reinterpret_cast<const float4*>(g_attn + (m0 + kc) * B_);
        float4* asp = reinterpret_cast<float4*>(as);
        for (int i = threadIdx.x; i < 64 * 8; i += 256) asp[i] = Ap[i];
        __syncthreads();
#pragma unroll 4
        for (int kk = 0; kk < 64; ++kk) {
            int m = m0 + kc + kk;
            float em = fmaf(0.5f, trace[(size_t)m * H_ + h], bank[(size_t)m * H_ + h]);
            ull w2 = pack2(em);
            const ulonglong2* ap = reinterpret_cast<const ulonglong2*>(&as[kk * B_]);
#pragma unroll
            for (int j = 0; j < 8; ++j) {
                ulonglong2 a2 = ap[j];
                fma2(acc[2 * j], a2.x, w2);
                fma2(acc[2 * j + 1], a2.y, w2);
            }
        }
        __syncthreads();
    }
    ull* dst = reinterpret_cast<ull*>(&g_mtp[((size_t)ms * H_ + h) * B_]);
#pragma unroll
    for (int j = 0; j < 16; ++j) dst[j] = acc[j];
}

// ---------------- the persistent kernel ----------------
__global__ void __launch_bounds__(256, 1)
k_fused(const float* __restrict__ x, const float* __restrict__ prev_h,
        const float* __restrict__ trace, const float* __restrict__ bank,
        const float* __restrict__ W_enc, const float* __restrict__ b_enc,
        const float* __restrict__ gamma1, const float* __restrict__ beta1,
        const float* __restrict__ W_int, const float* __restrict__ b_int,
        const float* __restrict__ W_out, const float* __restrict__ b_out,
        const float* __restrict__ gamma2, const float* __restrict__ beta2,
        float* __restrict__ out) {
    __shared__ float as[96 * B_];     // 12 KB, reused per phase
    __shared__ float sb[8];
    const int tx = threadIdx.x;
    const int G = gridDim.x;

    // ---- P0: x transpose (32 tasks) + eff_mem transpose + ssq partials (2048 tasks) ----
    {
        int r = tx >> 3, c4 = (tx & 7) * 4;
        for (int t = blockIdx.x; t < 2080; t += G) {
            if (t < 32) {
                int k0 = t * 32;
                float4 v = *reinterpret_cast<const float4*>(x + r * D_ + k0 + c4);
                as[r * 33 + c4] = v.x; as[r * 33 + c4 + 1] = v.y;
                as[r * 33 + c4 + 2] = v.z; as[r * 33 + c4 + 3] = v.w;
                __syncthreads();
                float4 o;
                o.x = as[(c4 + 0) * 33 + r]; o.y = as[(c4 + 1) * 33 + r];
                o.z = as[(c4 + 2) * 33 + r]; o.w = as[(c4 + 3) * 33 + r];
                *reinterpret_cast<float4*>(&g_xT[(k0 + r) * B_ + c4]) = o;
                __syncthreads();
            } else {
                int tt = t - 32;
                int m0 = (tt & 63) * 32, h0 = (tt >> 6) * 32;
                size_t base = (size_t)(m0 + r) * H_ + h0 + c4;
                float4 bv = *reinterpret_cast<const float4*>(bank + base);
                float4 tv = *reinterpret_cast<const float4*>(trace + base);
                float4 em;
                em.x = fmaf(0.5f, tv.x, bv.x); em.y = fmaf(0.5f, tv.y, bv.y);
                em.z = fmaf(0.5f, tv.z, bv.z); em.w = fmaf(0.5f, tv.w, bv.w);
                as[r * 33 + c4] = em.x; as[r * 33 + c4 + 1] = em.y;
                as[r * 33 + c4 + 2] = em.z; as[r * 33 + c4 + 3] = em.w;
                float ss = em.x * em.x + em.y * em.y + em.z * em.z + em.w * em.w;
#pragma unroll
                for (int o = 4; o > 0; o >>= 1) ss += __shfl_down_sync(0xffffffffu, ss, o, 8);
                if ((tx & 7) == 0) g_ssqp[(tt >> 6) * M_ + m0 + r] = ss;
                __syncthreads();
                float4 o4;
                o4.x = as[(c4 + 0) * 33 + r]; o4.y = as[(c4 + 1) * 33 + r];
                o4.z = as[(c4 + 2) * 33 + r]; o4.w = as[(c4 + 3) * 33 + r];
                *reinterpret_cast<float4*>(&g_emT[(size_t)(h0 + r) * M_ + m0 + c4]) = o4;
                __syncthreads();
            }
        }
    }
    gbar();

    // ---- P1: enc gemm (128 tasks: 4 tiles x 32 ks, Kper=32) + ssq reduce (8 tasks) ----
    for (int t = blockIdx.x; t < 136; t += G) {
        if (t < 128) {
            gemm_task(g_xT, W_enc, g_encp, 1024, t & 3, t >> 2, 1024 / KS_ENC, 32, as);
        } else {
            int m = (t - 128) * 256 + tx;
            float s = 0.f;
#pragma unroll
            for (int j = 0; j < 32; ++j) s += g_ssqp[j * M_ + m];
            g_rss[m] = rsqrtf(fmaxf(s, 1e-12f));
        }
    }
    gbar();

    // ---- P2: encfin (32 tasks) ----
    for (int t = blockIdx.x; t < 32; t += G) {
        int b = t;
        float v[4], ls = 0.f, lss = 0.f;
#pragma unroll
        for (int j = 0; j < 4; ++j) {
            int h = tx + j * 256;
            float s = b_enc[h];
#pragma unroll
            for (int p = 0; p < KS_ENC; ++p) s += g_encp[p * (H_ * B_) + h * B_ + b];
            s = fmaxf(s, 0.f);
            v[j] = s; ls += s; lss += s * s;
        }
        float mean = bsum256(ls, sb) * (1.0f / H_);
        float msq  = bsum256(lss, sb) * (1.0f / H_);
        float rstd = rsqrtf(msq - mean * mean + 1e-6f);
        float zss = 0.f;
#pragma unroll
        for (int j = 0; j < 4; ++j) {
            int h = tx + j * 256;
            float z = (v[j] - mean) * rstd * gamma1[h] + beta1[h];
            g_comb[h * B_ + b] = z;
            zss += z * z;
            g_comb[(2048 + h) * B_ + b] = prev_h[b * H_ + h];
        }
        float zs = bsum256(zss, sb);
        if (tx == 0) g_zinv[b] = rsqrtf(fmaxf(zs, 1e-12f));
    }
    gbar();

    // ---- P3: sim gemm (128 tasks: 8 tiles x 16 ks, Kper=64) ----
    for (int t = blockIdx.x; t < 128; t += G)
        gemm_task(g_comb, g_emT, g_simp, 2048, t & 7, t >> 3, 1024 / KS_SIM, 64, as);
    gbar();

    // ---- P4: softmax (32 tasks) ----
    for (int t = blockIdx.x; t < 32; t += G) {
        int b = t;
        float zi = g_zinv[b];
        float s[8];
        float mx = -3.0e38f;
#pragma unroll
        for (int j = 0; j < 8; ++j) {
            int m = tx + j * 256;
            float dot = 0.f;
#pragma unroll
            for (int p = 0; p < KS_SIM; ++p) dot += g_simp[p * (M_ * B_) + m * B_ + b];
            float v = dot * zi * g_rss[m] * (1.0f / 0.75f);
            s[j] = v; mx = fmaxf(mx, v);
        }
        mx = bmax256(mx, sb);
        float sum = 0.f;
#pragma unroll
        for (int j = 0; j < 8; ++j) { s[j] = expf(s[j] - mx); sum += s[j]; }
        sum = bsum256(sum, sb);
        float inv = 1.0f / sum;
#pragma unroll
        for (int j = 0; j < 8; ++j) g_attn[(tx + j * 256) * B_ + b] = s[j] * inv;
    }
    gbar();

    // ---- P5: m_t partials (64 tasks) + hebbian trace update (512 tasks) ----
    for (int t = blockIdx.x; t < 576; t += G) {
        if (t < 64) {
            mt_task(bank, trace, t & 3, t >> 2, as);
        } else {
            int tt = t - 64;
            int h = (tt & 3) * 256 + tx;
            int m0 = (tt >> 2) * 8;
            for (int i = tx; i < 16 * B_; i += 256) {
                int r = i >> 5, b = i & 31;
                int m = (r < 8) ? (m0 + r) : (1024 + m0 + r - 8);
                as[i] = g_attn[m * B_ + b];
            }
            __syncthreads();
            ull z2[16];
            const ull* zp = reinterpret_cast<const ull*>(&g_comb[h * B_]);
#pragma unroll
            for (int j = 0; j < 16; ++j) z2[j] = zp[j];
#pragma unroll 2
            for (int mi = 0; mi < 8; ++mi) {
                int m = m0 + mi;
                ull a0 = 0ull, a1 = 0ull;
                const ull* ap0 = reinterpret_cast<const ull*>(&as[mi * B_]);
                const ull* ap1 = reinterpret_cast<const ull*>(&as[(8 + mi) * B_]);
#pragma unroll
                for (int j = 0; j < 16; ++j) { fma2(a0, ap0[j], z2[j]); fma2(a1, ap1[j], z2[j]); }
                float s0 = hadd2(a0), s1 = hadd2(a1);
                uint32_t e0 = (uint32_t)(m * 1024 + h);
                uint32_t e1 = e0 + 1048576u;
                float n0 = bits2normal(threefry_xor(0u, e0)) * 0.001f;
                float n1 = bits2normal(threefry_xor(0u, e1)) * 0.001f;
                float t0 = trace[(size_t)m * H_ + h];
                float t1 = trace[(size_t)(m + 1024) * H_ + h];
                float r0 = t0 * 0.95f + 0.05f * (s0 * (1.0f / 32.0f) + n0);
                float r1 = t1 * 0.95f + 0.05f * (s1 * (1.0f / 32.0f) + n1);
                out[32768 + m * 1024 + h] = fminf(fmaxf(r0, -0.1f), 0.1f);
                out[32768 + (m + 1024) * 1024 + h] = fminf(fmaxf(r1, -0.1f), 0.1f);
            }
            __syncthreads();
        }
    }
    gbar();

    // ---- P6: reduce m_t partials (128 tasks) ----
    for (int t = blockIdx.x; t < 128; t += G) {
        int idx = t * 256 + tx;
        float s = 0.f;
#pragma unroll
        for (int p = 0; p < MS_MT; ++p) s += g_mtp[p * (H_ * B_) + idx];
        g_comb[H_ * B_ + idx] = s;
    }
    gbar();

    // ---- P7: int gemm (144 tasks: 12 tiles x 12 ks, Kper=256) ----
    for (int t = blockIdx.x; t < 144; t += G)
        gemm_task(g_comb, W_int, g_intp, 3072, t % 12, t / 12, 3072 / KS_INT, 64, as);
    gbar();

    // ---- P8: intfin (384 tasks) ----
    for (int t = blockIdx.x; t < 384; t += G) {
        int idx = t * 256 + tx;
        int n = idx >> 5;
        float s = b_int[n];
#pragma unroll
        for (int p = 0; p < KS_INT; ++p) s += g_intp[p * (K3_ * B_) + idx];
        g_hid[idx] = fmaxf(s, 0.f);
    }
    gbar();

    // ---- P9: out gemm (128 tasks: 4 tiles x 32 ks, Kper=96) ----
    for (int t = blockIdx.x; t < 128; t += G)
        gemm_task(g_hid, W_out, g_outp, 1024, t & 3, t >> 2, 3072 / KS_OUT, 96, as);
    gbar();

    // ---- P10: outfin (32 tasks) ----
    for (int t = blockIdx.x; t < 32; t += G) {
        int b = t;
        float v[4], ls = 0.f, lss = 0.f;
#pragma unroll
        for (int j = 0; j < 4; ++j) {
            int h = tx + j * 256;
            float s = b_out[h];
#pragma unroll
            for (int p = 0; p < KS_OUT; ++p) s += g_outp[p * (H_ * B_) + h * B_ + b];
            s = fmaxf(s, 0.f);
            v[j] = s; ls += s; lss += s * s;
        }
        float mean = bsum256(ls, sb) * (1.0f / H_);
        float msq  = bsum256(lss, sb) * (1.0f / H_);
        float rstd = rsqrtf(msq - mean * mean + 1e-6f);
#pragma unroll
        for (int j = 0; j < 4; ++j) {
            int h = tx + j * 256;
            out[b * H_ + h] = (v[j] - mean) * rstd * gamma2[h] + beta2[h];
        }
    }
}

// ---------------- launch ----------------
extern "C" void kernel_launch(void* const* d_in, const int* in_sizes, int n_in,
                              void* d_out, int out_size) {
    const float* x      = (const float*)d_in[0];
    const float* prev_h = (const float*)d_in[1];
    const float* trace  = (const float*)d_in[2];
    const float* bank   = (const float*)d_in[3];
    const float* W_enc  = (const float*)d_in[4];
    const float* b_enc  = (const float*)d_in[5];
    const float* gamma1 = (const float*)d_in[6];
    const float* beta1  = (const float*)d_in[7];
    const float* W_int  = (const float*)d_in[8];
    const float* b_int  = (const float*)d_in[9];
    const float* W_out  = (const float*)d_in[10];
    const float* b_out  = (const float*)d_in[11];
    const float* gamma2 = (const float*)d_in[12];
    const float* beta2  = (const float*)d_in[13];
    float* out = (float*)d_out;

    k_fused<<<GRID_, 256>>>(x, prev_h, trace, bank, W_enc, b_enc, gamma1, beta1,
                            W_int, b_int, W_out, b_out, gamma2, beta2, out);
}

// round 8
// speedup vs baseline: 2.1102x; 1.0372x over previous
#include <cuda_runtime.h>
#include <cstdint>

typedef unsigned long long ull;

#define B_  32
#define D_  1024
#define H_  1024
#define M_  2048
#define K3_ 3072

#define GRID_ 444          // 3 CTAs per SM

#define KS_ENC 32
#define KS_SIM 32
#define KS_INT 32
#define KS_OUT 64
#define MS_MT  32

// ---------------- scratch ----------------
__device__ float g_comb[K3_ * B_];              // [k][b]: 0..1023=z, 1024..2047=m_t, 2048..3071=prev_h
__device__ float g_zinv[B_];
__device__ float g_encp[KS_ENC * H_ * B_];
__device__ float g_emT[H_ * M_];                // eff_mem transposed [h][m]
__device__ float g_ssqp[32 * M_];
__device__ float g_rss[M_];
__device__ float g_simp[KS_SIM * M_ * B_];
__device__ float g_attn[M_ * B_];
__device__ float g_mtp[MS_MT * H_ * B_];
__device__ float g_intp[KS_INT * K3_ * B_];
__device__ float g_hid[K3_ * B_];
__device__ float g_outp[KS_OUT * H_ * B_];

__device__ unsigned g_cnt = 0;
__device__ unsigned g_gen = 0;

// ---------------- helpers ----------------
__device__ __forceinline__ ull pack2(float w) {
    ull r; asm("mov.b64 %0, {%1, %1};" : "=l"(r) : "f"(w)); return r;
}
__device__ __forceinline__ void fma2(ull& d, ull a, ull b) {
    asm("fma.rn.f32x2 %0, %1, %2, %0;" : "+l"(d) : "l"(a), "l"(b));
}
__device__ __forceinline__ float hadd2(ull a) {
    float2 f = *reinterpret_cast<float2*>(&a); return f.x + f.y;
}

__device__ __forceinline__ void gbar() {
    __syncthreads();
    if (threadIdx.x == 0) {
        __threadfence();
        unsigned gen = *(volatile unsigned*)&g_gen;
        if (atomicAdd(&g_cnt, 1u) == (unsigned)(gridDim.x - 1)) {
            g_cnt = 0;
            __threadfence();
            atomicAdd(&g_gen, 1u);
        } else {
            while (*(volatile unsigned*)&g_gen == gen) { __nanosleep(32); }
            __threadfence();
        }
    }
    __syncthreads();
}

__device__ __forceinline__ float bsum256(float v, float* sb) {
    int tx = threadIdx.x;
#pragma unroll
    for (int o = 16; o > 0; o >>= 1) v += __shfl_xor_sync(0xffffffffu, v, o);
    if ((tx & 31) == 0) sb[tx >> 5] = v;
    __syncthreads();
    float r = (tx < 8) ? sb[tx] : 0.f;
    if (tx < 32) {
#pragma unroll
        for (int o = 4; o > 0; o >>= 1) r += __shfl_xor_sync(0xffffffffu, r, o);
        if (tx == 0) sb[0] = r;
    }
    __syncthreads();
    r = sb[0];
    __syncthreads();
    return r;
}
__device__ __forceinline__ float bmax256(float v, float* sb) {
    int tx = threadIdx.x;
#pragma unroll
    for (int o = 16; o > 0; o >>= 1) v = fmaxf(v, __shfl_xor_sync(0xffffffffu, v, o));
    if ((tx & 31) == 0) sb[tx >> 5] = v;
    __syncthreads();
    float r = (tx < 8) ? sb[tx] : -3.0e38f;
    if (tx < 32) {
#pragma unroll
        for (int o = 4; o > 0; o >>= 1) r = fmaxf(r, __shfl_xor_sync(0xffffffffu, r, o));
        if (tx == 0) sb[0] = r;
    }
    __syncthreads();
    r = sb[0];
    __syncthreads();
    return r;
}

// jax threefry2x32, key=(0,42), partitionable: counter=(0,e), bits = o0^o1
__device__ __forceinline__ uint32_t rotl32(uint32_t x, int r) { return (x << r) | (x >> (32 - r)); }
__device__ __forceinline__ uint32_t threefry_xor(uint32_t c0, uint32_t c1) {
    const uint32_t ks0 = 0u, ks1 = 42u, ks2 = 0u ^ 42u ^ 0x1BD11BDAu;
    uint32_t x0 = c0 + ks0, x1 = c1 + ks1;
#define TF_R4(a,b,c,d) \
    x0 += x1; x1 = rotl32(x1,a); x1 ^= x0; \
    x0 += x1; x1 = rotl32(x1,b); x1 ^= x0; \
    x0 += x1; x1 = rotl32(x1,c); x1 ^= x0; \
    x0 += x1; x1 = rotl32(x1,d); x1 ^= x0;
    TF_R4(13,15,26,6)  x0 += ks1; x1 += ks2 + 1u;
    TF_R4(17,29,16,24) x0 += ks2; x1 += ks0 + 2u;
    TF_R4(13,15,26,6)  x0 += ks0; x1 += ks1 + 3u;
    TF_R4(17,29,16,24) x0 += ks1; x1 += ks2 + 4u;
    TF_R4(13,15,26,6)  x0 += ks2; x1 += ks0 + 5u;
#undef TF_R4
    return x0 ^ x1;
}
__device__ __forceinline__ float bits2normal(uint32_t bits) {
    uint32_t fb = (bits >> 9) | 0x3F800000u;
    float u01 = __uint_as_float(fb) - 1.0f;
    const float lo = -0.99999994f;
    float u = fmaf(u01, 1.99999994f, lo);
    u = fmaxf(lo, u);
    return 1.4142135623730951f * erfinvf(u);
}

// half-batch split-K GEMM task: 256 threads, n-tile 128 wide, 2 threads/column.
// P[ks][n][b] = sum_{k in split} A[k][b]*W[k][n]
__device__ __forceinline__ void gemm_half(const float* __restrict__ A, const float* __restrict__ W,
                                          float* __restrict__ P, int N, int tile, int ks,
                                          int Kper, int kchunk, float* as) {
    int n = tile * 128 + (threadIdx.x >> 1);
    int half16 = (threadIdx.x & 1) * 16;
    int k0 = ks * Kper;
    ull acc[8];
#pragma unroll
    for (int j = 0; j < 8; ++j) acc[j] = 0ull;
    for (int kc = 0; kc < Kper; kc += kchunk) {
        const float4* Ap = reinterpret_cast<const float4*>(A + (k0 + kc) * B_);
        float4* asp = reinterpret_cast<float4*>(as);
        for (int i = threadIdx.x; i < kchunk * 8; i += 256) asp[i] = Ap[i];
        __syncthreads();
#pragma unroll 4
        for (int kk = 0; kk < kchunk; ++kk) {
            float w = W[(size_t)(k0 + kc + kk) * N + n];
            ull w2 = pack2(w);
            const ulonglong2* ap = reinterpret_cast<const ulonglong2*>(&as[kk * B_ + half16]);
#pragma unroll
            for (int j = 0; j < 4; ++j) {
                ulonglong2 a2 = ap[j];
                fma2(acc[2 * j], a2.x, w2);
                fma2(acc[2 * j + 1], a2.y, w2);
            }
        }
        __syncthreads();
    }
    ull* dst = reinterpret_cast<ull*>(P + ((size_t)ks * N + n) * B_ + half16);
#pragma unroll
    for (int j = 0; j < 8; ++j) dst[j] = acc[j];
}

// ---------------- the persistent kernel ----------------
__global__ void __launch_bounds__(256, 3)
k_fused(const float* __restrict__ x, const float* __restrict__ prev_h,
        const float* __restrict__ trace, const float* __restrict__ bank,
        const float* __restrict__ W_enc, const float* __restrict__ b_enc,
        const float* __restrict__ gamma1, const float* __restrict__ beta1,
        const float* __restrict__ W_int, const float* __restrict__ b_int,
        const float* __restrict__ W_out, const float* __restrict__ b_out,
        const float* __restrict__ gamma2, const float* __restrict__ beta2,
        float* __restrict__ out) {
    __shared__ float as[64 * B_ + 64];     // 8.5 KB — P5 mt stages a 64x32 attn chunk (2048 floats)
    __shared__ float sb[8];
    const int tx = threadIdx.x;
    const int G = gridDim.x;

    // ---- P1: eff_mem transpose + ssq (2048 tasks) + enc gemm from x (256 tasks) ----
    for (int t = blockIdx.x; t < 2048 + 8 * KS_ENC; t += G) {
        if (t < 2048) {
            int r = tx >> 3, c4 = (tx & 7) * 4;
            int m0 = (t & 63) * 32, h0 = (t >> 6) * 32;
            size_t base = (size_t)(m0 + r) * H_ + h0 + c4;
            float4 bv = *reinterpret_cast<const float4*>(bank + base);
            float4 tv = *reinterpret_cast<const float4*>(trace + base);
            float4 em;
            em.x = fmaf(0.5f, tv.x, bv.x); em.y = fmaf(0.5f, tv.y, bv.y);
            em.z = fmaf(0.5f, tv.z, bv.z); em.w = fmaf(0.5f, tv.w, bv.w);
            as[r * 33 + c4] = em.x; as[r * 33 + c4 + 1] = em.y;
            as[r * 33 + c4 + 2] = em.z; as[r * 33 + c4 + 3] = em.w;
            float ss = em.x * em.x + em.y * em.y + em.z * em.z + em.w * em.w;
#pragma unroll
            for (int o = 4; o > 0; o >>= 1) ss += __shfl_down_sync(0xffffffffu, ss, o, 8);
            if ((tx & 7) == 0) g_ssqp[(t >> 6) * M_ + m0 + r] = ss;
            __syncthreads();
            float4 o4;
            o4.x = as[(c4 + 0) * 33 + r]; o4.y = as[(c4 + 1) * 33 + r];
            o4.z = as[(c4 + 2) * 33 + r]; o4.w = as[(c4 + 3) * 33 + r];
            *reinterpret_cast<float4*>(&g_emT[(size_t)(h0 + r) * M_ + m0 + c4]) = o4;
            __syncthreads();
        } else {
            // enc gemm: A[k][b] gathered from x[b][k]; tile q&7, ks q>>3, Kper=32
            int q = t - 2048;
            int tile = q & 7, ks = q >> 3;
            int n = tile * 128 + (tx >> 1);
            int half16 = (tx & 1) * 16;
            int k0 = ks * 32;
            for (int i = tx; i < 32 * B_; i += 256) {
                int k = i >> 5, b = i & 31;
                as[k * B_ + b] = x[b * D_ + k0 + k];
            }
            __syncthreads();
            ull acc[8];
#pragma unroll
            for (int j = 0; j < 8; ++j) acc[j] = 0ull;
#pragma unroll 4
            for (int kk = 0; kk < 32; ++kk) {
                float w = W_enc[(size_t)(k0 + kk) * H_ + n];
                ull w2 = pack2(w);
                const ulonglong2* ap = reinterpret_cast<const ulonglong2*>(&as[kk * B_ + half16]);
#pragma unroll
                for (int j = 0; j < 4; ++j) {
                    ulonglong2 a2 = ap[j];
                    fma2(acc[2 * j], a2.x, w2);
                    fma2(acc[2 * j + 1], a2.y, w2);
                }
            }
            __syncthreads();
            ull* dst = reinterpret_cast<ull*>(g_encp + ((size_t)ks * H_ + n) * B_ + half16);
#pragma unroll
            for (int j = 0; j < 8; ++j) dst[j] = acc[j];
        }
    }
    gbar();

    // ---- P2: encfin (32 tasks) + ssqred (8 tasks) ----
    for (int t = blockIdx.x; t < 40; t += G) {
        if (t < 32) {
            int b = t;
            float v[4], ls = 0.f, lss = 0.f;
#pragma unroll
            for (int j = 0; j < 4; ++j) {
                int h = tx + j * 256;
                float s = b_enc[h];
#pragma unroll
                for (int p = 0; p < KS_ENC; ++p) s += g_encp[p * (H_ * B_) + h * B_ + b];
                s = fmaxf(s, 0.f);
                v[j] = s; ls += s; lss += s * s;
            }
            float mean = bsum256(ls, sb) * (1.0f / H_);
            float msq  = bsum256(lss, sb) * (1.0f / H_);
            float rstd = rsqrtf(msq - mean * mean + 1e-6f);
            float zss = 0.f;
#pragma unroll
            for (int j = 0; j < 4; ++j) {
                int h = tx + j * 256;
                float z = (v[j] - mean) * rstd * gamma1[h] + beta1[h];
                g_comb[h * B_ + b] = z;
                zss += z * z;
                g_comb[(2048 + h) * B_ + b] = prev_h[b * H_ + h];
            }
            float zs = bsum256(zss, sb);
            if (tx == 0) g_zinv[b] = rsqrtf(fmaxf(zs, 1e-12f));
        } else {
            int m = (t - 32) * 256 + tx;
            float s = 0.f;
#pragma unroll
            for (int j = 0; j < 32; ++j) s += g_ssqp[j * M_ + m];
            g_rss[m] = rsqrtf(fmaxf(s, 1e-12f));
        }
    }
    gbar();

    // ---- P3: sim gemm (16 tiles x 32 ks = 512 tasks, Kper=32) ----
    for (int t = blockIdx.x; t < 16 * KS_SIM; t += G)
        gemm_half(g_comb, g_emT, g_simp, 2048, t & 15, t >> 4, 1024 / KS_SIM, 32, as);
    gbar();

    // ---- P4: softmax (32 tasks) ----
    for (int t = blockIdx.x; t < 32; t += G) {
        int b = t;
        float zi = g_zinv[b];
        float s[8];
        float mx = -3.0e38f;
#pragma unroll
        for (int j = 0; j < 8; ++j) {
            int m = tx + j * 256;
            float dot = 0.f;
#pragma unroll
            for (int p = 0; p < KS_SIM; ++p) dot += g_simp[p * (M_ * B_) + m * B_ + b];
            float v = dot * zi * g_rss[m] * (1.0f / 0.75f);
            s[j] = v; mx = fmaxf(mx, v);
        }
        mx = bmax256(mx, sb);
        float sum = 0.f;
#pragma unroll
        for (int j = 0; j < 8; ++j) { s[j] = expf(s[j] - mx); sum += s[j]; }
        sum = bsum256(sum, sb);
        float inv = 1.0f / sum;
#pragma unroll
        for (int j = 0; j < 8; ++j) g_attn[(tx + j * 256) * B_ + b] = s[j] * inv;
    }
    gbar();

    // ---- P5: m_t partials (8 tiles x 32 ms = 256 tasks) + trace update (1024 tasks) ----
    for (int t = blockIdx.x; t < 256 + 1024; t += G) {
        if (t < 256) {
            // mt: like gemm_half but W computed on the fly; m-chunk 64
            int tile = t & 7, ms = t >> 3;
            int h = tile * 128 + (tx >> 1);
            int half16 = (tx & 1) * 16;
            int m0 = ms * 64;
            ull acc[8];
#pragma unroll
            for (int j = 0; j < 8; ++j) acc[j] = 0ull;
            {
                const float4* Ap = reinterpret_cast<const float4*>(g_attn + m0 * B_);
                float4* asp = reinterpret_cast<float4*>(as);
                for (int i = tx; i < 64 * 8; i += 256) asp[i] = Ap[i];
            }
            __syncthreads();
#pragma unroll 4
            for (int kk = 0; kk < 64; ++kk) {
                int m = m0 + kk;
                float em = fmaf(0.5f, trace[(size_t)m * H_ + h], bank[(size_t)m * H_ + h]);
                ull w2 = pack2(em);
                const ulonglong2* ap = reinterpret_cast<const ulonglong2*>(&as[kk * B_ + half16]);
#pragma unroll
                for (int j = 0; j < 4; ++j) {
                    ulonglong2 a2 = ap[j];
                    fma2(acc[2 * j], a2.x, w2);
                    fma2(acc[2 * j + 1], a2.y, w2);
                }
            }
            __syncthreads();
            ull* dst = reinterpret_cast<ull*>(&g_mtp[((size_t)ms * H_ + h) * B_ + half16]);
#pragma unroll
            for (int j = 0; j < 8; ++j) dst[j] = acc[j];
        } else {
            // trace update: h-tile 128 wide (2 threads/h), m-group of 8 (x2 halves of M)
            int tt = t - 256;
            int h = (tt & 7) * 128 + (tx >> 1);
            int lohi = tx & 1;                  // 0: m in [0,1024), 1: m+1024
            int m0 = (tt >> 3) * 8;
            for (int i = tx; i < 16 * B_; i += 256) {
                int r = i >> 5, b = i & 31;
                int m = (r < 8) ? (m0 + r) : (1024 + m0 + r - 8);
                as[i] = g_attn[m * B_ + b];
            }
            __syncthreads();
            ull z2[8];
            {
                const ull* zp = reinterpret_cast<const ull*>(&g_comb[h * B_ + lohi * 16]);
#pragma unroll
                for (int j = 0; j < 8; ++j) z2[j] = zp[j];
            }
#pragma unroll 2
            for (int mi = 0; mi < 8; ++mi) {
                int m = m0 + mi;
                // this thread's half-batch partial for both m and m+1024 rows
                ull a0 = 0ull, a1 = 0ull;
                const ull* ap0 = reinterpret_cast<const ull*>(&as[mi * B_ + lohi * 16]);
                const ull* ap1 = reinterpret_cast<const ull*>(&as[(8 + mi) * B_ + lohi * 16]);
#pragma unroll
                for (int j = 0; j < 8; ++j) { fma2(a0, ap0[j], z2[j]); fma2(a1, ap1[j], z2[j]); }
                float s0 = hadd2(a0), s1 = hadd2(a1);
                s0 += __shfl_xor_sync(0xffffffffu, s0, 1);
                s1 += __shfl_xor_sync(0xffffffffu, s1, 1);
                // lane lohi==0 finishes row m; lane lohi==1 finishes row m+1024
                int mrow = m + lohi * 1024;
                float sdot = lohi ? s1 : s0;
                uint32_t e = (uint32_t)(mrow * 1024 + h);
                float nz = bits2normal(threefry_xor(0u, e)) * 0.001f;
                float tv = trace[(size_t)mrow * H_ + h];
                float r = tv * 0.95f + 0.05f * (sdot * (1.0f / 32.0f) + nz);
                out[32768 + mrow * 1024 + h] = fminf(fmaxf(r, -0.1f), 0.1f);
            }
            __syncthreads();
        }
    }
    gbar();

    // ---- P6: reduce m_t partials (128 tasks) ----
    for (int t = blockIdx.x; t < 128; t += G) {
        int idx = t * 256 + tx;
        float s = 0.f;
#pragma unroll
        for (int p = 0; p < MS_MT; ++p) s += g_mtp[p * (H_ * B_) + idx];
        g_comb[H_ * B_ + idx] = s;
    }
    gbar();

    // ---- P7: int gemm (24 tiles x 32 ks = 768 tasks, Kper=96) ----
    for (int t = blockIdx.x; t < 24 * KS_INT; t += G)
        gemm_half(g_comb, W_int, g_intp, 3072, t % 24, t / 24, 3072 / KS_INT, 48, as);
    gbar();

    // ---- P8: intfin (384 tasks) ----
    for (int t = blockIdx.x; t < 384; t += G) {
        int idx = t * 256 + tx;
        int n = idx >> 5;
        float s = b_int[n];
#pragma unroll
        for (int p = 0; p < KS_INT; ++p) s += g_intp[p * (K3_ * B_) + idx];
        g_hid[idx] = fmaxf(s, 0.f);
    }
    gbar();

    // ---- P9: out gemm (8 tiles x 64 ks = 512 tasks, Kper=48) ----
    for (int t = blockIdx.x; t < 8 * KS_OUT; t += G)
        gemm_half(g_hid, W_out, g_outp, 1024, t & 7, t >> 3, 3072 / KS_OUT, 48, as);
    gbar();

    // ---- P10: outfin (32 tasks) ----
    for (int t = blockIdx.x; t < 32; t += G) {
        int b = t;
        float v[4], ls = 0.f, lss = 0.f;
#pragma unroll
        for (int j = 0; j < 4; ++j) {
            int h = tx + j * 256;
            float s = b_out[h];
#pragma unroll
            for (int p = 0; p < KS_OUT; ++p) s += g_outp[p * (H_ * B_) + h * B_ + b];
            s = fmaxf(s, 0.f);
            v[j] = s; ls += s; lss += s * s;
        }
        float mean = bsum256(ls, sb) * (1.0f / H_);
        float msq  = bsum256(lss, sb) * (1.0f / H_);
        float rstd = rsqrtf(msq - mean * mean + 1e-6f);
#pragma unroll
        for (int j = 0; j < 4; ++j) {
            int h = tx + j * 256;
            out[b * H_ + h] = (v[j] - mean) * rstd * gamma2[h] + beta2[h];
        }
    }
}

// ---------------- launch ----------------
extern "C" void kernel_launch(void* const* d_in, const int* in_sizes, int n_in,
                              void* d_out, int out_size) {
    const float* x      = (const float*)d_in[0];
    const float* prev_h = (const float*)d_in[1];
    const float* trace  = (const float*)d_in[2];
    const float* bank   = (const float*)d_in[3];
    const float* W_enc  = (const float*)d_in[4];
    const float* b_enc  = (const float*)d_in[5];
    const float* gamma1 = (const float*)d_in[6];
    const float* beta1  = (const float*)d_in[7];
    const float* W_int  = (const float*)d_in[8];
    const float* b_int  = (const float*)d_in[9];
    const float* W_out  = (const float*)d_in[10];
    const float* b_out  = (const float*)d_in[11];
    const float* gamma2 = (const float*)d_in[12];
    const float* beta2  = (const float*)d_in[13];
    float* out = (float*)d_out;

    k_fused<<<GRID_, 256>>>(x, prev_h, trace, bank, W_enc, b_enc, gamma1, beta1,
                            W_int, b_int, W_out, b_out, gamma2, beta2, out);
}

// round 9
// speedup vs baseline: 2.3735x; 1.1248x over previous
#include <cuda_runtime.h>
#include <cstdint>

typedef unsigned long long ull;

#define B_  32
#define D_  1024
#define H_  1024
#define M_  2048
#define K3_ 3072

#define GRID_ 296          // 2 CTAs per SM

#define KS_ENC 16
#define KS_SIM 16
#define KS_INT 16
#define KS_OUT 32
#define MS_MT  16

// ---------------- scratch ----------------
__device__ float g_comb[K3_ * B_];              // [k][b]: 0..1023=z, 1024..2047=m_t, 2048..3071=prev_h
__device__ float g_zinv[B_];
__device__ float g_encp[KS_ENC * H_ * B_];
__device__ float g_emT[H_ * M_];                // eff_mem transposed [h][m]
__device__ float g_ssqp[32 * M_];
__device__ float g_rss[M_];
__device__ float g_simp[KS_SIM * M_ * B_];
__device__ float g_attn[M_ * B_];
__device__ float g_mtp[MS_MT * H_ * B_];
__device__ float g_intp[KS_INT * K3_ * B_];
__device__ float g_hid[K3_ * B_];
__device__ float g_outp[KS_OUT * H_ * B_];

__device__ unsigned g_cnt = 0;
__device__ unsigned g_gen = 0;

// ---------------- helpers ----------------
__device__ __forceinline__ ull pack2(float w) {
    ull r; asm("mov.b64 %0, {%1, %1};" : "=l"(r) : "f"(w)); return r;
}
__device__ __forceinline__ void fma2(ull& d, ull a, ull b) {
    asm("fma.rn.f32x2 %0, %1, %2, %0;" : "+l"(d) : "l"(a), "l"(b));
}
__device__ __forceinline__ float hadd2(ull a) {
    float2 f = *reinterpret_cast<float2*>(&a); return f.x + f.y;
}

__device__ __forceinline__ void gbar() {
    __syncthreads();
    if (threadIdx.x == 0) {
        __threadfence();
        unsigned gen = *(volatile unsigned*)&g_gen;
        if (atomicAdd(&g_cnt, 1u) == (unsigned)(gridDim.x - 1)) {
            g_cnt = 0;
            __threadfence();
            atomicAdd(&g_gen, 1u);
        } else {
            while (*(volatile unsigned*)&g_gen == gen) { __nanosleep(32); }
            __threadfence();
        }
    }
    __syncthreads();
}

__device__ __forceinline__ float bsum256(float v, float* sb) {
    int tx = threadIdx.x;
#pragma unroll
    for (int o = 16; o > 0; o >>= 1) v += __shfl_xor_sync(0xffffffffu, v, o);
    if ((tx & 31) == 0) sb[tx >> 5] = v;
    __syncthreads();
    float r = (tx < 8) ? sb[tx] : 0.f;
    if (tx < 32) {
#pragma unroll
        for (int o = 4; o > 0; o >>= 1) r += __shfl_xor_sync(0xffffffffu, r, o);
        if (tx == 0) sb[0] = r;
    }
    __syncthreads();
    r = sb[0];
    __syncthreads();
    return r;
}
__device__ __forceinline__ float bmax256(float v, float* sb) {
    int tx = threadIdx.x;
#pragma unroll
    for (int o = 16; o > 0; o >>= 1) v = fmaxf(v, __shfl_xor_sync(0xffffffffu, v, o));
    if ((tx & 31) == 0) sb[tx >> 5] = v;
    __syncthreads();
    float r = (tx < 8) ? sb[tx] : -3.0e38f;
    if (tx < 32) {
#pragma unroll
        for (int o = 4; o > 0; o >>= 1) r = fmaxf(r, __shfl_xor_sync(0xffffffffu, r, o));
        if (tx == 0) sb[0] = r;
    }
    __syncthreads();
    r = sb[0];
    __syncthreads();
    return r;
}

// jax threefry2x32, key=(0,42), partitionable: counter=(0,e), bits = o0^o1
__device__ __forceinline__ uint32_t rotl32(uint32_t x, int r) { return (x << r) | (x >> (32 - r)); }
__device__ __forceinline__ uint32_t threefry_xor(uint32_t c0, uint32_t c1) {
    const uint32_t ks0 = 0u, ks1 = 42u, ks2 = 0u ^ 42u ^ 0x1BD11BDAu;
    uint32_t x0 = c0 + ks0, x1 = c1 + ks1;
#define TF_R4(a,b,c,d) \
    x0 += x1; x1 = rotl32(x1,a); x1 ^= x0; \
    x0 += x1; x1 = rotl32(x1,b); x1 ^= x0; \
    x0 += x1; x1 = rotl32(x1,c); x1 ^= x0; \
    x0 += x1; x1 = rotl32(x1,d); x1 ^= x0;
    TF_R4(13,15,26,6)  x0 += ks1; x1 += ks2 + 1u;
    TF_R4(17,29,16,24) x0 += ks2; x1 += ks0 + 2u;
    TF_R4(13,15,26,6)  x0 += ks0; x1 += ks1 + 3u;
    TF_R4(17,29,16,24) x0 += ks1; x1 += ks2 + 4u;
    TF_R4(13,15,26,6)  x0 += ks2; x1 += ks0 + 5u;
#undef TF_R4
    return x0 ^ x1;
}
__device__ __forceinline__ float bits2normal(uint32_t bits) {
    uint32_t fb = (bits >> 9) | 0x3F800000u;
    float u01 = __uint_as_float(fb) - 1.0f;
    const float lo = -0.99999994f;
    float u = fmaf(u01, 1.99999994f, lo);
    u = fmaxf(lo, u);
    return 1.4142135623730951f * erfinvf(u);
}

// full-batch split-K GEMM task: 256 threads, n-tile 256 wide, 1 thread/column,
// 16 f32x2 accumulators (full batch of 32). W prefetched 4-deep.
// P[ks][n][b] = sum_{k in split} A[k][b]*W[k][n]
__device__ __forceinline__ void gemm_full(const float* __restrict__ A, const float* __restrict__ W,
                                          float* __restrict__ P, int N, int tile, int ks,
                                          int Kper, int kchunk, float* as) {
    int n = tile * 256 + threadIdx.x;
    int k0 = ks * Kper;
    ull acc[16];
#pragma unroll
    for (int j = 0; j < 16; ++j) acc[j] = 0ull;
    for (int kc = 0; kc < Kper; kc += kchunk) {
        const float4* Ap = reinterpret_cast<const float4*>(A + (k0 + kc) * B_);
        float4* asp = reinterpret_cast<float4*>(as);
        for (int i = threadIdx.x; i < kchunk * 8; i += 256) asp[i] = Ap[i];
        __syncthreads();
        const float* Wp = W + (size_t)(k0 + kc) * N + n;
        for (int kk = 0; kk < kchunk; kk += 4) {
            float w0 = Wp[0];
            float w1 = Wp[N];
            float w2 = Wp[2 * (size_t)N];
            float w3 = Wp[3 * (size_t)N];
            Wp += 4 * (size_t)N;
#pragma unroll
            for (int q = 0; q < 4; ++q) {
                float wv = (q == 0) ? w0 : (q == 1) ? w1 : (q == 2) ? w2 : w3;
                ull wq = pack2(wv);
                const ulonglong2* ap = reinterpret_cast<const ulonglong2*>(&as[(kk + q) * B_]);
#pragma unroll
                for (int j = 0; j < 8; ++j) {
                    ulonglong2 a2 = ap[j];
                    fma2(acc[2 * j], a2.x, wq);
                    fma2(acc[2 * j + 1], a2.y, wq);
                }
            }
        }
        __syncthreads();
    }
    ull* dst = reinterpret_cast<ull*>(P + ((size_t)ks * N + n) * B_);
#pragma unroll
    for (int j = 0; j < 16; ++j) dst[j] = acc[j];
}

// ---------------- the persistent kernel ----------------
__global__ void __launch_bounds__(256, 2)
k_fused(const float* __restrict__ x, const float* __restrict__ prev_h,
        const float* __restrict__ trace, const float* __restrict__ bank,
        const float* __restrict__ W_enc, const float* __restrict__ b_enc,
        const float* __restrict__ gamma1, const float* __restrict__ beta1,
        const float* __restrict__ W_int, const float* __restrict__ b_int,
        const float* __restrict__ W_out, const float* __restrict__ b_out,
        const float* __restrict__ gamma2, const float* __restrict__ beta2,
        float* __restrict__ out) {
    __shared__ float as[64 * B_ + 64];     // 8.5 KB
    __shared__ float sb[8];
    const int tx = threadIdx.x;
    const int G = gridDim.x;

    // ---- P1: eff_mem transpose + ssq (2048 tasks) + enc gemm (4 tiles x 16 ks = 64 tasks) ----
    for (int t = blockIdx.x; t < 2048 + 4 * KS_ENC; t += G) {
        if (t < 2048) {
            int r = tx >> 3, c4 = (tx & 7) * 4;
            int m0 = (t & 63) * 32, h0 = (t >> 6) * 32;
            size_t base = (size_t)(m0 + r) * H_ + h0 + c4;
            float4 bv = *reinterpret_cast<const float4*>(bank + base);
            float4 tv = *reinterpret_cast<const float4*>(trace + base);
            float4 em;
            em.x = fmaf(0.5f, tv.x, bv.x); em.y = fmaf(0.5f, tv.y, bv.y);
            em.z = fmaf(0.5f, tv.z, bv.z); em.w = fmaf(0.5f, tv.w, bv.w);
            as[r * 33 + c4] = em.x; as[r * 33 + c4 + 1] = em.y;
            as[r * 33 + c4 + 2] = em.z; as[r * 33 + c4 + 3] = em.w;
            float ss = em.x * em.x + em.y * em.y + em.z * em.z + em.w * em.w;
#pragma unroll
            for (int o = 4; o > 0; o >>= 1) ss += __shfl_down_sync(0xffffffffu, ss, o, 8);
            if ((tx & 7) == 0) g_ssqp[(t >> 6) * M_ + m0 + r] = ss;
            __syncthreads();
            float4 o4;
            o4.x = as[(c4 + 0) * 33 + r]; o4.y = as[(c4 + 1) * 33 + r];
            o4.z = as[(c4 + 2) * 33 + r]; o4.w = as[(c4 + 3) * 33 + r];
            *reinterpret_cast<float4*>(&g_emT[(size_t)(h0 + r) * M_ + m0 + c4]) = o4;
            __syncthreads();
        } else {
            // enc gemm: A gathered from x[b][k]; tile q&3, ks q>>2, Kper=64
            int q = t - 2048;
            int tile = q & 3, ks = q >> 2;
            int n = tile * 256 + tx;
            int k0 = ks * 64;
            for (int i = tx; i < 64 * B_; i += 256) {
                int k = i >> 5, b = i & 31;
                as[k * B_ + b] = x[b * D_ + k0 + k];
            }
            __syncthreads();
            ull acc[16];
#pragma unroll
            for (int j = 0; j < 16; ++j) acc[j] = 0ull;
            const float* Wp = W_enc + (size_t)k0 * H_ + n;
            for (int kk = 0; kk < 64; kk += 4) {
                float w0 = Wp[0];
                float w1 = Wp[H_];
                float w2 = Wp[2 * H_];
                float w3 = Wp[3 * H_];
                Wp += 4 * H_;
#pragma unroll
                for (int qq = 0; qq < 4; ++qq) {
                    float wv = (qq == 0) ? w0 : (qq == 1) ? w1 : (qq == 2) ? w2 : w3;
                    ull wq = pack2(wv);
                    const ulonglong2* ap = reinterpret_cast<const ulonglong2*>(&as[(kk + qq) * B_]);
#pragma unroll
                    for (int j = 0; j < 8; ++j) {
                        ulonglong2 a2 = ap[j];
                        fma2(acc[2 * j], a2.x, wq);
                        fma2(acc[2 * j + 1], a2.y, wq);
                    }
                }
            }
            __syncthreads();
            ull* dst = reinterpret_cast<ull*>(g_encp + ((size_t)ks * H_ + n) * B_);
#pragma unroll
            for (int j = 0; j < 16; ++j) dst[j] = acc[j];
        }
    }
    gbar();

    // ---- P2: encfin (32 tasks) + ssqred (8 tasks) ----
    for (int t = blockIdx.x; t < 40; t += G) {
        if (t < 32) {
            int b = t;
            float v[4], ls = 0.f, lss = 0.f;
#pragma unroll
            for (int j = 0; j < 4; ++j) {
                int h = tx + j * 256;
                float s = b_enc[h];
#pragma unroll
                for (int p = 0; p < KS_ENC; ++p) s += g_encp[p * (H_ * B_) + h * B_ + b];
                s = fmaxf(s, 0.f);
                v[j] = s; ls += s; lss += s * s;
            }
            float mean = bsum256(ls, sb) * (1.0f / H_);
            float msq  = bsum256(lss, sb) * (1.0f / H_);
            float rstd = rsqrtf(msq - mean * mean + 1e-6f);
            float zss = 0.f;
#pragma unroll
            for (int j = 0; j < 4; ++j) {
                int h = tx + j * 256;
                float z = (v[j] - mean) * rstd * gamma1[h] + beta1[h];
                g_comb[h * B_ + b] = z;
                zss += z * z;
                g_comb[(2048 + h) * B_ + b] = prev_h[b * H_ + h];
            }
            float zs = bsum256(zss, sb);
            if (tx == 0) g_zinv[b] = rsqrtf(fmaxf(zs, 1e-12f));
        } else {
            int m = (t - 32) * 256 + tx;
            float s = 0.f;
#pragma unroll
            for (int j = 0; j < 32; ++j) s += g_ssqp[j * M_ + m];
            g_rss[m] = rsqrtf(fmaxf(s, 1e-12f));
        }
    }
    gbar();

    // ---- P3: sim gemm (8 tiles x 16 ks = 128 tasks, Kper=64) ----
    for (int t = blockIdx.x; t < 8 * KS_SIM; t += G)
        gemm_full(g_comb, g_emT, g_simp, 2048, t & 7, t >> 3, 1024 / KS_SIM, 64, as);
    gbar();

    // ---- P4: softmax (32 tasks) ----
    for (int t = blockIdx.x; t < 32; t += G) {
        int b = t;
        float zi = g_zinv[b];
        float s[8];
        float mx = -3.0e38f;
#pragma unroll
        for (int j = 0; j < 8; ++j) {
            int m = tx + j * 256;
            float dot = 0.f;
#pragma unroll
            for (int p = 0; p < KS_SIM; ++p) dot += g_simp[p * (M_ * B_) + m * B_ + b];
            float v = dot * zi * g_rss[m] * (1.0f / 0.75f);
            s[j] = v; mx = fmaxf(mx, v);
        }
        mx = bmax256(mx, sb);
        float sum = 0.f;
#pragma unroll
        for (int j = 0; j < 8; ++j) { s[j] = expf(s[j] - mx); sum += s[j]; }
        sum = bsum256(sum, sb);
        float inv = 1.0f / sum;
#pragma unroll
        for (int j = 0; j < 8; ++j) g_attn[(tx + j * 256) * B_ + b] = s[j] * inv;
    }
    gbar();

    // ---- P5: m_t partials (4 tiles x 16 ms = 64 tasks, Kper=128m) + trace update (512 tasks) ----
    for (int t = blockIdx.x; t < 64 + 512; t += G) {
        if (t < 64) {
            int tile = t & 3, ms = t >> 2;
            int h = tile * 256 + tx;
            ull acc[16];
#pragma unroll
            for (int j = 0; j < 16; ++j) acc[j] = 0ull;
            for (int kc = 0; kc < 128; kc += 64) {
                int m0 = ms * 128 + kc;
                {
                    const float4* Ap = reinterpret_cast<const float4*>(g_attn + m0 * B_);
                    float4* asp = reinterpret_cast<float4*>(as);
                    for (int i = tx; i < 64 * 8; i += 256) asp[i] = Ap[i];
                }
                __syncthreads();
                const float* bp = bank + (size_t)m0 * H_ + h;
                const float* tp = trace + (size_t)m0 * H_ + h;
                for (int kk = 0; kk < 64; kk += 4) {
                    float e0 = fmaf(0.5f, tp[0], bp[0]);
                    float e1 = fmaf(0.5f, tp[H_], bp[H_]);
                    float e2 = fmaf(0.5f, tp[2 * H_], bp[2 * H_]);
                    float e3 = fmaf(0.5f, tp[3 * H_], bp[3 * H_]);
                    bp += 4 * H_; tp += 4 * H_;
#pragma unroll
                    for (int qq = 0; qq < 4; ++qq) {
                        float wv = (qq == 0) ? e0 : (qq == 1) ? e1 : (qq == 2) ? e2 : e3;
                        ull wq = pack2(wv);
                        const ulonglong2* ap = reinterpret_cast<const ulonglong2*>(&as[(kk + qq) * B_]);
#pragma unroll
                        for (int j = 0; j < 8; ++j) {
                            ulonglong2 a2 = ap[j];
                            fma2(acc[2 * j], a2.x, wq);
                            fma2(acc[2 * j + 1], a2.y, wq);
                        }
                    }
                }
                __syncthreads();
            }
            ull* dst = reinterpret_cast<ull*>(&g_mtp[((size_t)ms * H_ + h) * B_]);
#pragma unroll
            for (int j = 0; j < 16; ++j) dst[j] = acc[j];
        } else {
            // trace update: full batch per thread; h-tile 256, m-group of 8 (both M halves)
            int tt = t - 64;
            int h = (tt & 3) * 256 + tx;
            int m0 = (tt >> 2) * 8;
            for (int i = tx; i < 16 * B_; i += 256) {
                int r = i >> 5, b = i & 31;
                int m = (r < 8) ? (m0 + r) : (1024 + m0 + r - 8);
                as[i] = g_attn[m * B_ + b];
            }
            __syncthreads();
            ull z2[16];
            const ull* zp = reinterpret_cast<const ull*>(&g_comb[h * B_]);
#pragma unroll
            for (int j = 0; j < 16; ++j) z2[j] = zp[j];
#pragma unroll 2
            for (int mi = 0; mi < 8; ++mi) {
                int m = m0 + mi;
                ull a0 = 0ull, a1 = 0ull;
                const ull* ap0 = reinterpret_cast<const ull*>(&as[mi * B_]);
                const ull* ap1 = reinterpret_cast<const ull*>(&as[(8 + mi) * B_]);
#pragma unroll
                for (int j = 0; j < 16; ++j) { fma2(a0, ap0[j], z2[j]); fma2(a1, ap1[j], z2[j]); }
                float s0 = hadd2(a0), s1 = hadd2(a1);
                uint32_t e0 = (uint32_t)(m * 1024 + h);
                uint32_t e1 = e0 + 1048576u;
                float n0 = bits2normal(threefry_xor(0u, e0)) * 0.001f;
                float n1 = bits2normal(threefry_xor(0u, e1)) * 0.001f;
                float t0 = trace[(size_t)m * H_ + h];
                float t1 = trace[(size_t)(m + 1024) * H_ + h];
                float r0 = t0 * 0.95f + 0.05f * (s0 * (1.0f / 32.0f) + n0);
                float r1 = t1 * 0.95f + 0.05f * (s1 * (1.0f / 32.0f) + n1);
                out[32768 + m * 1024 + h] = fminf(fmaxf(r0, -0.1f), 0.1f);
                out[32768 + (m + 1024) * 1024 + h] = fminf(fmaxf(r1, -0.1f), 0.1f);
            }
            __syncthreads();
        }
    }
    gbar();

    // ---- P6: reduce m_t partials (128 tasks) ----
    for (int t = blockIdx.x; t < 128; t += G) {
        int idx = t * 256 + tx;
        float s = 0.f;
#pragma unroll
        for (int p = 0; p < MS_MT; ++p) s += g_mtp[p * (H_ * B_) + idx];
        g_comb[H_ * B_ + idx] = s;
    }
    gbar();

    // ---- P7: int gemm (12 tiles x 16 ks = 192 tasks, Kper=192) ----
    for (int t = blockIdx.x; t < 12 * KS_INT; t += G)
        gemm_full(g_comb, W_int, g_intp, 3072, t % 12, t / 12, 3072 / KS_INT, 64, as);
    gbar();

    // ---- P8: intfin (384 tasks) ----
    for (int t = blockIdx.x; t < 384; t += G) {
        int idx = t * 256 + tx;
        int n = idx >> 5;
        float s = b_int[n];
#pragma unroll
        for (int p = 0; p < KS_INT; ++p) s += g_intp[p * (K3_ * B_) + idx];
        g_hid[idx] = fmaxf(s, 0.f);
    }
    gbar();

    // ---- P9: out gemm (4 tiles x 32 ks = 128 tasks, Kper=96) ----
    for (int t = blockIdx.x; t < 4 * KS_OUT; t += G)
        gemm_full(g_hid, W_out, g_outp, 1024, t & 3, t >> 2, 3072 / KS_OUT, 48, as);
    gbar();

    // ---- P10: outfin (32 tasks) ----
    for (int t = blockIdx.x; t < 32; t += G) {
        int b = t;
        float v[4], ls = 0.f, lss = 0.f;
#pragma unroll
        for (int j = 0; j < 4; ++j) {
            int h = tx + j * 256;
            float s = b_out[h];
#pragma unroll
            for (int p = 0; p < KS_OUT; ++p) s += g_outp[p * (H_ * B_) + h * B_ + b];
            s = fmaxf(s, 0.f);
            v[j] = s; ls += s; lss += s * s;
        }
        float mean = bsum256(ls, sb) * (1.0f / H_);
        float msq  = bsum256(lss, sb) * (1.0f / H_);
        float rstd = rsqrtf(msq - mean * mean + 1e-6f);
#pragma unroll
        for (int j = 0; j < 4; ++j) {
            int h = tx + j * 256;
            out[b * H_ + h] = (v[j] - mean) * rstd * gamma2[h] + beta2[h];
        }
    }
}

// ---------------- launch ----------------
extern "C" void kernel_launch(void* const* d_in, const int* in_sizes, int n_in,
                              void* d_out, int out_size) {
    const float* x      = (const float*)d_in[0];
    const float* prev_h = (const float*)d_in[1];
    const float* trace  = (const float*)d_in[2];
    const float* bank   = (const float*)d_in[3];
    const float* W_enc  = (const float*)d_in[4];
    const float* b_enc  = (const float*)d_in[5];
    const float* gamma1 = (const float*)d_in[6];
    const float* beta1  = (const float*)d_in[7];
    const float* W_int  = (const float*)d_in[8];
    const float* b_int  = (const float*)d_in[9];
    const float* W_out  = (const float*)d_in[10];
    const float* b_out  = (const float*)d_in[11];
    const float* gamma2 = (const float*)d_in[12];
    const float* beta2  = (const float*)d_in[13];
    float* out = (float*)d_out;

    k_fused<<<GRID_, 256>>>(x, prev_h, trace, bank, W_enc, b_enc, gamma1, beta1,
                            W_int, b_int, W_out, b_out, gamma2, beta2, out);
}

// round 10
// speedup vs baseline: 3.3677x; 1.4189x over previous
#include <cuda_runtime.h>
#include <cstdint>

typedef unsigned long long ull;

#define B_  32
#define D_  1024
#define H_  1024
#define M_  2048
#define K3_ 3072

#define GRID_ 296          // 2 CTAs per SM

#define KS_ENC 16
#define KS_SIM 32
#define KS_INT 24
#define KS_OUT 48
#define MS_MT  16

// ---------------- scratch ----------------
__device__ float g_comb[K3_ * B_];              // [k][b]: 0..1023=z, 1024..2047=m_t, 2048..3071=prev_h
__device__ float g_zinv[B_];
__device__ float g_encp[KS_ENC * H_ * B_];
__device__ float g_zpre[H_ * B_];               // relu(enc+bias), pre-LN
__device__ float g_emT[H_ * M_];                // eff_mem transposed [h][m]
__device__ float g_ssqp[32 * M_];
__device__ float g_rss[M_];
__device__ float g_simp[KS_SIM * M_ * B_];
__device__ float g_sim[M_ * B_];                // reduced+scaled sim
__device__ float g_attn[M_ * B_];
__device__ float g_mtp[MS_MT * H_ * B_];
__device__ float g_intp[KS_INT * K3_ * B_];
__device__ float g_hid[K3_ * B_];
__device__ float g_outp[KS_OUT * H_ * B_];
__device__ float g_opre[H_ * B_];               // relu(out+bias), pre-LN

__device__ unsigned g_cnt = 0;
__device__ unsigned g_gen = 0;

// ---------------- helpers ----------------
__device__ __forceinline__ ull pack2(float w) {
    ull r; asm("mov.b64 %0, {%1, %1};" : "=l"(r) : "f"(w)); return r;
}
__device__ __forceinline__ void fma2(ull& d, ull a, ull b) {
    asm("fma.rn.f32x2 %0, %1, %2, %0;" : "+l"(d) : "l"(a), "l"(b));
}
__device__ __forceinline__ float hadd2(ull a) {
    float2 f = *reinterpret_cast<float2*>(&a); return f.x + f.y;
}

__device__ __forceinline__ void gbar() {
    __syncthreads();
    if (threadIdx.x == 0) {
        __threadfence();
        unsigned gen = *(volatile unsigned*)&g_gen;
        if (atomicAdd(&g_cnt, 1u) == (unsigned)(gridDim.x - 1)) {
            g_cnt = 0;
            __threadfence();
            atomicAdd(&g_gen, 1u);
        } else {
            while (*(volatile unsigned*)&g_gen == gen) { __nanosleep(32); }
            __threadfence();
        }
    }
    __syncthreads();
}

__device__ __forceinline__ float bsum256(float v, float* sb) {
    int tx = threadIdx.x;
#pragma unroll
    for (int o = 16; o > 0; o >>= 1) v += __shfl_xor_sync(0xffffffffu, v, o);
    if ((tx & 31) == 0) sb[tx >> 5] = v;
    __syncthreads();
    float r = (tx < 8) ? sb[tx] : 0.f;
    if (tx < 32) {
#pragma unroll
        for (int o = 4; o > 0; o >>= 1) r += __shfl_xor_sync(0xffffffffu, r, o);
        if (tx == 0) sb[0] = r;
    }
    __syncthreads();
    r = sb[0];
    __syncthreads();
    return r;
}
__device__ __forceinline__ float bmax256(float v, float* sb) {
    int tx = threadIdx.x;
#pragma unroll
    for (int o = 16; o > 0; o >>= 1) v = fmaxf(v, __shfl_xor_sync(0xffffffffu, v, o));
    if ((tx & 31) == 0) sb[tx >> 5] = v;
    __syncthreads();
    float r = (tx < 8) ? sb[tx] : -3.0e38f;
    if (tx < 32) {
#pragma unroll
        for (int o = 4; o > 0; o >>= 1) r = fmaxf(r, __shfl_xor_sync(0xffffffffu, r, o));
        if (tx == 0) sb[0] = r;
    }
    __syncthreads();
    r = sb[0];
    __syncthreads();
    return r;
}

// jax threefry2x32, key=(0,42), partitionable: counter=(0,e), bits = o0^o1
__device__ __forceinline__ uint32_t rotl32(uint32_t x, int r) { return (x << r) | (x >> (32 - r)); }
__device__ __forceinline__ uint32_t threefry_xor(uint32_t c0, uint32_t c1) {
    const uint32_t ks0 = 0u, ks1 = 42u, ks2 = 0u ^ 42u ^ 0x1BD11BDAu;
    uint32_t x0 = c0 + ks0, x1 = c1 + ks1;
#define TF_R4(a,b,c,d) \
    x0 += x1; x1 = rotl32(x1,a); x1 ^= x0; \
    x0 += x1; x1 = rotl32(x1,b); x1 ^= x0; \
    x0 += x1; x1 = rotl32(x1,c); x1 ^= x0; \
    x0 += x1; x1 = rotl32(x1,d); x1 ^= x0;
    TF_R4(13,15,26,6)  x0 += ks1; x1 += ks2 + 1u;
    TF_R4(17,29,16,24) x0 += ks2; x1 += ks0 + 2u;
    TF_R4(13,15,26,6)  x0 += ks0; x1 += ks1 + 3u;
    TF_R4(17,29,16,24) x0 += ks1; x1 += ks2 + 4u;
    TF_R4(13,15,26,6)  x0 += ks2; x1 += ks0 + 5u;
#undef TF_R4
    return x0 ^ x1;
}
__device__ __forceinline__ float bits2normal(uint32_t bits) {
    uint32_t fb = (bits >> 9) | 0x3F800000u;
    float u01 = __uint_as_float(fb) - 1.0f;
    const float lo = -0.99999994f;
    float u = fmaf(u01, 1.99999994f, lo);
    u = fmaxf(lo, u);
    return 1.4142135623730951f * erfinvf(u);
}

// consume 8 staged-weight values against 8 smem A rows
__device__ __forceinline__ void consume8(ull* acc, const float* wbuf, const float* as, int kk) {
#pragma unroll
    for (int q = 0; q < 8; ++q) {
        ull wq = pack2(wbuf[q]);
        const ulonglong2* ap = reinterpret_cast<const ulonglong2*>(&as[(kk + q) * B_]);
#pragma unroll
        for (int j = 0; j < 8; ++j) {
            ulonglong2 a2 = ap[j];
            fma2(acc[2 * j], a2.x, wq);
            fma2(acc[2 * j + 1], a2.y, wq);
        }
    }
}

// full-batch split-K GEMM task: 256 threads, n-tile 256 wide, 1 thread/column,
// 16 f32x2 accumulators, 8-deep software-pipelined weight prefetch.
// P[ks][n][b] = sum_{k in split} A[k][b]*W[k][n]
__device__ __forceinline__ void gemm_full(const float* __restrict__ A, const float* __restrict__ W,
                                          float* __restrict__ P, int N, int tile, int ks,
                                          int Kper, int kchunk, float* as) {
    int n = tile * 256 + threadIdx.x;
    int k0 = ks * Kper;
    ull acc[16];
#pragma unroll
    for (int j = 0; j < 16; ++j) acc[j] = 0ull;
    for (int kc = 0; kc < Kper; kc += kchunk) {
        const float4* Ap = reinterpret_cast<const float4*>(A + (k0 + kc) * B_);
        float4* asp = reinterpret_cast<float4*>(as);
        for (int i = threadIdx.x; i < kchunk * 8; i += 256) asp[i] = Ap[i];
        __syncthreads();
        const float* Wp = W + (size_t)(k0 + kc) * N + n;
        float wbuf[8];
#pragma unroll
        for (int q = 0; q < 8; ++q) wbuf[q] = Wp[(size_t)q * N];
        int kk = 0;
        for (; kk < kchunk - 8; kk += 8) {
            float wnext[8];
#pragma unroll
            for (int q = 0; q < 8; ++q) wnext[q] = Wp[(size_t)(kk + 8 + q) * N];
            consume8(acc, wbuf, as, kk);
#pragma unroll
            for (int q = 0; q < 8; ++q) wbuf[q] = wnext[q];
        }
        consume8(acc, wbuf, as, kk);
        __syncthreads();
    }
    ull* dst = reinterpret_cast<ull*>(P + ((size_t)ks * N + n) * B_);
#pragma unroll
    for (int j = 0; j < 16; ++j) dst[j] = acc[j];
}

// ---------------- the persistent kernel ----------------
__global__ void __launch_bounds__(256, 2)
k_fused(const float* __restrict__ x, const float* __restrict__ prev_h,
        const float* __restrict__ trace, const float* __restrict__ bank,
        const float* __restrict__ W_enc, const float* __restrict__ b_enc,
        const float* __restrict__ gamma1, const float* __restrict__ beta1,
        const float* __restrict__ W_int, const float* __restrict__ b_int,
        const float* __restrict__ W_out, const float* __restrict__ b_out,
        const float* __restrict__ gamma2, const float* __restrict__ beta2,
        float* __restrict__ out) {
    __shared__ float as[64 * B_ + 64];     // 8.5 KB
    __shared__ float sb[8];
    const int tx = threadIdx.x;
    const int G = gridDim.x;

    // ---- P1: eff_mem transpose + ssq (2048 tasks) + enc gemm (4 tiles x 16 ks = 64 tasks) ----
    for (int t = blockIdx.x; t < 2048 + 4 * KS_ENC; t += G) {
        if (t < 2048) {
            int r = tx >> 3, c4 = (tx & 7) * 4;
            int m0 = (t & 63) * 32, h0 = (t >> 6) * 32;
            size_t base = (size_t)(m0 + r) * H_ + h0 + c4;
            float4 bv = *reinterpret_cast<const float4*>(bank + base);
            float4 tv = *reinterpret_cast<const float4*>(trace + base);
            float4 em;
            em.x = fmaf(0.5f, tv.x, bv.x); em.y = fmaf(0.5f, tv.y, bv.y);
            em.z = fmaf(0.5f, tv.z, bv.z); em.w = fmaf(0.5f, tv.w, bv.w);
            as[r * 33 + c4] = em.x; as[r * 33 + c4 + 1] = em.y;
            as[r * 33 + c4 + 2] = em.z; as[r * 33 + c4 + 3] = em.w;
            float ss = em.x * em.x + em.y * em.y + em.z * em.z + em.w * em.w;
#pragma unroll
            for (int o = 4; o > 0; o >>= 1) ss += __shfl_down_sync(0xffffffffu, ss, o, 8);
            if ((tx & 7) == 0) g_ssqp[(t >> 6) * M_ + m0 + r] = ss;
            __syncthreads();
            float4 o4;
            o4.x = as[(c4 + 0) * 33 + r]; o4.y = as[(c4 + 1) * 33 + r];
            o4.z = as[(c4 + 2) * 33 + r]; o4.w = as[(c4 + 3) * 33 + r];
            *reinterpret_cast<float4*>(&g_emT[(size_t)(h0 + r) * M_ + m0 + c4]) = o4;
            __syncthreads();
        } else {
            // enc gemm: A gathered from x[b][k]; tile q&3, ks q>>2, Kper=64
            int q = t - 2048;
            int tile = q & 3, ks = q >> 2;
            int n = tile * 256 + tx;
            int k0 = ks * 64;
            for (int i = tx; i < 64 * B_; i += 256) {
                int k = i >> 5, b = i & 31;
                as[k * B_ + b] = x[b * D_ + k0 + k];
            }
            __syncthreads();
            ull acc[16];
#pragma unroll
            for (int j = 0; j < 16; ++j) acc[j] = 0ull;
            const float* Wp = W_enc + (size_t)k0 * H_ + n;
            float wbuf[8];
#pragma unroll
            for (int qq = 0; qq < 8; ++qq) wbuf[qq] = Wp[(size_t)qq * H_];
            int kk = 0;
            for (; kk < 64 - 8; kk += 8) {
                float wnext[8];
#pragma unroll
                for (int qq = 0; qq < 8; ++qq) wnext[qq] = Wp[(size_t)(kk + 8 + qq) * H_];
                consume8(acc, wbuf, as, kk);
#pragma unroll
                for (int qq = 0; qq < 8; ++qq) wbuf[qq] = wnext[qq];
            }
            consume8(acc, wbuf, as, kk);
            __syncthreads();
            ull* dst = reinterpret_cast<ull*>(g_encp + ((size_t)ks * H_ + n) * B_);
#pragma unroll
            for (int j = 0; j < 16; ++j) dst[j] = acc[j];
        }
    }
    gbar();

    // ---- P2a: coalesced reduce encp + bias + relu (128 tasks) + ssqred (8 tasks) ----
    for (int t = blockIdx.x; t < 136; t += G) {
        if (t < 128) {
            int idx = t * 256 + tx;
            int h = idx >> 5;
            float s = b_enc[h];
#pragma unroll
            for (int p = 0; p < KS_ENC; ++p) s += g_encp[p * (H_ * B_) + idx];
            g_zpre[idx] = fmaxf(s, 0.f);
        } else {
            int m = (t - 128) * 256 + tx;
            float s = 0.f;
#pragma unroll
            for (int j = 0; j < 32; ++j) s += g_ssqp[j * M_ + m];
            g_rss[m] = rsqrtf(fmaxf(s, 1e-12f));
        }
    }
    gbar();

    // ---- P2b: LN over h per batch (32 tasks) ----
    for (int t = blockIdx.x; t < 32; t += G) {
        int b = t;
        float v[4], ls = 0.f, lss = 0.f;
#pragma unroll
        for (int j = 0; j < 4; ++j) {
            int h = tx + j * 256;
            float s = g_zpre[h * B_ + b];
            v[j] = s; ls += s; lss += s * s;
        }
        float mean = bsum256(ls, sb) * (1.0f / H_);
        float msq  = bsum256(lss, sb) * (1.0f / H_);
        float rstd = rsqrtf(msq - mean * mean + 1e-6f);
        float zss = 0.f;
#pragma unroll
        for (int j = 0; j < 4; ++j) {
            int h = tx + j * 256;
            float z = (v[j] - mean) * rstd * gamma1[h] + beta1[h];
            g_comb[h * B_ + b] = z;
            zss += z * z;
            g_comb[(2048 + h) * B_ + b] = prev_h[b * H_ + h];
        }
        float zs = bsum256(zss, sb);
        if (tx == 0) g_zinv[b] = rsqrtf(fmaxf(zs, 1e-12f));
    }
    gbar();

    // ---- P3: sim gemm (8 tiles x 32 ks = 256 tasks, Kper=32) ----
    for (int t = blockIdx.x; t < 8 * KS_SIM; t += G)
        gemm_full(g_comb, g_emT, g_simp, 2048, t & 7, t >> 3, 1024 / KS_SIM, 32, as);
    gbar();

    // ---- P4a: coalesced reduce simp + scale (256 tasks) ----
    for (int t = blockIdx.x; t < 256; t += G) {
        int idx = t * 256 + tx;
        int m = idx >> 5, b = idx & 31;
        float s = 0.f;
#pragma unroll
        for (int p = 0; p < KS_SIM; ++p) s += g_simp[p * (M_ * B_) + idx];
        g_sim[idx] = s * g_zinv[b] * g_rss[m] * (1.0f / 0.75f);
    }
    gbar();

    // ---- P4b: softmax over m per batch (32 tasks) ----
    for (int t = blockIdx.x; t < 32; t += G) {
        int b = t;
        float s[8];
        float mx = -3.0e38f;
#pragma unroll
        for (int j = 0; j < 8; ++j) {
            int m = tx + j * 256;
            float v = g_sim[m * B_ + b];
            s[j] = v; mx = fmaxf(mx, v);
        }
        mx = bmax256(mx, sb);
        float sum = 0.f;
#pragma unroll
        for (int j = 0; j < 8; ++j) { s[j] = expf(s[j] - mx); sum += s[j]; }
        sum = bsum256(sum, sb);
        float inv = 1.0f / sum;
#pragma unroll
        for (int j = 0; j < 8; ++j) g_attn[(tx + j * 256) * B_ + b] = s[j] * inv;
    }
    gbar();

    // ---- P5: m_t partials from emT (4 tiles x 16 ms = 64 tasks) + trace update (512 tasks) ----
    for (int t = blockIdx.x; t < 64 + 512; t += G) {
        if (t < 64) {
            int tile = t & 3, ms = t >> 2;
            int h = tile * 256 + tx;
            ull acc[16];
#pragma unroll
            for (int j = 0; j < 16; ++j) acc[j] = 0ull;
            for (int kc = 0; kc < 128; kc += 64) {
                int m0 = ms * 128 + kc;
                {
                    const float4* Ap = reinterpret_cast<const float4*>(g_attn + m0 * B_);
                    float4* asp = reinterpret_cast<float4*>(as);
                    for (int i = tx; i < 64 * 8; i += 256) asp[i] = Ap[i];
                }
                __syncthreads();
                const float4* ep = reinterpret_cast<const float4*>(g_emT + (size_t)h * M_ + m0);
                for (int kk = 0; kk < 64; kk += 8) {
                    float4 e0 = ep[kk / 4];
                    float4 e1 = ep[kk / 4 + 1];
                    float wbuf[8] = {e0.x, e0.y, e0.z, e0.w, e1.x, e1.y, e1.z, e1.w};
                    consume8(acc, wbuf, as, kk);
                }
                __syncthreads();
            }
            ull* dst = reinterpret_cast<ull*>(&g_mtp[((size_t)ms * H_ + h) * B_]);
#pragma unroll
            for (int j = 0; j < 16; ++j) dst[j] = acc[j];
        } else {
            // trace update: full batch per thread; h-tile 256, m-group of 8 (both M halves)
            int tt = t - 64;
            int h = (tt & 3) * 256 + tx;
            int m0 = (tt >> 2) * 8;
            for (int i = tx; i < 16 * B_; i += 256) {
                int r = i >> 5, b = i & 31;
                int m = (r < 8) ? (m0 + r) : (1024 + m0 + r - 8);
                as[i] = g_attn[m * B_ + b];
            }
            __syncthreads();
            ull z2[16];
            const ull* zp = reinterpret_cast<const ull*>(&g_comb[h * B_]);
#pragma unroll
            for (int j = 0; j < 16; ++j) z2[j] = zp[j];
#pragma unroll 2
            for (int mi = 0; mi < 8; ++mi) {
                int m = m0 + mi;
                ull a0 = 0ull, a1 = 0ull;
                const ull* ap0 = reinterpret_cast<const ull*>(&as[mi * B_]);
                const ull* ap1 = reinterpret_cast<const ull*>(&as[(8 + mi) * B_]);
#pragma unroll
                for (int j = 0; j < 16; ++j) { fma2(a0, ap0[j], z2[j]); fma2(a1, ap1[j], z2[j]); }
                float s0 = hadd2(a0), s1 = hadd2(a1);
                uint32_t e0 = (uint32_t)(m * 1024 + h);
                uint32_t e1 = e0 + 1048576u;
                float n0 = bits2normal(threefry_xor(0u, e0)) * 0.001f;
                float n1 = bits2normal(threefry_xor(0u, e1)) * 0.001f;
                float t0 = trace[(size_t)m * H_ + h];
                float t1 = trace[(size_t)(m + 1024) * H_ + h];
                float r0 = t0 * 0.95f + 0.05f * (s0 * (1.0f / 32.0f) + n0);
                float r1 = t1 * 0.95f + 0.05f * (s1 * (1.0f / 32.0f) + n1);
                out[32768 + m * 1024 + h] = fminf(fmaxf(r0, -0.1f), 0.1f);
                out[32768 + (m + 1024) * 1024 + h] = fminf(fmaxf(r1, -0.1f), 0.1f);
            }
            __syncthreads();
        }
    }
    gbar();

    // ---- P6: reduce m_t partials (128 tasks) ----
    for (int t = blockIdx.x; t < 128; t += G) {
        int idx = t * 256 + tx;
        float s = 0.f;
#pragma unroll
        for (int p = 0; p < MS_MT; ++p) s += g_mtp[p * (H_ * B_) + idx];
        g_comb[H_ * B_ + idx] = s;
    }
    gbar();

    // ---- P7: int gemm (12 tiles x 24 ks = 288 tasks, Kper=128) ----
    for (int t = blockIdx.x; t < 12 * KS_INT; t += G)
        gemm_full(g_comb, W_int, g_intp, 3072, t % 12, t / 12, 3072 / KS_INT, 64, as);
    gbar();

    // ---- P8: intfin (384 tasks) ----
    for (int t = blockIdx.x; t < 384; t += G) {
        int idx = t * 256 + tx;
        int n = idx >> 5;
        float s = b_int[n];
#pragma unroll
        for (int p = 0; p < KS_INT; ++p) s += g_intp[p * (K3_ * B_) + idx];
        g_hid[idx] = fmaxf(s, 0.f);
    }
    gbar();

    // ---- P9: out gemm (4 tiles x 48 ks = 192 tasks, Kper=64) ----
    for (int t = blockIdx.x; t < 4 * KS_OUT; t += G)
        gemm_full(g_hid, W_out, g_outp, 1024, t & 3, t >> 2, 3072 / KS_OUT, 64, as);
    gbar();

    // ---- P10a: coalesced reduce outp + bias + relu (128 tasks) ----
    for (int t = blockIdx.x; t < 128; t += G) {
        int idx = t * 256 + tx;
        int h = idx >> 5;
        float s = b_out[h];
#pragma unroll
        for (int p = 0; p < KS_OUT; ++p) s += g_outp[p * (H_ * B_) + idx];
        g_opre[idx] = fmaxf(s, 0.f);
    }
    gbar();

    // ---- P10b: LN -> h_t (32 tasks) ----
    for (int t = blockIdx.x; t < 32; t += G) {
        int b = t;
        float v[4], ls = 0.f, lss = 0.f;
#pragma unroll
        for (int j = 0; j < 4; ++j) {
            int h = tx + j * 256;
            float s = g_opre[h * B_ + b];
            v[j] = s; ls += s; lss += s * s;
        }
        float mean = bsum256(ls, sb) * (1.0f / H_);
        float msq  = bsum256(lss, sb) * (1.0f / H_);
        float rstd = rsqrtf(msq - mean * mean + 1e-6f);
#pragma unroll
        for (int j = 0; j < 4; ++j) {
            int h = tx + j * 256;
            out[b * H_ + h] = (v[j] - mean) * rstd * gamma2[h] + beta2[h];
        }
    }
}

// ---------------- launch ----------------
extern "C" void kernel_launch(void* const* d_in, const int* in_sizes, int n_in,
                              void* d_out, int out_size) {
    const float* x      = (const float*)d_in[0];
    const float* prev_h = (const float*)d_in[1];
    const float* trace  = (const float*)d_in[2];
    const float* bank   = (const float*)d_in[3];
    const float* W_enc  = (const float*)d_in[4];
    const float* b_enc  = (const float*)d_in[5];
    const float* gamma1 = (const float*)d_in[6];
    const float* beta1  = (const float*)d_in[7];
    const float* W_int  = (const float*)d_in[8];
    const float* b_int  = (const float*)d_in[9];
    const float* W_out  = (const float*)d_in[10];
    const float* b_out  = (const float*)d_in[11];
    const float* gamma2 = (const float*)d_in[12];
    const float* beta2  = (const float*)d_in[13];
    float* out = (float*)d_out;

    k_fused<<<GRID_, 256>>>(x, prev_h, trace, bank, W_enc, b_enc, gamma1, beta1,
                            W_int, b_int, W_out, b_out, gamma2, beta2, out);
}

// round 11
// speedup vs baseline: 3.3848x; 1.0051x over previous
#include <cuda_runtime.h>
#include <cstdint>

typedef unsigned long long ull;

#define B_  32
#define D_  1024
#define H_  1024
#define M_  2048
#define K3_ 3072

#define GRID_ 296          // 2 CTAs per SM

#define KS_ENC 16
#define KS_SIM 32
#define KS_INT 48
#define KS_OUT 64
#define MS_MT  32

// ---------------- scratch ----------------
__device__ float g_comb[K3_ * B_];              // [k][b]: 0..1023=z, 1024..2047=m_t, 2048..3071=prev_h
__device__ float g_zinv[B_];
__device__ float g_encp[KS_ENC * H_ * B_];
__device__ float g_zpre[H_ * B_];               // relu(enc+bias), pre-LN
__device__ float g_emT[H_ * M_];                // eff_mem transposed [h][m]
__device__ float g_ssqp[32 * M_];
__device__ float g_rss[M_];
__device__ float g_simp[KS_SIM * M_ * B_];
__device__ float g_sim[M_ * B_];
__device__ float g_attn[M_ * B_];
__device__ float g_mtp[MS_MT * H_ * B_];
__device__ float g_intp[KS_INT * K3_ * B_];
__device__ float g_hid[K3_ * B_];
__device__ float g_outp[KS_OUT * H_ * B_];
__device__ float g_opre[H_ * B_];

__device__ unsigned g_cnt = 0;
__device__ unsigned g_gen = 0;

// ---------------- helpers ----------------
__device__ __forceinline__ ull pack2(float w) {
    ull r; asm("mov.b64 %0, {%1, %1};" : "=l"(r) : "f"(w)); return r;
}
__device__ __forceinline__ void fma2(ull& d, ull a, ull b) {
    asm("fma.rn.f32x2 %0, %1, %2, %0;" : "+l"(d) : "l"(a), "l"(b));
}
__device__ __forceinline__ float hadd2(ull a) {
    float2 f = *reinterpret_cast<float2*>(&a); return f.x + f.y;
}
__device__ __forceinline__ void cpa16(uint32_t s, const float* g) {
    asm volatile("cp.async.cg.shared.global [%0], [%1], 16;" :: "r"(s), "l"(g) : "memory");
}
#define CPA_COMMIT() asm volatile("cp.async.commit_group;" ::: "memory")
#define CPA_WAIT1()  asm volatile("cp.async.wait_group 1;" ::: "memory")
#define CPA_WAIT0()  asm volatile("cp.async.wait_group 0;" ::: "memory")

__device__ __forceinline__ void gbar() {
    __syncthreads();
    if (threadIdx.x == 0) {
        __threadfence();
        unsigned gen = *(volatile unsigned*)&g_gen;
        if (atomicAdd(&g_cnt, 1u) == (unsigned)(gridDim.x - 1)) {
            g_cnt = 0;
            __threadfence();
            atomicAdd(&g_gen, 1u);
        } else {
            while (*(volatile unsigned*)&g_gen == gen) { __nanosleep(32); }
            __threadfence();
        }
    }
    __syncthreads();
}

__device__ __forceinline__ float bsum256(float v, float* sb) {
    int tx = threadIdx.x;
#pragma unroll
    for (int o = 16; o > 0; o >>= 1) v += __shfl_xor_sync(0xffffffffu, v, o);
    if ((tx & 31) == 0) sb[tx >> 5] = v;
    __syncthreads();
    float r = (tx < 8) ? sb[tx] : 0.f;
    if (tx < 32) {
#pragma unroll
        for (int o = 4; o > 0; o >>= 1) r += __shfl_xor_sync(0xffffffffu, r, o);
        if (tx == 0) sb[0] = r;
    }
    __syncthreads();
    r = sb[0];
    __syncthreads();
    return r;
}
__device__ __forceinline__ float bmax256(float v, float* sb) {
    int tx = threadIdx.x;
#pragma unroll
    for (int o = 16; o > 0; o >>= 1) v = fmaxf(v, __shfl_xor_sync(0xffffffffu, v, o));
    if ((tx & 31) == 0) sb[tx >> 5] = v;
    __syncthreads();
    float r = (tx < 8) ? sb[tx] : -3.0e38f;
    if (tx < 32) {
#pragma unroll
        for (int o = 4; o > 0; o >>= 1) r = fmaxf(r, __shfl_xor_sync(0xffffffffu, r, o));
        if (tx == 0) sb[0] = r;
    }
    __syncthreads();
    r = sb[0];
    __syncthreads();
    return r;
}

// jax threefry2x32, key=(0,42), partitionable: counter=(0,e), bits = o0^o1
__device__ __forceinline__ uint32_t rotl32(uint32_t x, int r) { return (x << r) | (x >> (32 - r)); }
__device__ __forceinline__ uint32_t threefry_xor(uint32_t c0, uint32_t c1) {
    const uint32_t ks0 = 0u, ks1 = 42u, ks2 = 0u ^ 42u ^ 0x1BD11BDAu;
    uint32_t x0 = c0 + ks0, x1 = c1 + ks1;
#define TF_R4(a,b,c,d) \
    x0 += x1; x1 = rotl32(x1,a); x1 ^= x0; \
    x0 += x1; x1 = rotl32(x1,b); x1 ^= x0; \
    x0 += x1; x1 = rotl32(x1,c); x1 ^= x0; \
    x0 += x1; x1 = rotl32(x1,d); x1 ^= x0;
    TF_R4(13,15,26,6)  x0 += ks1; x1 += ks2 + 1u;
    TF_R4(17,29,16,24) x0 += ks2; x1 += ks0 + 2u;
    TF_R4(13,15,26,6)  x0 += ks0; x1 += ks1 + 3u;
    TF_R4(17,29,16,24) x0 += ks1; x1 += ks2 + 4u;
    TF_R4(13,15,26,6)  x0 += ks2; x1 += ks0 + 5u;
#undef TF_R4
    return x0 ^ x1;
}
__device__ __forceinline__ float bits2normal(uint32_t bits) {
    uint32_t fb = (bits >> 9) | 0x3F800000u;
    float u01 = __uint_as_float(fb) - 1.0f;
    const float lo = -0.99999994f;
    float u = fmaf(u01, 1.99999994f, lo);
    u = fmaxf(lo, u);
    return 1.4142135623730951f * erfinvf(u);
}

// consume 8 staged-weight values against 8 smem A rows
__device__ __forceinline__ void consume8(ull* acc, const float* wbuf, const float* as, int kk) {
#pragma unroll
    for (int q = 0; q < 8; ++q) {
        ull wq = pack2(wbuf[q]);
        const ulonglong2* ap = reinterpret_cast<const ulonglong2*>(&as[(kk + q) * B_]);
#pragma unroll
        for (int j = 0; j < 8; ++j) {
            ulonglong2 a2 = ap[j];
            fma2(acc[2 * j], a2.x, wq);
            fma2(acc[2 * j + 1], a2.y, wq);
        }
    }
}

// stage Kper x 32 floats of A (contiguous [k][b]) into smem via cp.async
__device__ __forceinline__ void stageA(uint32_t sbuf, const float* Asrc, int Kper) {
    int nops = Kper * 8;
    for (int i = threadIdx.x; i < nops; i += 256)
        cpa16(sbuf + i * 16, Asrc + i * 4);
}

// pipelined split-K GEMM phase: tasks (tile, ks); A staged for task t+G while consuming t.
__device__ void gemm_phase(const float* __restrict__ A, const float* __restrict__ W,
                           float* __restrict__ P, int N, int ntiles, int KS, int Kper,
                           float* b0, float* b1, uint32_t s0, uint32_t s1) {
    const int G = gridDim.x, tx = threadIdx.x;
    const int T = ntiles * KS;
    int t0 = blockIdx.x;
    if (t0 >= T) return;
    stageA(s0, A + (size_t)(t0 / ntiles) * Kper * B_, Kper);
    CPA_COMMIT();
    int cur = 0;
    for (int t = t0; t < T; t += G) {
        int tn = t + G;
        if (tn < T) {
            stageA(cur ? s0 : s1, A + (size_t)(tn / ntiles) * Kper * B_, Kper);
            CPA_COMMIT();
            CPA_WAIT1();
        } else {
            CPA_WAIT0();
        }
        __syncthreads();
        const float* as = cur ? b1 : b0;
        int tile = t % ntiles, ks = t / ntiles;
        int n = tile * 256 + tx;
        int k0 = ks * Kper;
        ull acc[16];
#pragma unroll
        for (int j = 0; j < 16; ++j) acc[j] = 0ull;
        const float* Wp = W + (size_t)k0 * N + n;
        float wbuf[8];
#pragma unroll
        for (int q = 0; q < 8; ++q) wbuf[q] = Wp[(size_t)q * N];
        int kk = 0;
        for (; kk < Kper - 8; kk += 8) {
            float wnext[8];
#pragma unroll
            for (int q = 0; q < 8; ++q) wnext[q] = Wp[(size_t)(kk + 8 + q) * N];
            consume8(acc, wbuf, as, kk);
#pragma unroll
            for (int q = 0; q < 8; ++q) wbuf[q] = wnext[q];
        }
        consume8(acc, wbuf, as, kk);
        ull* dst = reinterpret_cast<ull*>(P + ((size_t)ks * N + n) * B_);
#pragma unroll
        for (int j = 0; j < 16; ++j) dst[j] = acc[j];
        cur ^= 1;
        __syncthreads();
    }
}

// ---------------- the persistent kernel ----------------
__global__ void __launch_bounds__(256, 2)
k_fused(const float* __restrict__ x, const float* __restrict__ prev_h,
        const float* __restrict__ trace, const float* __restrict__ bank,
        const float* __restrict__ W_enc, const float* __restrict__ b_enc,
        const float* __restrict__ gamma1, const float* __restrict__ beta1,
        const float* __restrict__ W_int, const float* __restrict__ b_int,
        const float* __restrict__ W_out, const float* __restrict__ b_out,
        const float* __restrict__ gamma2, const float* __restrict__ beta2,
        float* __restrict__ out) {
    __shared__ float buf0[64 * B_];
    __shared__ float buf1[64 * B_];
    __shared__ float sb[8];
    const int tx = threadIdx.x;
    const int G = gridDim.x;
    const uint32_t s0 = (uint32_t)__cvta_generic_to_shared(buf0);
    const uint32_t s1 = (uint32_t)__cvta_generic_to_shared(buf1);
    float* as = buf0;

    // ---- P1: eff_mem transpose + ssq (2048 tasks) + enc gemm (4 tiles x 16 ks = 64 tasks) ----
    for (int t = blockIdx.x; t < 2048 + 4 * KS_ENC; t += G) {
        if (t < 2048) {
            int r = tx >> 3, c4 = (tx & 7) * 4;
            int m0 = (t & 63) * 32, h0 = (t >> 6) * 32;
            size_t base = (size_t)(m0 + r) * H_ + h0 + c4;
            float4 bv = *reinterpret_cast<const float4*>(bank + base);
            float4 tv = *reinterpret_cast<const float4*>(trace + base);
            float4 em;
            em.x = fmaf(0.5f, tv.x, bv.x); em.y = fmaf(0.5f, tv.y, bv.y);
            em.z = fmaf(0.5f, tv.z, bv.z); em.w = fmaf(0.5f, tv.w, bv.w);
            as[r * 33 + c4] = em.x; as[r * 33 + c4 + 1] = em.y;
            as[r * 33 + c4 + 2] = em.z; as[r * 33 + c4 + 3] = em.w;
            float ss = em.x * em.x + em.y * em.y + em.z * em.z + em.w * em.w;
#pragma unroll
            for (int o = 4; o > 0; o >>= 1) ss += __shfl_down_sync(0xffffffffu, ss, o, 8);
            if ((tx & 7) == 0) g_ssqp[(t >> 6) * M_ + m0 + r] = ss;
            __syncthreads();
            float4 o4;
            o4.x = as[(c4 + 0) * 33 + r]; o4.y = as[(c4 + 1) * 33 + r];
            o4.z = as[(c4 + 2) * 33 + r]; o4.w = as[(c4 + 3) * 33 + r];
            *reinterpret_cast<float4*>(&g_emT[(size_t)(h0 + r) * M_ + m0 + c4]) = o4;
            __syncthreads();
        } else {
            // enc gemm: A gathered from x[b][k] (non-contiguous — plain staging)
            int q = t - 2048;
            int tile = q & 3, ks = q >> 2;
            int n = tile * 256 + tx;
            int k0 = ks * 64;
            for (int i = tx; i < 64 * B_; i += 256) {
                int k = i >> 5, b = i & 31;
                as[k * B_ + b] = x[b * D_ + k0 + k];
            }
            __syncthreads();
            ull acc[16];
#pragma unroll
            for (int j = 0; j < 16; ++j) acc[j] = 0ull;
            const float* Wp = W_enc + (size_t)k0 * H_ + n;
            float wbuf[8];
#pragma unroll
            for (int qq = 0; qq < 8; ++qq) wbuf[qq] = Wp[(size_t)qq * H_];
            int kk = 0;
            for (; kk < 64 - 8; kk += 8) {
                float wnext[8];
#pragma unroll
                for (int qq = 0; qq < 8; ++qq) wnext[qq] = Wp[(size_t)(kk + 8 + qq) * H_];
                consume8(acc, wbuf, as, kk);
#pragma unroll
                for (int qq = 0; qq < 8; ++qq) wbuf[qq] = wnext[qq];
            }
            consume8(acc, wbuf, as, kk);
            __syncthreads();
            ull* dst = reinterpret_cast<ull*>(g_encp + ((size_t)ks * H_ + n) * B_);
#pragma unroll
            for (int j = 0; j < 16; ++j) dst[j] = acc[j];
        }
    }
    gbar();

    // ---- P2a: coalesced reduce encp + bias + relu (128 tasks) + ssqred (8 tasks) ----
    for (int t = blockIdx.x; t < 136; t += G) {
        if (t < 128) {
            int idx = t * 256 + tx;
            int h = idx >> 5;
            float s = b_enc[h];
#pragma unroll
            for (int p = 0; p < KS_ENC; ++p) s += g_encp[p * (H_ * B_) + idx];
            g_zpre[idx] = fmaxf(s, 0.f);
        } else {
            int m = (t - 128) * 256 + tx;
            float s = 0.f;
#pragma unroll
            for (int j = 0; j < 32; ++j) s += g_ssqp[j * M_ + m];
            g_rss[m] = rsqrtf(fmaxf(s, 1e-12f));
        }
    }
    gbar();

    // ---- P2b: LN over h per batch (32 tasks) ----
    for (int t = blockIdx.x; t < 32; t += G) {
        int b = t;
        float v[4], ls = 0.f, lss = 0.f;
#pragma unroll
        for (int j = 0; j < 4; ++j) {
            int h = tx + j * 256;
            float s = g_zpre[h * B_ + b];
            v[j] = s; ls += s; lss += s * s;
        }
        float mean = bsum256(ls, sb) * (1.0f / H_);
        float msq  = bsum256(lss, sb) * (1.0f / H_);
        float rstd = rsqrtf(msq - mean * mean + 1e-6f);
        float zss = 0.f;
#pragma unroll
        for (int j = 0; j < 4; ++j) {
            int h = tx + j * 256;
            float z = (v[j] - mean) * rstd * gamma1[h] + beta1[h];
            g_comb[h * B_ + b] = z;
            zss += z * z;
            g_comb[(2048 + h) * B_ + b] = prev_h[b * H_ + h];
        }
        float zs = bsum256(zss, sb);
        if (tx == 0) g_zinv[b] = rsqrtf(fmaxf(zs, 1e-12f));
    }
    gbar();

    // ---- P3: sim gemm (8 tiles x 32 ks = 256 tasks, Kper=32, pipelined) ----
    gemm_phase(g_comb, g_emT, g_simp, 2048, 8, KS_SIM, 1024 / KS_SIM, buf0, buf1, s0, s1);
    gbar();

    // ---- P4a: coalesced reduce simp + scale (256 tasks) ----
    for (int t = blockIdx.x; t < 256; t += G) {
        int idx = t * 256 + tx;
        int m = idx >> 5, b = idx & 31;
        float s = 0.f;
#pragma unroll
        for (int p = 0; p < KS_SIM; ++p) s += g_simp[p * (M_ * B_) + idx];
        g_sim[idx] = s * g_zinv[b] * g_rss[m] * (1.0f / 0.75f);
    }
    gbar();

    // ---- P4b: softmax over m per batch (32 tasks) ----
    for (int t = blockIdx.x; t < 32; t += G) {
        int b = t;
        float s[8];
        float mx = -3.0e38f;
#pragma unroll
        for (int j = 0; j < 8; ++j) {
            int m = tx + j * 256;
            float v = g_sim[m * B_ + b];
            s[j] = v; mx = fmaxf(mx, v);
        }
        mx = bmax256(mx, sb);
        float sum = 0.f;
#pragma unroll
        for (int j = 0; j < 8; ++j) { s[j] = expf(s[j] - mx); sum += s[j]; }
        sum = bsum256(sum, sb);
        float inv = 1.0f / sum;
#pragma unroll
        for (int j = 0; j < 8; ++j) g_attn[(tx + j * 256) * B_ + b] = s[j] * inv;
    }
    gbar();

    // ---- P5: m_t partials (4 tiles x 32 ms = 128 tasks, 64 m each) + trace update (512 tasks) ----
    for (int t = blockIdx.x; t < 128 + 512; t += G) {
        if (t < 128) {
            int tile = t & 3, ms = t >> 2;
            int h = tile * 256 + tx;
            int m0 = ms * 64;
            stageA(s0, g_attn + m0 * B_, 64);
            CPA_COMMIT();
            CPA_WAIT0();
            __syncthreads();
            ull acc[16];
#pragma unroll
            for (int j = 0; j < 16; ++j) acc[j] = 0ull;
            const float4* ep = reinterpret_cast<const float4*>(g_emT + (size_t)h * M_ + m0);
            for (int kk = 0; kk < 64; kk += 8) {
                float4 e0 = ep[kk / 4];
                float4 e1 = ep[kk / 4 + 1];
                float wbuf[8] = {e0.x, e0.y, e0.z, e0.w, e1.x, e1.y, e1.z, e1.w};
                consume8(acc, wbuf, buf0, kk);
            }
            __syncthreads();
            ull* dst = reinterpret_cast<ull*>(&g_mtp[((size_t)ms * H_ + h) * B_]);
#pragma unroll
            for (int j = 0; j < 16; ++j) dst[j] = acc[j];
        } else {
            // trace update: full batch per thread; h-tile 256, m-group of 8 (both M halves)
            int tt = t - 128;
            int h = (tt & 3) * 256 + tx;
            int m0 = (tt >> 2) * 8;
            for (int i = tx; i < 16 * B_; i += 256) {
                int r = i >> 5, b = i & 31;
                int m = (r < 8) ? (m0 + r) : (1024 + m0 + r - 8);
                as[i] = g_attn[m * B_ + b];
            }
            __syncthreads();
            ull z2[16];
            const ull* zp = reinterpret_cast<const ull*>(&g_comb[h * B_]);
#pragma unroll
            for (int j = 0; j < 16; ++j) z2[j] = zp[j];
#pragma unroll 2
            for (int mi = 0; mi < 8; ++mi) {
                int m = m0 + mi;
                ull a0 = 0ull, a1 = 0ull;
                const ull* ap0 = reinterpret_cast<const ull*>(&as[mi * B_]);
                const ull* ap1 = reinterpret_cast<const ull*>(&as[(8 + mi) * B_]);
#pragma unroll
                for (int j = 0; j < 16; ++j) { fma2(a0, ap0[j], z2[j]); fma2(a1, ap1[j], z2[j]); }
                float s0v = hadd2(a0), s1v = hadd2(a1);
                uint32_t e0 = (uint32_t)(m * 1024 + h);
                uint32_t e1 = e0 + 1048576u;
                float n0 = bits2normal(threefry_xor(0u, e0)) * 0.001f;
                float n1 = bits2normal(threefry_xor(0u, e1)) * 0.001f;
                float t0v = trace[(size_t)m * H_ + h];
                float t1v = trace[(size_t)(m + 1024) * H_ + h];
                float r0 = t0v * 0.95f + 0.05f * (s0v * (1.0f / 32.0f) + n0);
                float r1 = t1v * 0.95f + 0.05f * (s1v * (1.0f / 32.0f) + n1);
                out[32768 + m * 1024 + h] = fminf(fmaxf(r0, -0.1f), 0.1f);
                out[32768 + (m + 1024) * 1024 + h] = fminf(fmaxf(r1, -0.1f), 0.1f);
            }
            __syncthreads();
        }
    }
    gbar();

    // ---- P6: reduce m_t partials (128 tasks) ----
    for (int t = blockIdx.x; t < 128; t += G) {
        int idx = t * 256 + tx;
        float s = 0.f;
#pragma unroll
        for (int p = 0; p < MS_MT; ++p) s += g_mtp[p * (H_ * B_) + idx];
        g_comb[H_ * B_ + idx] = s;
    }
    gbar();

    // ---- P7: int gemm (12 tiles x 48 ks = 576 tasks, Kper=64, pipelined) ----
    gemm_phase(g_comb, W_int, g_intp, 3072, 12, KS_INT, K3_ / KS_INT, buf0, buf1, s0, s1);
    gbar();

    // ---- P8: intfin (384 tasks) ----
    for (int t = blockIdx.x; t < 384; t += G) {
        int idx = t * 256 + tx;
        int n = idx >> 5;
        float s = b_int[n];
#pragma unroll
        for (int p = 0; p < KS_INT; ++p) s += g_intp[p * (K3_ * B_) + idx];
        g_hid[idx] = fmaxf(s, 0.f);
    }
    gbar();

    // ---- P9: out gemm (4 tiles x 64 ks = 256 tasks, Kper=48, pipelined) ----
    gemm_phase(g_hid, W_out, g_outp, 1024, 4, KS_OUT, K3_ / KS_OUT, buf0, buf1, s0, s1);
    gbar();

    // ---- P10a: coalesced reduce outp + bias + relu (128 tasks) ----
    for (int t = blockIdx.x; t < 128; t += G) {
        int idx = t * 256 + tx;
        int h = idx >> 5;
        float s = b_out[h];
#pragma unroll
        for (int p = 0; p < KS_OUT; ++p) s += g_outp[p * (H_ * B_) + idx];
        g_opre[idx] = fmaxf(s, 0.f);
    }
    gbar();

    // ---- P10b: LN -> h_t (32 tasks) ----
    for (int t = blockIdx.x; t < 32; t += G) {
        int b = t;
        float v[4], ls = 0.f, lss = 0.f;
#pragma unroll
        for (int j = 0; j < 4; ++j) {
            int h = tx + j * 256;
            float s = g_opre[h * B_ + b];
            v[j] = s; ls += s; lss += s * s;
        }
        float mean = bsum256(ls, sb) * (1.0f / H_);
        float msq  = bsum256(lss, sb) * (1.0f / H_);
        float rstd = rsqrtf(msq - mean * mean + 1e-6f);
#pragma unroll
        for (int j = 0; j < 4; ++j) {
            int h = tx + j * 256;
            out[b * H_ + h] = (v[j] - mean) * rstd * gamma2[h] + beta2[h];
        }
    }
}

// ---------------- launch ----------------
extern "C" void kernel_launch(void* const* d_in, const int* in_sizes, int n_in,
                              void* d_out, int out_size) {
    const float* x      = (const float*)d_in[0];
    const float* prev_h = (const float*)d_in[1];
    const float* trace  = (const float*)d_in[2];
    const float* bank   = (const float*)d_in[3];
    const float* W_enc  = (const float*)d_in[4];
    const float* b_enc  = (const float*)d_in[5];
    const float* gamma1 = (const float*)d_in[6];
    const float* beta1  = (const float*)d_in[7];
    const float* W_int  = (const float*)d_in[8];
    const float* b_int  = (const float*)d_in[9];
    const float* W_out  = (const float*)d_in[10];
    const float* b_out  = (const float*)d_in[11];
    const float* gamma2 = (const float*)d_in[12];
    const float* beta2  = (const float*)d_in[13];
    float* out = (float*)d_out;

    k_fused<<<GRID_, 256>>>(x, prev_h, trace, bank, W_enc, b_enc, gamma1, beta1,
                            W_int, b_int, W_out, b_out, gamma2, beta2, out);
}

// round 12
// speedup vs baseline: 3.5943x; 1.0619x over previous
#include <cuda_runtime.h>
#include <cstdint>

typedef unsigned long long ull;

#define B_  32
#define D_  1024
#define H_  1024
#define M_  2048
#define K3_ 3072

#define GRID_ 296          // 2 CTAs per SM

#define KS_ENC 16
#define KS_SIM 32
#define KS_INT 24
#define KS_OUT 48
#define MS_MT  32

// ---------------- scratch ----------------
__device__ float g_comb[K3_ * B_];              // [k][b]: 0..1023=z, 1024..2047=m_t, 2048..3071=prev_h
__device__ float g_zinv[B_];
__device__ float g_encp[KS_ENC * H_ * B_];
__device__ float g_zpre[H_ * B_];
__device__ float g_em[M_ * H_];                 // eff_mem [m][h]
__device__ float g_emT[H_ * M_];                // eff_mem transposed [h][m]
__device__ float g_ssqp[32 * M_];
__device__ float g_rss[M_];
__device__ float g_simp[KS_SIM * M_ * B_];
__device__ float g_sim[M_ * B_];
__device__ float g_attn[M_ * B_];
__device__ float g_mtp[MS_MT * H_ * B_];
__device__ float g_intp[KS_INT * K3_ * B_];
__device__ float g_hid[K3_ * B_];
__device__ float g_outp[KS_OUT * H_ * B_];
__device__ float g_opre[H_ * B_];

__device__ unsigned g_cnt = 0;
__device__ unsigned g_gen = 0;

// ---------------- helpers ----------------
__device__ __forceinline__ ull pack2(float w) {
    ull r; asm("mov.b64 %0, {%1, %1};" : "=l"(r) : "f"(w)); return r;
}
__device__ __forceinline__ void fma2(ull& d, ull a, ull b) {
    asm("fma.rn.f32x2 %0, %1, %2, %0;" : "+l"(d) : "l"(a), "l"(b));
}
__device__ __forceinline__ float hadd2(ull a) {
    float2 f = *reinterpret_cast<float2*>(&a); return f.x + f.y;
}
__device__ __forceinline__ void cpa16(uint32_t s, const float* g) {
    asm volatile("cp.async.cg.shared.global [%0], [%1], 16;" :: "r"(s), "l"(g) : "memory");
}
#define CPA_COMMIT() asm volatile("cp.async.commit_group;" ::: "memory")
#define CPA_WAIT1()  asm volatile("cp.async.wait_group 1;" ::: "memory")
#define CPA_WAIT0()  asm volatile("cp.async.wait_group 0;" ::: "memory")

__device__ __forceinline__ void gbar() {
    __syncthreads();
    if (threadIdx.x == 0) {
        __threadfence();
        unsigned gen = *(volatile unsigned*)&g_gen;
        if (atomicAdd(&g_cnt, 1u) == (unsigned)(gridDim.x - 1)) {
            g_cnt = 0;
            __threadfence();
            atomicAdd(&g_gen, 1u);
        } else {
            while (*(volatile unsigned*)&g_gen == gen) { __nanosleep(32); }
            __threadfence();
        }
    }
    __syncthreads();
}

__device__ __forceinline__ float bsum256(float v, float* sb) {
    int tx = threadIdx.x;
#pragma unroll
    for (int o = 16; o > 0; o >>= 1) v += __shfl_xor_sync(0xffffffffu, v, o);
    if ((tx & 31) == 0) sb[tx >> 5] = v;
    __syncthreads();
    float r = (tx < 8) ? sb[tx] : 0.f;
    if (tx < 32) {
#pragma unroll
        for (int o = 4; o > 0; o >>= 1) r += __shfl_xor_sync(0xffffffffu, r, o);
        if (tx == 0) sb[0] = r;
    }
    __syncthreads();
    r = sb[0];
    __syncthreads();
    return r;
}
__device__ __forceinline__ float bmax256(float v, float* sb) {
    int tx = threadIdx.x;
#pragma unroll
    for (int o = 16; o > 0; o >>= 1) v = fmaxf(v, __shfl_xor_sync(0xffffffffu, v, o));
    if ((tx & 31) == 0) sb[tx >> 5] = v;
    __syncthreads();
    float r = (tx < 8) ? sb[tx] : -3.0e38f;
    if (tx < 32) {
#pragma unroll
        for (int o = 4; o > 0; o >>= 1) r = fmaxf(r, __shfl_xor_sync(0xffffffffu, r, o));
        if (tx == 0) sb[0] = r;
    }
    __syncthreads();
    r = sb[0];
    __syncthreads();
    return r;
}

// jax threefry2x32, key=(0,42), partitionable: counter=(0,e), bits = o0^o1
__device__ __forceinline__ uint32_t rotl32(uint32_t x, int r) { return (x << r) | (x >> (32 - r)); }
__device__ __forceinline__ uint32_t threefry_xor(uint32_t c0, uint32_t c1) {
    const uint32_t ks0 = 0u, ks1 = 42u, ks2 = 0u ^ 42u ^ 0x1BD11BDAu;
    uint32_t x0 = c0 + ks0, x1 = c1 + ks1;
#define TF_R4(a,b,c,d) \
    x0 += x1; x1 = rotl32(x1,a); x1 ^= x0; \
    x0 += x1; x1 = rotl32(x1,b); x1 ^= x0; \
    x0 += x1; x1 = rotl32(x1,c); x1 ^= x0; \
    x0 += x1; x1 = rotl32(x1,d); x1 ^= x0;
    TF_R4(13,15,26,6)  x0 += ks1; x1 += ks2 + 1u;
    TF_R4(17,29,16,24) x0 += ks2; x1 += ks0 + 2u;
    TF_R4(13,15,26,6)  x0 += ks0; x1 += ks1 + 3u;
    TF_R4(17,29,16,24) x0 += ks1; x1 += ks2 + 4u;
    TF_R4(13,15,26,6)  x0 += ks2; x1 += ks0 + 5u;
#undef TF_R4
    return x0 ^ x1;
}
__device__ __forceinline__ float bits2normal(uint32_t bits) {
    uint32_t fb = (bits >> 9) | 0x3F800000u;
    float u01 = __uint_as_float(fb) - 1.0f;
    const float lo = -0.99999994f;
    float u = fmaf(u01, 1.99999994f, lo);
    u = fmaxf(lo, u);
    return 1.4142135623730951f * erfinvf(u);
}

// register-tiled consume: 4 k-rows, weights w[r] = 4 columns each, A broadcast from smem.
// acc layout: acc[c*4 + p], c=column 0..3, p=batch-pair 0..3 (8 batch elems at boff)
__device__ __forceinline__ void consume4(ull* acc, const float4* w, const float* as,
                                         int kk, int boff) {
#pragma unroll
    for (int r = 0; r < 4; ++r) {
        const ulonglong2* ap = reinterpret_cast<const ulonglong2*>(&as[(kk + r) * B_ + boff]);
        ulonglong2 a01 = ap[0];
        ulonglong2 a23 = ap[1];
        const float* wf = reinterpret_cast<const float*>(&w[r]);
#pragma unroll
        for (int c = 0; c < 4; ++c) {
            ull wq = pack2(wf[c]);
            fma2(acc[c * 4 + 0], a01.x, wq);
            fma2(acc[c * 4 + 1], a01.y, wq);
            fma2(acc[c * 4 + 2], a23.x, wq);
            fma2(acc[c * 4 + 3], a23.y, wq);
        }
    }
}

// stage Kper x 32 floats of A (contiguous [k][b]) into smem via cp.async
__device__ __forceinline__ void stageA(uint32_t sbuf, const float* Asrc, int Kper) {
    int nops = Kper * 8;
    for (int i = threadIdx.x; i < nops; i += 256)
        cpa16(sbuf + i * 16, Asrc + i * 4);
}

// register-tiled, pipelined split-K GEMM phase. Tile = 256 cols x 32 batch.
// Thread: 4 cols x 8 batch. Kper multiple of 8, <= 128.
__device__ void gemm_phase(const float* __restrict__ A, const float* __restrict__ W,
                           float* __restrict__ P, int N, int ntiles, int KS, int Kper,
                           float* b0, float* b1, uint32_t s0, uint32_t s1) {
    const int G = gridDim.x, tx = threadIdx.x;
    const int T = ntiles * KS;
    const int cg = tx & 63, bh = tx >> 6, boff = bh * 8;
    int t0 = blockIdx.x;
    if (t0 >= T) return;
    stageA(s0, A + (size_t)(t0 / ntiles) * Kper * B_, Kper);
    CPA_COMMIT();
    int cur = 0;
    for (int t = t0; t < T; t += G) {
        int tn = t + G;
        if (tn < T) {
            stageA(cur ? s0 : s1, A + (size_t)(tn / ntiles) * Kper * B_, Kper);
            CPA_COMMIT();
            CPA_WAIT1();
        } else {
            CPA_WAIT0();
        }
        __syncthreads();
        const float* as = cur ? b1 : b0;
        int tile = t % ntiles, ks = t / ntiles;
        int n = tile * 256 + cg * 4;
        int k0 = ks * Kper;
        ull acc[16];
#pragma unroll
        for (int j = 0; j < 16; ++j) acc[j] = 0ull;
        const float* Wp = W + (size_t)k0 * N + n;
        float4 wa[4], wb[4];
#pragma unroll
        for (int q = 0; q < 4; ++q) wa[q] = *reinterpret_cast<const float4*>(Wp + (size_t)q * N);
        for (int kk = 0; kk < Kper; kk += 8) {
#pragma unroll
            for (int q = 0; q < 4; ++q) wb[q] = *reinterpret_cast<const float4*>(Wp + (size_t)(kk + 4 + q) * N);
            consume4(acc, wa, as, kk, boff);
            if (kk + 8 < Kper) {
#pragma unroll
                for (int q = 0; q < 4; ++q) wa[q] = *reinterpret_cast<const float4*>(Wp + (size_t)(kk + 8 + q) * N);
            }
            consume4(acc, wb, as, kk + 4, boff);
        }
#pragma unroll
        for (int c = 0; c < 4; ++c) {
            ull* dst = reinterpret_cast<ull*>(P + ((size_t)ks * N + n + c) * B_) + bh * 4;
            dst[0] = acc[c * 4 + 0]; dst[1] = acc[c * 4 + 1];
            dst[2] = acc[c * 4 + 2]; dst[3] = acc[c * 4 + 3];
        }
        cur ^= 1;
        __syncthreads();
    }
}

// ---------------- the persistent kernel ----------------
__global__ void __launch_bounds__(256, 2)
k_fused(const float* __restrict__ x, const float* __restrict__ prev_h,
        const float* __restrict__ trace, const float* __restrict__ bank,
        const float* __restrict__ W_enc, const float* __restrict__ b_enc,
        const float* __restrict__ gamma1, const float* __restrict__ beta1,
        const float* __restrict__ W_int, const float* __restrict__ b_int,
        const float* __restrict__ W_out, const float* __restrict__ b_out,
        const float* __restrict__ gamma2, const float* __restrict__ beta2,
        float* __restrict__ out) {
    __shared__ float buf0[128 * B_];
    __shared__ float buf1[128 * B_];
    __shared__ float sb[8];
    const int tx = threadIdx.x;
    const int G = gridDim.x;
    const uint32_t s0 = (uint32_t)__cvta_generic_to_shared(buf0);
    const uint32_t s1 = (uint32_t)__cvta_generic_to_shared(buf1);
    float* as = buf0;
    const int cg = tx & 63, bh = tx >> 6, boff = bh * 8;

    // ---- P1: eff_mem transpose + em store + ssq (2048 tasks) + enc gemm (64 tasks) ----
    for (int t = blockIdx.x; t < 2048 + 4 * KS_ENC; t += G) {
        if (t < 2048) {
            int r = tx >> 3, c4 = (tx & 7) * 4;
            int m0 = (t & 63) * 32, h0 = (t >> 6) * 32;
            size_t base = (size_t)(m0 + r) * H_ + h0 + c4;
            float4 bv = *reinterpret_cast<const float4*>(bank + base);
            float4 tv = *reinterpret_cast<const float4*>(trace + base);
            float4 em;
            em.x = fmaf(0.5f, tv.x, bv.x); em.y = fmaf(0.5f, tv.y, bv.y);
            em.z = fmaf(0.5f, tv.z, bv.z); em.w = fmaf(0.5f, tv.w, bv.w);
            *reinterpret_cast<float4*>(&g_em[base]) = em;
            as[r * 33 + c4] = em.x; as[r * 33 + c4 + 1] = em.y;
            as[r * 33 + c4 + 2] = em.z; as[r * 33 + c4 + 3] = em.w;
            float ss = em.x * em.x + em.y * em.y + em.z * em.z + em.w * em.w;
#pragma unroll
            for (int o = 4; o > 0; o >>= 1) ss += __shfl_down_sync(0xffffffffu, ss, o, 8);
            if ((tx & 7) == 0) g_ssqp[(t >> 6) * M_ + m0 + r] = ss;
            __syncthreads();
            float4 o4;
            o4.x = as[(c4 + 0) * 33 + r]; o4.y = as[(c4 + 1) * 33 + r];
            o4.z = as[(c4 + 2) * 33 + r]; o4.w = as[(c4 + 3) * 33 + r];
            *reinterpret_cast<float4*>(&g_emT[(size_t)(h0 + r) * M_ + m0 + c4]) = o4;
            __syncthreads();
        } else {
            // enc gemm: A gathered from x[b][k]; register-tiled consume
            int q = t - 2048;
            int tile = q & 3, ks = q >> 2;
            int n = tile * 256 + cg * 4;
            int k0 = ks * 64;
            for (int i = tx; i < 64 * B_; i += 256) {
                int k = i >> 5, b = i & 31;
                as[k * B_ + b] = x[b * D_ + k0 + k];
            }
            __syncthreads();
            ull acc[16];
#pragma unroll
            for (int j = 0; j < 16; ++j) acc[j] = 0ull;
            const float* Wp = W_enc + (size_t)k0 * H_ + n;
            float4 wa[4], wb[4];
#pragma unroll
            for (int qq = 0; qq < 4; ++qq) wa[qq] = *reinterpret_cast<const float4*>(Wp + (size_t)qq * H_);
            for (int kk = 0; kk < 64; kk += 8) {
#pragma unroll
                for (int qq = 0; qq < 4; ++qq) wb[qq] = *reinterpret_cast<const float4*>(Wp + (size_t)(kk + 4 + qq) * H_);
                consume4(acc, wa, as, kk, boff);
                if (kk + 8 < 64) {
#pragma unroll
                    for (int qq = 0; qq < 4; ++qq) wa[qq] = *reinterpret_cast<const float4*>(Wp + (size_t)(kk + 8 + qq) * H_);
                }
                consume4(acc, wb, as, kk + 4, boff);
            }
            __syncthreads();
#pragma unroll
            for (int c = 0; c < 4; ++c) {
                ull* dst = reinterpret_cast<ull*>(g_encp + ((size_t)ks * H_ + n + c) * B_) + bh * 4;
                dst[0] = acc[c * 4 + 0]; dst[1] = acc[c * 4 + 1];
                dst[2] = acc[c * 4 + 2]; dst[3] = acc[c * 4 + 3];
            }
        }
    }
    gbar();

    // ---- P2a: coalesced reduce encp + bias + relu (128 tasks) + ssqred (8 tasks) ----
    for (int t = blockIdx.x; t < 136; t += G) {
        if (t < 128) {
            int idx = t * 256 + tx;
            int h = idx >> 5;
            float s = b_enc[h];
#pragma unroll
            for (int p = 0; p < KS_ENC; ++p) s += g_encp[p * (H_ * B_) + idx];
            g_zpre[idx] = fmaxf(s, 0.f);
        } else {
            int m = (t - 128) * 256 + tx;
            float s = 0.f;
#pragma unroll
            for (int j = 0; j < 32; ++j) s += g_ssqp[j * M_ + m];
            g_rss[m] = rsqrtf(fmaxf(s, 1e-12f));
        }
    }
    gbar();

    // ---- P2b: LN over h per batch (32 tasks) ----
    for (int t = blockIdx.x; t < 32; t += G) {
        int b = t;
        float v[4], ls = 0.f, lss = 0.f;
#pragma unroll
        for (int j = 0; j < 4; ++j) {
            int h = tx + j * 256;
            float s = g_zpre[h * B_ + b];
            v[j] = s; ls += s; lss += s * s;
        }
        float mean = bsum256(ls, sb) * (1.0f / H_);
        float msq  = bsum256(lss, sb) * (1.0f / H_);
        float rstd = rsqrtf(msq - mean * mean + 1e-6f);
        float zss = 0.f;
#pragma unroll
        for (int j = 0; j < 4; ++j) {
            int h = tx + j * 256;
            float z = (v[j] - mean) * rstd * gamma1[h] + beta1[h];
            g_comb[h * B_ + b] = z;
            zss += z * z;
            g_comb[(2048 + h) * B_ + b] = prev_h[b * H_ + h];
        }
        float zs = bsum256(zss, sb);
        if (tx == 0) g_zinv[b] = rsqrtf(fmaxf(zs, 1e-12f));
    }
    gbar();

    // ---- P3: sim gemm (8 tiles x 32 ks = 256 tasks, Kper=32) ----
    gemm_phase(g_comb, g_emT, g_simp, 2048, 8, KS_SIM, 1024 / KS_SIM, buf0, buf1, s0, s1);
    gbar();

    // ---- P4a: coalesced reduce simp + scale (256 tasks) ----
    for (int t = blockIdx.x; t < 256; t += G) {
        int idx = t * 256 + tx;
        int m = idx >> 5, b = idx & 31;
        float s = 0.f;
#pragma unroll
        for (int p = 0; p < KS_SIM; ++p) s += g_simp[p * (M_ * B_) + idx];
        g_sim[idx] = s * g_zinv[b] * g_rss[m] * (1.0f / 0.75f);
    }
    gbar();

    // ---- P4b: softmax over m per batch (32 tasks) ----
    for (int t = blockIdx.x; t < 32; t += G) {
        int b = t;
        float s[8];
        float mx = -3.0e38f;
#pragma unroll
        for (int j = 0; j < 8; ++j) {
            int m = tx + j * 256;
            float v = g_sim[m * B_ + b];
            s[j] = v; mx = fmaxf(mx, v);
        }
        mx = bmax256(mx, sb);
        float sum = 0.f;
#pragma unroll
        for (int j = 0; j < 8; ++j) { s[j] = expf(s[j] - mx); sum += s[j]; }
        sum = bsum256(sum, sb);
        float inv = 1.0f / sum;
#pragma unroll
        for (int j = 0; j < 8; ++j) g_attn[(tx + j * 256) * B_ + b] = s[j] * inv;
    }
    gbar();

    // ---- P5: m_t gemm (4 tiles x 32 ms = 128 tasks, Kper=64) then trace update (512 tasks) ----
    gemm_phase(g_attn, g_em, g_mtp, 1024, 4, MS_MT, M_ / MS_MT, buf0, buf1, s0, s1);
    for (int t = blockIdx.x; t < 512; t += G) {
        int h = (t & 3) * 256 + tx;
        int m0 = (t >> 2) * 8;
        __syncthreads();
        for (int i = tx; i < 16 * B_; i += 256) {
            int r = i >> 5, b = i & 31;
            int m = (r < 8) ? (m0 + r) : (1024 + m0 + r - 8);
            as[i] = g_attn[m * B_ + b];
        }
        __syncthreads();
        ull z2[16];
        const ull* zp = reinterpret_cast<const ull*>(&g_comb[h * B_]);
#pragma unroll
        for (int j = 0; j < 16; ++j) z2[j] = zp[j];
#pragma unroll 2
        for (int mi = 0; mi < 8; ++mi) {
            int m = m0 + mi;
            ull a0 = 0ull, a1 = 0ull;
            const ull* ap0 = reinterpret_cast<const ull*>(&as[mi * B_]);
            const ull* ap1 = reinterpret_cast<const ull*>(&as[(8 + mi) * B_]);
#pragma unroll
            for (int j = 0; j < 16; ++j) { fma2(a0, ap0[j], z2[j]); fma2(a1, ap1[j], z2[j]); }
            float s0v = hadd2(a0), s1v = hadd2(a1);
            uint32_t e0 = (uint32_t)(m * 1024 + h);
            uint32_t e1 = e0 + 1048576u;
            float n0 = bits2normal(threefry_xor(0u, e0)) * 0.001f;
            float n1 = bits2normal(threefry_xor(0u, e1)) * 0.001f;
            float t0v = trace[(size_t)m * H_ + h];
            float t1v = trace[(size_t)(m + 1024) * H_ + h];
            float r0 = t0v * 0.95f + 0.05f * (s0v * (1.0f / 32.0f) + n0);
            float r1 = t1v * 0.95f + 0.05f * (s1v * (1.0f / 32.0f) + n1);
            out[32768 + m * 1024 + h] = fminf(fmaxf(r0, -0.1f), 0.1f);
            out[32768 + (m + 1024) * 1024 + h] = fminf(fmaxf(r1, -0.1f), 0.1f);
        }
    }
    gbar();

    // ---- P6: reduce m_t partials (128 tasks) ----
    for (int t = blockIdx.x; t < 128; t += G) {
        int idx = t * 256 + tx;
        float s = 0.f;
#pragma unroll
        for (int p = 0; p < MS_MT; ++p) s += g_mtp[p * (H_ * B_) + idx];
        g_comb[H_ * B_ + idx] = s;
    }
    gbar();

    // ---- P7: int gemm (12 tiles x 24 ks = 288 tasks, Kper=128) ----
    gemm_phase(g_comb, W_int, g_intp, 3072, 12, KS_INT, K3_ / KS_INT, buf0, buf1, s0, s1);
    gbar();

    // ---- P8: intfin (384 tasks) ----
    for (int t = blockIdx.x; t < 384; t += G) {
        int idx = t * 256 + tx;
        int n = idx >> 5;
        float s = b_int[n];
#pragma unroll
        for (int p = 0; p < KS_INT; ++p) s += g_intp[p * (K3_ * B_) + idx];
        g_hid[idx] = fmaxf(s, 0.f);
    }
    gbar();

    // ---- P9: out gemm (4 tiles x 48 ks = 192 tasks, Kper=64) ----
    gemm_phase(g_hid, W_out, g_outp, 1024, 4, KS_OUT, K3_ / KS_OUT, buf0, buf1, s0, s1);
    gbar();

    // ---- P10a: coalesced reduce outp + bias + relu (128 tasks) ----
    for (int t = blockIdx.x; t < 128; t += G) {
        int idx = t * 256 + tx;
        int h = idx >> 5;
        float s = b_out[h];
#pragma unroll
        for (int p = 0; p < KS_OUT; ++p) s += g_outp[p * (H_ * B_) + idx];
        g_opre[idx] = fmaxf(s, 0.f);
    }
    gbar();

    // ---- P10b: LN -> h_t (32 tasks) ----
    for (int t = blockIdx.x; t < 32; t += G) {
        int b = t;
        float v[4], ls = 0.f, lss = 0.f;
#pragma unroll
        for (int j = 0; j < 4; ++j) {
            int h = tx + j * 256;
            float s = g_opre[h * B_ + b];
            v[j] = s; ls += s; lss += s * s;
        }
        float mean = bsum256(ls, sb) * (1.0f / H_);
        float msq  = bsum256(lss, sb) * (1.0f / H_);
        float rstd = rsqrtf(msq - mean * mean + 1e-6f);
#pragma unroll
        for (int j = 0; j < 4; ++j) {
            int h = tx + j * 256;
            out[b * H_ + h] = (v[j] - mean) * rstd * gamma2[h] + beta2[h];
        }
    }
}

// ---------------- launch ----------------
extern "C" void kernel_launch(void* const* d_in, const int* in_sizes, int n_in,
                              void* d_out, int out_size) {
    const float* x      = (const float*)d_in[0];
    const float* prev_h = (const float*)d_in[1];
    const float* trace  = (const float*)d_in[2];
    const float* bank   = (const float*)d_in[3];
    const float* W_enc  = (const float*)d_in[4];
    const float* b_enc  = (const float*)d_in[5];
    const float* gamma1 = (const float*)d_in[6];
    const float* beta1  = (const float*)d_in[7];
    const float* W_int  = (const float*)d_in[8];
    const float* b_int  = (const float*)d_in[9];
    const float* W_out  = (const float*)d_in[10];
    const float* b_out  = (const float*)d_in[11];
    const float* gamma2 = (const float*)d_in[12];
    const float* beta2  = (const float*)d_in[13];
    float* out = (float*)d_out;

    k_fused<<<GRID_, 256>>>(x, prev_h, trace, bank, W_enc, b_enc, gamma1, beta1,
                            W_int, b_int, W_out, b_out, gamma2, beta2, out);
}

// round 13
// speedup vs baseline: 3.8882x; 1.0818x over previous
#include <cuda_runtime.h>
#include <cstdint>

typedef unsigned long long ull;

#define B_  32
#define D_  1024
#define H_  1024
#define M_  2048
#define K3_ 3072

#define GRID_ 296          // 2 CTAs per SM

#define KS_ENC 16
#define KS_SIM 32
#define KS_INT 24
#define KS_OUT 48
#define MS_MT  32

// ---------------- scratch ----------------
__device__ float g_comb[K3_ * B_];              // [k][b]: 0..1023=z, 1024..2047=m_t, 2048..3071=prev_h
__device__ float g_zinv[B_];
__device__ float g_encp[KS_ENC * H_ * B_];
__device__ float g_zpre[H_ * B_];
__device__ float g_em[M_ * H_];                 // eff_mem [m][h]
__device__ float g_emT[H_ * M_];                // eff_mem transposed [h][m]
__device__ float g_ssqp[32 * M_];
__device__ float g_rss[M_];
__device__ float g_simp[KS_SIM * M_ * B_];
__device__ float g_sim[M_ * B_];
__device__ float g_attn[M_ * B_];
__device__ float g_mtp[MS_MT * H_ * B_];
__device__ float g_intp[KS_INT * K3_ * B_];
__device__ float g_hid[K3_ * B_];
__device__ float g_outp[KS_OUT * H_ * B_];
__device__ float g_opre[H_ * B_];

__device__ unsigned g_cnt = 0;
__device__ unsigned g_gen = 0;

// ---------------- helpers ----------------
__device__ __forceinline__ ull pack2(float w) {
    ull r; asm("mov.b64 %0, {%1, %1};" : "=l"(r) : "f"(w)); return r;
}
__device__ __forceinline__ void fma2(ull& d, ull a, ull b) {
    asm("fma.rn.f32x2 %0, %1, %2, %0;" : "+l"(d) : "l"(a), "l"(b));
}
__device__ __forceinline__ float hadd2(ull a) {
    float2 f = *reinterpret_cast<float2*>(&a); return f.x + f.y;
}
__device__ __forceinline__ void cpa16(uint32_t s, const float* g) {
    asm volatile("cp.async.cg.shared.global [%0], [%1], 16;" :: "r"(s), "l"(g) : "memory");
}
#define CPA_COMMIT() asm volatile("cp.async.commit_group;" ::: "memory")
#define CPA_WAIT1()  asm volatile("cp.async.wait_group 1;" ::: "memory")
#define CPA_WAIT0()  asm volatile("cp.async.wait_group 0;" ::: "memory")

// split fp32 into tf32 hi + tf32(lo) for 3xTF32 mma
__device__ __forceinline__ void tf32split(float v, uint32_t& hi, uint32_t& lo) {
    asm("cvt.rna.tf32.f32 %0, %1;" : "=r"(hi) : "f"(v));
    float l = v - __uint_as_float(hi);
    asm("cvt.rna.tf32.f32 %0, %1;" : "=r"(lo) : "f"(l));
}
// D += A(m16k8,tf32) * B(k8n8,tf32), fp32 accum
__device__ __forceinline__ void mma8(float* d, const uint32_t* a, const uint32_t* b) {
    asm("mma.sync.aligned.m16n8k8.row.col.f32.tf32.tf32.f32 "
        "{%0,%1,%2,%3}, {%4,%5,%6,%7}, {%8,%9}, {%0,%1,%2,%3};"
        : "+f"(d[0]), "+f"(d[1]), "+f"(d[2]), "+f"(d[3])
        : "r"(a[0]), "r"(a[1]), "r"(a[2]), "r"(a[3]), "r"(b[0]), "r"(b[1]));
}

__device__ __forceinline__ void gbar() {
    __syncthreads();
    if (threadIdx.x == 0) {
        __threadfence();
        unsigned gen = *(volatile unsigned*)&g_gen;
        if (atomicAdd(&g_cnt, 1u) == (unsigned)(gridDim.x - 1)) {
            g_cnt = 0;
            __threadfence();
            atomicAdd(&g_gen, 1u);
        } else {
            while (*(volatile unsigned*)&g_gen == gen) { __nanosleep(32); }
            __threadfence();
        }
    }
    __syncthreads();
}

__device__ __forceinline__ float bsum256(float v, float* sb) {
    int tx = threadIdx.x;
#pragma unroll
    for (int o = 16; o > 0; o >>= 1) v += __shfl_xor_sync(0xffffffffu, v, o);
    if ((tx & 31) == 0) sb[tx >> 5] = v;
    __syncthreads();
    float r = (tx < 8) ? sb[tx] : 0.f;
    if (tx < 32) {
#pragma unroll
        for (int o = 4; o > 0; o >>= 1) r += __shfl_xor_sync(0xffffffffu, r, o);
        if (tx == 0) sb[0] = r;
    }
    __syncthreads();
    r = sb[0];
    __syncthreads();
    return r;
}
__device__ __forceinline__ float bmax256(float v, float* sb) {
    int tx = threadIdx.x;
#pragma unroll
    for (int o = 16; o > 0; o >>= 1) v = fmaxf(v, __shfl_xor_sync(0xffffffffu, v, o));
    if ((tx & 31) == 0) sb[tx >> 5] = v;
    __syncthreads();
    float r = (tx < 8) ? sb[tx] : -3.0e38f;
    if (tx < 32) {
#pragma unroll
        for (int o = 4; o > 0; o >>= 1) r = fmaxf(r, __shfl_xor_sync(0xffffffffu, r, o));
        if (tx == 0) sb[0] = r;
    }
    __syncthreads();
    r = sb[0];
    __syncthreads();
    return r;
}

// jax threefry2x32, key=(0,42), partitionable: counter=(0,e), bits = o0^o1
__device__ __forceinline__ uint32_t rotl32(uint32_t x, int r) { return (x << r) | (x >> (32 - r)); }
__device__ __forceinline__ uint32_t threefry_xor(uint32_t c0, uint32_t c1) {
    const uint32_t ks0 = 0u, ks1 = 42u, ks2 = 0u ^ 42u ^ 0x1BD11BDAu;
    uint32_t x0 = c0 + ks0, x1 = c1 + ks1;
#define TF_R4(a,b,c,d) \
    x0 += x1; x1 = rotl32(x1,a); x1 ^= x0; \
    x0 += x1; x1 = rotl32(x1,b); x1 ^= x0; \
    x0 += x1; x1 = rotl32(x1,c); x1 ^= x0; \
    x0 += x1; x1 = rotl32(x1,d); x1 ^= x0;
    TF_R4(13,15,26,6)  x0 += ks1; x1 += ks2 + 1u;
    TF_R4(17,29,16,24) x0 += ks2; x1 += ks0 + 2u;
    TF_R4(13,15,26,6)  x0 += ks0; x1 += ks1 + 3u;
    TF_R4(17,29,16,24) x0 += ks1; x1 += ks2 + 4u;
    TF_R4(13,15,26,6)  x0 += ks2; x1 += ks0 + 5u;
#undef TF_R4
    return x0 ^ x1;
}
__device__ __forceinline__ float bits2normal(uint32_t bits) {
    uint32_t fb = (bits >> 9) | 0x3F800000u;
    float u01 = __uint_as_float(fb) - 1.0f;
    const float lo = -0.99999994f;
    float u = fmaf(u01, 1.99999994f, lo);
    u = fmaxf(lo, u);
    return 1.4142135623730951f * erfinvf(u);
}

// register-tiled FFMA consume (for enc/sim/mt): 4 k-rows, weights w[r] = 4 cols
__device__ __forceinline__ void consume4(ull* acc, const float4* w, const float* as,
                                         int kk, int boff) {
#pragma unroll
    for (int r = 0; r < 4; ++r) {
        const ulonglong2* ap = reinterpret_cast<const ulonglong2*>(&as[(kk + r) * B_ + boff]);
        ulonglong2 a01 = ap[0];
        ulonglong2 a23 = ap[1];
        const float* wf = reinterpret_cast<const float*>(&w[r]);
#pragma unroll
        for (int c = 0; c < 4; ++c) {
            ull wq = pack2(wf[c]);
            fma2(acc[c * 4 + 0], a01.x, wq);
            fma2(acc[c * 4 + 1], a01.y, wq);
            fma2(acc[c * 4 + 2], a23.x, wq);
            fma2(acc[c * 4 + 3], a23.y, wq);
        }
    }
}

// stage Kper x 32 floats of A (contiguous [k][b], stride 32) into smem via cp.async
__device__ __forceinline__ void stageA(uint32_t sbuf, const float* Asrc, int Kper) {
    int nops = Kper * 8;
    for (int i = threadIdx.x; i < nops; i += 256)
        cpa16(sbuf + i * 16, Asrc + i * 4);
}

// FFMA register-tiled pipelined split-K GEMM (enc/sim/mt path)
__device__ void gemm_phase(const float* __restrict__ A, const float* __restrict__ W,
                           float* __restrict__ P, int N, int ntiles, int KS, int Kper,
                           float* b0, float* b1, uint32_t s0, uint32_t s1) {
    const int G = gridDim.x, tx = threadIdx.x;
    const int T = ntiles * KS;
    const int cg = tx & 63, bh = tx >> 6, boff = bh * 8;
    int t0 = blockIdx.x;
    if (t0 >= T) return;
    stageA(s0, A + (size_t)(t0 / ntiles) * Kper * B_, Kper);
    CPA_COMMIT();
    int cur = 0;
    for (int t = t0; t < T; t += G) {
        int tn = t + G;
        if (tn < T) {
            stageA(cur ? s0 : s1, A + (size_t)(tn / ntiles) * Kper * B_, Kper);
            CPA_COMMIT();
            CPA_WAIT1();
        } else {
            CPA_WAIT0();
        }
        __syncthreads();
        const float* as = cur ? b1 : b0;
        int tile = t % ntiles, ks = t / ntiles;
        int n = tile * 256 + cg * 4;
        int k0 = ks * Kper;
        ull acc[16];
#pragma unroll
        for (int j = 0; j < 16; ++j) acc[j] = 0ull;
        const float* Wp = W + (size_t)k0 * N + n;
        float4 wa[4], wb[4];
#pragma unroll
        for (int q = 0; q < 4; ++q) wa[q] = *reinterpret_cast<const float4*>(Wp + (size_t)q * N);
        for (int kk = 0; kk < Kper; kk += 8) {
#pragma unroll
            for (int q = 0; q < 4; ++q) wb[q] = *reinterpret_cast<const float4*>(Wp + (size_t)(kk + 4 + q) * N);
            consume4(acc, wa, as, kk, boff);
            if (kk + 8 < Kper) {
#pragma unroll
                for (int q = 0; q < 4; ++q) wa[q] = *reinterpret_cast<const float4*>(Wp + (size_t)(kk + 8 + q) * N);
            }
            consume4(acc, wb, as, kk + 4, boff);
        }
#pragma unroll
        for (int c = 0; c < 4; ++c) {
            ull* dst = reinterpret_cast<ull*>(P + ((size_t)ks * N + n + c) * B_) + bh * 4;
            dst[0] = acc[c * 4 + 0]; dst[1] = acc[c * 4 + 1];
            dst[2] = acc[c * 4 + 2]; dst[3] = acc[c * 4 + 3];
        }
        cur ^= 1;
        __syncthreads();
    }
}

// ---- 3xTF32 tensor-core split-K GEMM (int/out path) ----
// smem layout in pool: as[Kper][40] (Kper<=128), ws0/ws1 [8][264]
#define AS_STRIDE 40
#define WS_STRIDE 264
__device__ __forceinline__ void stage_w8(uint32_t wsaddr, const float* Wsrc, int N) {
    for (int i = threadIdx.x; i < 512; i += 256) {
        int r = i >> 6, q = i & 63;
        cpa16(wsaddr + (uint32_t)(r * WS_STRIDE + q * 4) * 4, Wsrc + (size_t)r * N + q * 4);
    }
}

__device__ void gemm_tf32(const float* __restrict__ A, const float* __restrict__ W,
                          float* __restrict__ P, int N, int ntiles, int KS, int Kper,
                          float* pool) {
    const int G = gridDim.x, tx = threadIdx.x;
    const int T = ntiles * KS;
    float* as = pool;
    float* wsb0 = pool + 5120;
    float* wsb1 = pool + 5120 + 2112;
    uint32_t asa = (uint32_t)__cvta_generic_to_shared(as);
    uint32_t wsa0 = (uint32_t)__cvta_generic_to_shared(wsb0);
    uint32_t wsa1 = (uint32_t)__cvta_generic_to_shared(wsb1);
    const int w = tx >> 5, lane = tx & 31;
    const int g8 = lane >> 2, t4 = lane & 3;

    for (int t = blockIdx.x; t < T; t += G) {
        int tile = t % ntiles, ks = t / ntiles;
        int k0 = ks * Kper;
        // stage A (stride 40) + first W chunk, one commit group
        for (int i = tx; i < Kper * 8; i += 256) {
            int k = i >> 3, q = i & 7;
            cpa16(asa + (uint32_t)(k * AS_STRIDE + q * 4) * 4, A + (size_t)(k0 + k) * B_ + q * 4);
        }
        stage_w8(wsa0, W + (size_t)k0 * N + tile * 256, N);
        CPA_COMMIT();

        float acc[2][4][4];
#pragma unroll
        for (int mt = 0; mt < 2; ++mt)
#pragma unroll
            for (int nt = 0; nt < 4; ++nt)
#pragma unroll
                for (int j = 0; j < 4; ++j) acc[mt][nt][j] = 0.f;

        int cur = 0;
        for (int kk = 0; kk < Kper; kk += 8) {
            if (kk + 8 < Kper) {
                stage_w8(cur ? wsa0 : wsa1, W + (size_t)(k0 + kk + 8) * N + tile * 256, N);
                CPA_COMMIT();
                CPA_WAIT1();
            } else {
                CPA_WAIT0();
            }
            __syncthreads();
            const float* ws = cur ? wsb1 : wsb0;
            // B fragments (activations) + split
            uint32_t bhi[4][2], blo[4][2];
#pragma unroll
            for (int nt = 0; nt < 4; ++nt) {
                float v0 = as[(kk + t4) * AS_STRIDE + nt * 8 + g8];
                float v1 = as[(kk + t4 + 4) * AS_STRIDE + nt * 8 + g8];
                tf32split(v0, bhi[nt][0], blo[nt][0]);
                tf32split(v1, bhi[nt][1], blo[nt][1]);
            }
#pragma unroll
            for (int mt = 0; mt < 2; ++mt) {
                int m0 = w * 32 + mt * 16;
                float av[4];
                av[0] = ws[t4 * WS_STRIDE + m0 + g8];
                av[1] = ws[t4 * WS_STRIDE + m0 + g8 + 8];
                av[2] = ws[(t4 + 4) * WS_STRIDE + m0 + g8];
                av[3] = ws[(t4 + 4) * WS_STRIDE + m0 + g8 + 8];
                uint32_t ahi[4], alo[4];
#pragma unroll
                for (int j = 0; j < 4; ++j) tf32split(av[j], ahi[j], alo[j]);
#pragma unroll
                for (int nt = 0; nt < 4; ++nt) {
                    mma8(acc[mt][nt], ahi, bhi[nt]);
                    mma8(acc[mt][nt], ahi, blo[nt]);
                    mma8(acc[mt][nt], alo, bhi[nt]);
                }
            }
            cur ^= 1;
            __syncthreads();
        }
        // store partials: P[(ks*N + m)*32 + b]
#pragma unroll
        for (int mt = 0; mt < 2; ++mt) {
#pragma unroll
            for (int nt = 0; nt < 4; ++nt) {
                int m = tile * 256 + w * 32 + mt * 16 + g8;
                int b = nt * 8 + 2 * t4;
                float* dp = P + ((size_t)ks * N + m) * B_ + b;
                *reinterpret_cast<float2*>(dp) = make_float2(acc[mt][nt][0], acc[mt][nt][1]);
                *reinterpret_cast<float2*>(dp + 8 * B_) = make_float2(acc[mt][nt][2], acc[mt][nt][3]);
            }
        }
    }
}

// ---------------- the persistent kernel ----------------
__global__ void __launch_bounds__(256, 2)
k_fused(const float* __restrict__ x, const float* __restrict__ prev_h,
        const float* __restrict__ trace, const float* __restrict__ bank,
        const float* __restrict__ W_enc, const float* __restrict__ b_enc,
        const float* __restrict__ gamma1, const float* __restrict__ beta1,
        const float* __restrict__ W_int, const float* __restrict__ b_int,
        const float* __restrict__ W_out, const float* __restrict__ b_out,
        const float* __restrict__ gamma2, const float* __restrict__ beta2,
        float* __restrict__ out) {
    __shared__ float pool[9344];          // 36.5 KB, aliased per phase
    __shared__ float sb[8];
    float* buf0 = pool;
    float* buf1 = pool + 4096;
    const int tx = threadIdx.x;
    const int G = gridDim.x;
    const uint32_t s0 = (uint32_t)__cvta_generic_to_shared(buf0);
    const uint32_t s1 = (uint32_t)__cvta_generic_to_shared(buf1);
    float* as = buf0;
    const int cg = tx & 63, bh = tx >> 6, boff = bh * 8;

    // ---- P1: eff_mem transpose + em store + ssq (2048 tasks) + enc gemm (64 tasks) ----
    for (int t = blockIdx.x; t < 2048 + 4 * KS_ENC; t += G) {
        if (t < 2048) {
            int r = tx >> 3, c4 = (tx & 7) * 4;
            int m0 = (t & 63) * 32, h0 = (t >> 6) * 32;
            size_t base = (size_t)(m0 + r) * H_ + h0 + c4;
            float4 bv = *reinterpret_cast<const float4*>(bank + base);
            float4 tv = *reinterpret_cast<const float4*>(trace + base);
            float4 em;
            em.x = fmaf(0.5f, tv.x, bv.x); em.y = fmaf(0.5f, tv.y, bv.y);
            em.z = fmaf(0.5f, tv.z, bv.z); em.w = fmaf(0.5f, tv.w, bv.w);
            *reinterpret_cast<float4*>(&g_em[base]) = em;
            as[r * 33 + c4] = em.x; as[r * 33 + c4 + 1] = em.y;
            as[r * 33 + c4 + 2] = em.z; as[r * 33 + c4 + 3] = em.w;
            float ss = em.x * em.x + em.y * em.y + em.z * em.z + em.w * em.w;
#pragma unroll
            for (int o = 4; o > 0; o >>= 1) ss += __shfl_down_sync(0xffffffffu, ss, o, 8);
            if ((tx & 7) == 0) g_ssqp[(t >> 6) * M_ + m0 + r] = ss;
            __syncthreads();
            float4 o4;
            o4.x = as[(c4 + 0) * 33 + r]; o4.y = as[(c4 + 1) * 33 + r];
            o4.z = as[(c4 + 2) * 33 + r]; o4.w = as[(c4 + 3) * 33 + r];
            *reinterpret_cast<float4*>(&g_emT[(size_t)(h0 + r) * M_ + m0 + c4]) = o4;
            __syncthreads();
        } else {
            int q = t - 2048;
            int tile = q & 3, ks = q >> 2;
            int n = tile * 256 + cg * 4;
            int k0 = ks * 64;
            for (int i = tx; i < 64 * B_; i += 256) {
                int k = i >> 5, b = i & 31;
                as[k * B_ + b] = x[b * D_ + k0 + k];
            }
            __syncthreads();
            ull acc[16];
#pragma unroll
            for (int j = 0; j < 16; ++j) acc[j] = 0ull;
            const float* Wp = W_enc + (size_t)k0 * H_ + n;
            float4 wa[4], wb[4];
#pragma unroll
            for (int qq = 0; qq < 4; ++qq) wa[qq] = *reinterpret_cast<const float4*>(Wp + (size_t)qq * H_);
            for (int kk = 0; kk < 64; kk += 8) {
#pragma unroll
                for (int qq = 0; qq < 4; ++qq) wb[qq] = *reinterpret_cast<const float4*>(Wp + (size_t)(kk + 4 + qq) * H_);
                consume4(acc, wa, as, kk, boff);
                if (kk + 8 < 64) {
#pragma unroll
                    for (int qq = 0; qq < 4; ++qq) wa[qq] = *reinterpret_cast<const float4*>(Wp + (size_t)(kk + 8 + qq) * H_);
                }
                consume4(acc, wb, as, kk + 4, boff);
            }
            __syncthreads();
#pragma unroll
            for (int c = 0; c < 4; ++c) {
                ull* dst = reinterpret_cast<ull*>(g_encp + ((size_t)ks * H_ + n + c) * B_) + bh * 4;
                dst[0] = acc[c * 4 + 0]; dst[1] = acc[c * 4 + 1];
                dst[2] = acc[c * 4 + 2]; dst[3] = acc[c * 4 + 3];
            }
        }
    }
    gbar();

    // ---- P2a: reduce encp + bias + relu (128) + ssqred (8) ----
    for (int t = blockIdx.x; t < 136; t += G) {
        if (t < 128) {
            int idx = t * 256 + tx;
            int h = idx >> 5;
            float s = b_enc[h];
#pragma unroll
            for (int p = 0; p < KS_ENC; ++p) s += g_encp[p * (H_ * B_) + idx];
            g_zpre[idx] = fmaxf(s, 0.f);
        } else {
            int m = (t - 128) * 256 + tx;
            float s = 0.f;
#pragma unroll
            for (int j = 0; j < 32; ++j) s += g_ssqp[j * M_ + m];
            g_rss[m] = rsqrtf(fmaxf(s, 1e-12f));
        }
    }
    gbar();

    // ---- P2b: LN over h per batch (32) ----
    for (int t = blockIdx.x; t < 32; t += G) {
        int b = t;
        float v[4], ls = 0.f, lss = 0.f;
#pragma unroll
        for (int j = 0; j < 4; ++j) {
            int h = tx + j * 256;
            float s = g_zpre[h * B_ + b];
            v[j] = s; ls += s; lss += s * s;
        }
        float mean = bsum256(ls, sb) * (1.0f / H_);
        float msq  = bsum256(lss, sb) * (1.0f / H_);
        float rstd = rsqrtf(msq - mean * mean + 1e-6f);
        float zss = 0.f;
#pragma unroll
        for (int j = 0; j < 4; ++j) {
            int h = tx + j * 256;
            float z = (v[j] - mean) * rstd * gamma1[h] + beta1[h];
            g_comb[h * B_ + b] = z;
            zss += z * z;
            g_comb[(2048 + h) * B_ + b] = prev_h[b * H_ + h];
        }
        float zs = bsum256(zss, sb);
        if (tx == 0) g_zinv[b] = rsqrtf(fmaxf(zs, 1e-12f));
    }
    gbar();

    // ---- P3: sim gemm (8 tiles x 32 ks, Kper=32, FFMA) ----
    gemm_phase(g_comb, g_emT, g_simp, 2048, 8, KS_SIM, 1024 / KS_SIM, buf0, buf1, s0, s1);
    gbar();

    // ---- P4a: reduce simp + scale (256) ----
    for (int t = blockIdx.x; t < 256; t += G) {
        int idx = t * 256 + tx;
        int m = idx >> 5, b = idx & 31;
        float s = 0.f;
#pragma unroll
        for (int p = 0; p < KS_SIM; ++p) s += g_simp[p * (M_ * B_) + idx];
        g_sim[idx] = s * g_zinv[b] * g_rss[m] * (1.0f / 0.75f);
    }
    gbar();

    // ---- P4b: softmax (32) ----
    for (int t = blockIdx.x; t < 32; t += G) {
        int b = t;
        float s[8];
        float mx = -3.0e38f;
#pragma unroll
        for (int j = 0; j < 8; ++j) {
            int m = tx + j * 256;
            float v = g_sim[m * B_ + b];
            s[j] = v; mx = fmaxf(mx, v);
        }
        mx = bmax256(mx, sb);
        float sum = 0.f;
#pragma unroll
        for (int j = 0; j < 8; ++j) { s[j] = expf(s[j] - mx); sum += s[j]; }
        sum = bsum256(sum, sb);
        float inv = 1.0f / sum;
#pragma unroll
        for (int j = 0; j < 8; ++j) g_attn[(tx + j * 256) * B_ + b] = s[j] * inv;
    }
    gbar();

    // ---- P5: m_t gemm (FFMA, Kper=64) then trace update (512 tasks) ----
    gemm_phase(g_attn, g_em, g_mtp, 1024, 4, MS_MT, M_ / MS_MT, buf0, buf1, s0, s1);
    for (int t = blockIdx.x; t < 512; t += G) {
        int h = (t & 3) * 256 + tx;
        int m0 = (t >> 2) * 8;
        __syncthreads();
        for (int i = tx; i < 16 * B_; i += 256) {
            int r = i >> 5, b = i & 31;
            int m = (r < 8) ? (m0 + r) : (1024 + m0 + r - 8);
            as[i] = g_attn[m * B_ + b];
        }
        __syncthreads();
        ull z2[16];
        const ull* zp = reinterpret_cast<const ull*>(&g_comb[h * B_]);
#pragma unroll
        for (int j = 0; j < 16; ++j) z2[j] = zp[j];
#pragma unroll 2
        for (int mi = 0; mi < 8; ++mi) {
            int m = m0 + mi;
            ull a0 = 0ull, a1 = 0ull;
            const ull* ap0 = reinterpret_cast<const ull*>(&as[mi * B_]);
            const ull* ap1 = reinterpret_cast<const ull*>(&as[(8 + mi) * B_]);
#pragma unroll
            for (int j = 0; j < 16; ++j) { fma2(a0, ap0[j], z2[j]); fma2(a1, ap1[j], z2[j]); }
            float s0v = hadd2(a0), s1v = hadd2(a1);
            uint32_t e0 = (uint32_t)(m * 1024 + h);
            uint32_t e1 = e0 + 1048576u;
            float n0 = bits2normal(threefry_xor(0u, e0)) * 0.001f;
            float n1 = bits2normal(threefry_xor(0u, e1)) * 0.001f;
            float t0v = trace[(size_t)m * H_ + h];
            float t1v = trace[(size_t)(m + 1024) * H_ + h];
            float r0 = t0v * 0.95f + 0.05f * (s0v * (1.0f / 32.0f) + n0);
            float r1 = t1v * 0.95f + 0.05f * (s1v * (1.0f / 32.0f) + n1);
            out[32768 + m * 1024 + h] = fminf(fmaxf(r0, -0.1f), 0.1f);
            out[32768 + (m + 1024) * 1024 + h] = fminf(fmaxf(r1, -0.1f), 0.1f);
        }
    }
    gbar();

    // ---- P6: reduce m_t partials (128) ----
    for (int t = blockIdx.x; t < 128; t += G) {
        int idx = t * 256 + tx;
        float s = 0.f;
#pragma unroll
        for (int p = 0; p < MS_MT; ++p) s += g_mtp[p * (H_ * B_) + idx];
        g_comb[H_ * B_ + idx] = s;
    }
    gbar();

    // ---- P7: int gemm (12 tiles x 24 ks, Kper=128, 3xTF32 tensor) ----
    gemm_tf32(g_comb, W_int, g_intp, 3072, 12, KS_INT, K3_ / KS_INT, pool);
    gbar();

    // ---- P8: intfin (384) ----
    for (int t = blockIdx.x; t < 384; t += G) {
        int idx = t * 256 + tx;
        int n = idx >> 5;
        float s = b_int[n];
#pragma unroll
        for (int p = 0; p < KS_INT; ++p) s += g_intp[p * (K3_ * B_) + idx];
        g_hid[idx] = fmaxf(s, 0.f);
    }
    gbar();

    // ---- P9: out gemm (4 tiles x 48 ks, Kper=64, 3xTF32 tensor) ----
    gemm_tf32(g_hid, W_out, g_outp, 1024, 4, KS_OUT, K3_ / KS_OUT, pool);
    gbar();

    // ---- P10a: reduce outp + bias + relu (128) ----
    for (int t = blockIdx.x; t < 128; t += G) {
        int idx = t * 256 + tx;
        int h = idx >> 5;
        float s = b_out[h];
#pragma unroll
        for (int p = 0; p < KS_OUT; ++p) s += g_outp[p * (H_ * B_) + idx];
        g_opre[idx] = fmaxf(s, 0.f);
    }
    gbar();

    // ---- P10b: LN -> h_t (32) ----
    for (int t = blockIdx.x; t < 32; t += G) {
        int b = t;
        float v[4], ls = 0.f, lss = 0.f;
#pragma unroll
        for (int j = 0; j < 4; ++j) {
            int h = tx + j * 256;
            float s = g_opre[h * B_ + b];
            v[j] = s; ls += s; lss += s * s;
        }
        float mean = bsum256(ls, sb) * (1.0f / H_);
        float msq  = bsum256(lss, sb) * (1.0f / H_);
        float rstd = rsqrtf(msq - mean * mean + 1e-6f);
#pragma unroll
        for (int j = 0; j < 4; ++j) {
            int h = tx + j * 256;
            out[b * H_ + h] = (v[j] - mean) * rstd * gamma2[h] + beta2[h];
        }
    }
}

// ---------------- launch ----------------
extern "C" void kernel_launch(void* const* d_in, const int* in_sizes, int n_in,
                              void* d_out, int out_size) {
    const float* x      = (const float*)d_in[0];
    const float* prev_h = (const float*)d_in[1];
    const float* trace  = (const float*)d_in[2];
    const float* bank   = (const float*)d_in[3];
    const float* W_enc  = (const float*)d_in[4];
    const float* b_enc  = (const float*)d_in[5];
    const float* gamma1 = (const float*)d_in[6];
    const float* beta1  = (const float*)d_in[7];
    const float* W_int  = (const float*)d_in[8];
    const float* b_int  = (const float*)d_in[9];
    const float* W_out  = (const float*)d_in[10];
    const float* b_out  = (const float*)d_in[11];
    const float* gamma2 = (const float*)d_in[12];
    const float* beta2  = (const float*)d_in[13];
    float* out = (float*)d_out;

    k_fused<<<GRID_, 256>>>(x, prev_h, trace, bank, W_enc, b_enc, gamma1, beta1,
                            W_int, b_int, W_out, b_out, gamma2, beta2, out);
}

// round 14
// speedup vs baseline: 3.9571x; 1.0177x over previous
#include <cuda_runtime.h>
#include <cstdint>

typedef unsigned long long ull;

#define B_  32
#define D_  1024
#define H_  1024
#define M_  2048
#define K3_ 3072

#define GRID_ 296          // 2 CTAs per SM

#define KS_ENC 16
#define KS_SIM 32
#define KS_INT 32
#define KS_OUT 48
#define MS_MT  32

// ---------------- scratch ----------------
__device__ float g_comb[K3_ * B_];              // [k][b]: 0..1023=z, 1024..2047=m_t, 2048..3071=prev_h
__device__ float g_zinv[B_];
__device__ float g_encp[KS_ENC * H_ * B_];
__device__ float g_zpre[H_ * B_];
__device__ float g_em[M_ * H_];                 // eff_mem [m][h]
__device__ float g_emT[H_ * M_];                // eff_mem transposed [h][m]
__device__ float g_ssqp[32 * M_];
__device__ float g_rss[M_];
__device__ float g_simp[KS_SIM * M_ * B_];
__device__ float g_sim[M_ * B_];
__device__ float g_attn[M_ * B_];
__device__ float g_mtp[MS_MT * H_ * B_];
__device__ float g_intp[KS_INT * K3_ * B_];
__device__ float g_hid[K3_ * B_];
__device__ float g_outp[KS_OUT * H_ * B_];
__device__ float g_opre[H_ * B_];

__device__ unsigned g_cnt = 0;
__device__ unsigned g_gen = 0;

// ---------------- helpers ----------------
__device__ __forceinline__ ull pack2(float w) {
    ull r; asm("mov.b64 %0, {%1, %1};" : "=l"(r) : "f"(w)); return r;
}
__device__ __forceinline__ void fma2(ull& d, ull a, ull b) {
    asm("fma.rn.f32x2 %0, %1, %2, %0;" : "+l"(d) : "l"(a), "l"(b));
}
__device__ __forceinline__ float hadd2(ull a) {
    float2 f = *reinterpret_cast<float2*>(&a); return f.x + f.y;
}
__device__ __forceinline__ void cpa16(uint32_t s, const float* g) {
    asm volatile("cp.async.cg.shared.global [%0], [%1], 16;" :: "r"(s), "l"(g) : "memory");
}
#define CPA_COMMIT() asm volatile("cp.async.commit_group;" ::: "memory")
#define CPA_WAIT1()  asm volatile("cp.async.wait_group 1;" ::: "memory")
#define CPA_WAIT0()  asm volatile("cp.async.wait_group 0;" ::: "memory")

// split fp32 into tf32 hi + tf32(lo) for 3xTF32 mma
__device__ __forceinline__ void tf32split(float v, uint32_t& hi, uint32_t& lo) {
    asm("cvt.rna.tf32.f32 %0, %1;" : "=r"(hi) : "f"(v));
    float l = v - __uint_as_float(hi);
    asm("cvt.rna.tf32.f32 %0, %1;" : "=r"(lo) : "f"(l));
}
// D += A(m16k8,tf32) * B(k8n8,tf32), fp32 accum
__device__ __forceinline__ void mma8(float* d, const uint32_t* a, const uint32_t* b) {
    asm("mma.sync.aligned.m16n8k8.row.col.f32.tf32.tf32.f32 "
        "{%0,%1,%2,%3}, {%4,%5,%6,%7}, {%8,%9}, {%0,%1,%2,%3};"
        : "+f"(d[0]), "+f"(d[1]), "+f"(d[2]), "+f"(d[3])
        : "r"(a[0]), "r"(a[1]), "r"(a[2]), "r"(a[3]), "r"(b[0]), "r"(b[1]));
}

__device__ __forceinline__ void gbar() {
    __syncthreads();
    if (threadIdx.x == 0) {
        __threadfence();
        unsigned gen = *(volatile unsigned*)&g_gen;
        if (atomicAdd(&g_cnt, 1u) == (unsigned)(gridDim.x - 1)) {
            g_cnt = 0;
            __threadfence();
            atomicAdd(&g_gen, 1u);
        } else {
            while (*(volatile unsigned*)&g_gen == gen) { __nanosleep(32); }
            __threadfence();
        }
    }
    __syncthreads();
}

__device__ __forceinline__ float bsum256(float v, float* sb) {
    int tx = threadIdx.x;
#pragma unroll
    for (int o = 16; o > 0; o >>= 1) v += __shfl_xor_sync(0xffffffffu, v, o);
    if ((tx & 31) == 0) sb[tx >> 5] = v;
    __syncthreads();
    float r = (tx < 8) ? sb[tx] : 0.f;
    if (tx < 32) {
#pragma unroll
        for (int o = 4; o > 0; o >>= 1) r += __shfl_xor_sync(0xffffffffu, r, o);
        if (tx == 0) sb[0] = r;
    }
    __syncthreads();
    r = sb[0];
    __syncthreads();
    return r;
}
__device__ __forceinline__ float bmax256(float v, float* sb) {
    int tx = threadIdx.x;
#pragma unroll
    for (int o = 16; o > 0; o >>= 1) v = fmaxf(v, __shfl_xor_sync(0xffffffffu, v, o));
    if ((tx & 31) == 0) sb[tx >> 5] = v;
    __syncthreads();
    float r = (tx < 8) ? sb[tx] : -3.0e38f;
    if (tx < 32) {
#pragma unroll
        for (int o = 4; o > 0; o >>= 1) r = fmaxf(r, __shfl_xor_sync(0xffffffffu, r, o));
        if (tx == 0) sb[0] = r;
    }
    __syncthreads();
    r = sb[0];
    __syncthreads();
    return r;
}

// jax threefry2x32, key=(0,42), partitionable: counter=(0,e), bits = o0^o1
__device__ __forceinline__ uint32_t rotl32(uint32_t x, int r) { return (x << r) | (x >> (32 - r)); }
__device__ __forceinline__ uint32_t threefry_xor(uint32_t c0, uint32_t c1) {
    const uint32_t ks0 = 0u, ks1 = 42u, ks2 = 0u ^ 42u ^ 0x1BD11BDAu;
    uint32_t x0 = c0 + ks0, x1 = c1 + ks1;
#define TF_R4(a,b,c,d) \
    x0 += x1; x1 = rotl32(x1,a); x1 ^= x0; \
    x0 += x1; x1 = rotl32(x1,b); x1 ^= x0; \
    x0 += x1; x1 = rotl32(x1,c); x1 ^= x0; \
    x0 += x1; x1 = rotl32(x1,d); x1 ^= x0;
    TF_R4(13,15,26,6)  x0 += ks1; x1 += ks2 + 1u;
    TF_R4(17,29,16,24) x0 += ks2; x1 += ks0 + 2u;
    TF_R4(13,15,26,6)  x0 += ks0; x1 += ks1 + 3u;
    TF_R4(17,29,16,24) x0 += ks1; x1 += ks2 + 4u;
    TF_R4(13,15,26,6)  x0 += ks2; x1 += ks0 + 5u;
#undef TF_R4
    return x0 ^ x1;
}
__device__ __forceinline__ float bits2normal(uint32_t bits) {
    uint32_t fb = (bits >> 9) | 0x3F800000u;
    float u01 = __uint_as_float(fb) - 1.0f;
    const float lo = -0.99999994f;
    float u = fmaf(u01, 1.99999994f, lo);
    u = fmaxf(lo, u);
    return 1.4142135623730951f * erfinvf(u);
}

// register-tiled FFMA consume (enc path)
__device__ __forceinline__ void consume4(ull* acc, const float4* w, const float* as,
                                         int kk, int boff) {
#pragma unroll
    for (int r = 0; r < 4; ++r) {
        const ulonglong2* ap = reinterpret_cast<const ulonglong2*>(&as[(kk + r) * B_ + boff]);
        ulonglong2 a01 = ap[0];
        ulonglong2 a23 = ap[1];
        const float* wf = reinterpret_cast<const float*>(&w[r]);
#pragma unroll
        for (int c = 0; c < 4; ++c) {
            ull wq = pack2(wf[c]);
            fma2(acc[c * 4 + 0], a01.x, wq);
            fma2(acc[c * 4 + 1], a01.y, wq);
            fma2(acc[c * 4 + 2], a23.x, wq);
            fma2(acc[c * 4 + 3], a23.y, wq);
        }
    }
}

// ---- 3xTF32 tensor-core split-K GEMM ----
// pool layout: as[96][40] (tf32-hi after split), aslo[96][40], ws0[8][264], ws1[8][264]
#define AS_STRIDE 40
#define WS_STRIDE 264
#define ASLO_OFF  3840
#define WS0_OFF   7680
#define WS1_OFF   9792
__device__ __forceinline__ void stage_w8(uint32_t wsaddr, const float* Wsrc, int N) {
    for (int i = threadIdx.x; i < 512; i += 256) {
        int r = i >> 6, q = i & 63;
        cpa16(wsaddr + (uint32_t)(r * WS_STRIDE + q * 4) * 4, Wsrc + (size_t)r * N + q * 4);
    }
}

__device__ void gemm_tf32(const float* __restrict__ A, const float* __restrict__ W,
                          float* __restrict__ P, int N, int ntiles, int KS, int Kper,
                          float* pool) {
    const int G = gridDim.x, tx = threadIdx.x;
    const int T = ntiles * KS;
    float* as = pool;
    uint32_t* asb = reinterpret_cast<uint32_t*>(pool);
    uint32_t* aslob = reinterpret_cast<uint32_t*>(pool + ASLO_OFF);
    float* wsb0 = pool + WS0_OFF;
    float* wsb1 = pool + WS1_OFF;
    uint32_t asa = (uint32_t)__cvta_generic_to_shared(as);
    uint32_t wsa0 = (uint32_t)__cvta_generic_to_shared(wsb0);
    uint32_t wsa1 = (uint32_t)__cvta_generic_to_shared(wsb1);
    const int w = tx >> 5, lane = tx & 31;
    const int g8 = lane >> 2, t4 = lane & 3;

    for (int t = blockIdx.x; t < T; t += G) {
        int tile = t % ntiles, ks = t / ntiles;
        int k0 = ks * Kper;
        // stage A (stride 40)
        for (int i = tx; i < Kper * 8; i += 256) {
            int k = i >> 3, q = i & 7;
            cpa16(asa + (uint32_t)(k * AS_STRIDE + q * 4) * 4, A + (size_t)(k0 + k) * B_ + q * 4);
        }
        CPA_COMMIT();
        CPA_WAIT0();
        __syncthreads();
        // pre-split A in place: as -> hi, aslo -> lo
        for (int i = tx; i < Kper * B_; i += 256) {
            int k = i >> 5, b = i & 31;
            int idx = k * AS_STRIDE + b;
            uint32_t hi, lo;
            tf32split(as[idx], hi, lo);
            asb[idx] = hi;
            aslob[idx] = lo;
        }
        stage_w8(wsa0, W + (size_t)k0 * N + tile * 256, N);
        CPA_COMMIT();
        __syncthreads();

        float acc[2][4][4];
#pragma unroll
        for (int mt = 0; mt < 2; ++mt)
#pragma unroll
            for (int nt = 0; nt < 4; ++nt)
#pragma unroll
                for (int j = 0; j < 4; ++j) acc[mt][nt][j] = 0.f;

        int cur = 0;
        for (int kk = 0; kk < Kper; kk += 8) {
            if (kk + 8 < Kper) {
                stage_w8(cur ? wsa0 : wsa1, W + (size_t)(k0 + kk + 8) * N + tile * 256, N);
                CPA_COMMIT();
                CPA_WAIT1();
            } else {
                CPA_WAIT0();
            }
            __syncthreads();
            const float* ws = cur ? wsb1 : wsb0;
            // B fragments: plain uint loads of pre-split activations
            uint32_t bhi[4][2], blo[4][2];
#pragma unroll
            for (int nt = 0; nt < 4; ++nt) {
                int i0 = (kk + t4) * AS_STRIDE + nt * 8 + g8;
                int i1 = (kk + t4 + 4) * AS_STRIDE + nt * 8 + g8;
                bhi[nt][0] = asb[i0]; blo[nt][0] = aslob[i0];
                bhi[nt][1] = asb[i1]; blo[nt][1] = aslob[i1];
            }
#pragma unroll
            for (int mt = 0; mt < 2; ++mt) {
                int m0 = w * 32 + mt * 16;
                float av[4];
                av[0] = ws[t4 * WS_STRIDE + m0 + g8];
                av[1] = ws[t4 * WS_STRIDE + m0 + g8 + 8];
                av[2] = ws[(t4 + 4) * WS_STRIDE + m0 + g8];
                av[3] = ws[(t4 + 4) * WS_STRIDE + m0 + g8 + 8];
                uint32_t ahi[4], alo[4];
#pragma unroll
                for (int j = 0; j < 4; ++j) tf32split(av[j], ahi[j], alo[j]);
#pragma unroll
                for (int nt = 0; nt < 4; ++nt) {
                    mma8(acc[mt][nt], ahi, bhi[nt]);
                    mma8(acc[mt][nt], ahi, blo[nt]);
                    mma8(acc[mt][nt], alo, bhi[nt]);
                }
            }
            cur ^= 1;
            __syncthreads();
        }
#pragma unroll
        for (int mt = 0; mt < 2; ++mt) {
#pragma unroll
            for (int nt = 0; nt < 4; ++nt) {
                int m = tile * 256 + w * 32 + mt * 16 + g8;
                int b = nt * 8 + 2 * t4;
                float* dp = P + ((size_t)ks * N + m) * B_ + b;
                *reinterpret_cast<float2*>(dp) = make_float2(acc[mt][nt][0], acc[mt][nt][1]);
                *reinterpret_cast<float2*>(dp + 8 * B_) = make_float2(acc[mt][nt][2], acc[mt][nt][3]);
            }
        }
    }
}

// ---------------- the persistent kernel ----------------
__global__ void __launch_bounds__(256, 2)
k_fused(const float* __restrict__ x, const float* __restrict__ prev_h,
        const float* __restrict__ trace, const float* __restrict__ bank,
        const float* __restrict__ W_enc, const float* __restrict__ b_enc,
        const float* __restrict__ gamma1, const float* __restrict__ beta1,
        const float* __restrict__ W_int, const float* __restrict__ b_int,
        const float* __restrict__ W_out, const float* __restrict__ b_out,
        const float* __restrict__ gamma2, const float* __restrict__ beta2,
        float* __restrict__ out) {
    __shared__ float pool[11904];         // 46.5 KB, aliased per phase
    __shared__ float sb[8];
    float* as = pool;
    const int tx = threadIdx.x;
    const int G = gridDim.x;
    const int cg = tx & 63, bh = tx >> 6, boff = bh * 8;

    // ---- P1: eff_mem transpose + em store + ssq (2048 tasks) + enc gemm (64 tasks) ----
    for (int t = blockIdx.x; t < 2048 + 4 * KS_ENC; t += G) {
        if (t < 2048) {
            int r = tx >> 3, c4 = (tx & 7) * 4;
            int m0 = (t & 63) * 32, h0 = (t >> 6) * 32;
            size_t base = (size_t)(m0 + r) * H_ + h0 + c4;
            float4 bv = *reinterpret_cast<const float4*>(bank + base);
            float4 tv = *reinterpret_cast<const float4*>(trace + base);
            float4 em;
            em.x = fmaf(0.5f, tv.x, bv.x); em.y = fmaf(0.5f, tv.y, bv.y);
            em.z = fmaf(0.5f, tv.z, bv.z); em.w = fmaf(0.5f, tv.w, bv.w);
            *reinterpret_cast<float4*>(&g_em[base]) = em;
            as[r * 33 + c4] = em.x; as[r * 33 + c4 + 1] = em.y;
            as[r * 33 + c4 + 2] = em.z; as[r * 33 + c4 + 3] = em.w;
            float ss = em.x * em.x + em.y * em.y + em.z * em.z + em.w * em.w;
#pragma unroll
            for (int o = 4; o > 0; o >>= 1) ss += __shfl_down_sync(0xffffffffu, ss, o, 8);
            if ((tx & 7) == 0) g_ssqp[(t >> 6) * M_ + m0 + r] = ss;
            __syncthreads();
            float4 o4;
            o4.x = as[(c4 + 0) * 33 + r]; o4.y = as[(c4 + 1) * 33 + r];
            o4.z = as[(c4 + 2) * 33 + r]; o4.w = as[(c4 + 3) * 33 + r];
            *reinterpret_cast<float4*>(&g_emT[(size_t)(h0 + r) * M_ + m0 + c4]) = o4;
            __syncthreads();
        } else {
            int q = t - 2048;
            int tile = q & 3, ks = q >> 2;
            int n = tile * 256 + cg * 4;
            int k0 = ks * 64;
            for (int i = tx; i < 64 * B_; i += 256) {
                int k = i >> 5, b = i & 31;
                as[k * B_ + b] = x[b * D_ + k0 + k];
            }
            __syncthreads();
            ull acc[16];
#pragma unroll
            for (int j = 0; j < 16; ++j) acc[j] = 0ull;
            const float* Wp = W_enc + (size_t)k0 * H_ + n;
            float4 wa[4], wb[4];
#pragma unroll
            for (int qq = 0; qq < 4; ++qq) wa[qq] = *reinterpret_cast<const float4*>(Wp + (size_t)qq * H_);
            for (int kk = 0; kk < 64; kk += 8) {
#pragma unroll
                for (int qq = 0; qq < 4; ++qq) wb[qq] = *reinterpret_cast<const float4*>(Wp + (size_t)(kk + 4 + qq) * H_);
                consume4(acc, wa, as, kk, boff);
                if (kk + 8 < 64) {
#pragma unroll
                    for (int qq = 0; qq < 4; ++qq) wa[qq] = *reinterpret_cast<const float4*>(Wp + (size_t)(kk + 8 + qq) * H_);
                }
                consume4(acc, wb, as, kk + 4, boff);
            }
            __syncthreads();
#pragma unroll
            for (int c = 0; c < 4; ++c) {
                ull* dst = reinterpret_cast<ull*>(g_encp + ((size_t)ks * H_ + n + c) * B_) + bh * 4;
                dst[0] = acc[c * 4 + 0]; dst[1] = acc[c * 4 + 1];
                dst[2] = acc[c * 4 + 2]; dst[3] = acc[c * 4 + 3];
            }
        }
    }
    gbar();

    // ---- P2a: reduce encp + bias + relu (128) + ssqred (8) ----
    for (int t = blockIdx.x; t < 136; t += G) {
        if (t < 128) {
            int idx = t * 256 + tx;
            int h = idx >> 5;
            float s = b_enc[h];
#pragma unroll
            for (int p = 0; p < KS_ENC; ++p) s += g_encp[p * (H_ * B_) + idx];
            g_zpre[idx] = fmaxf(s, 0.f);
        } else {
            int m = (t - 128) * 256 + tx;
            float s = 0.f;
#pragma unroll
            for (int j = 0; j < 32; ++j) s += g_ssqp[j * M_ + m];
            g_rss[m] = rsqrtf(fmaxf(s, 1e-12f));
        }
    }
    gbar();

    // ---- P2b: LN over h per batch (32) ----
    for (int t = blockIdx.x; t < 32; t += G) {
        int b = t;
        float v[4], ls = 0.f, lss = 0.f;
#pragma unroll
        for (int j = 0; j < 4; ++j) {
            int h = tx + j * 256;
            float s = g_zpre[h * B_ + b];
            v[j] = s; ls += s; lss += s * s;
        }
        float mean = bsum256(ls, sb) * (1.0f / H_);
        float msq  = bsum256(lss, sb) * (1.0f / H_);
        float rstd = rsqrtf(msq - mean * mean + 1e-6f);
        float zss = 0.f;
#pragma unroll
        for (int j = 0; j < 4; ++j) {
            int h = tx + j * 256;
            float z = (v[j] - mean) * rstd * gamma1[h] + beta1[h];
            g_comb[h * B_ + b] = z;
            zss += z * z;
            g_comb[(2048 + h) * B_ + b] = prev_h[b * H_ + h];
        }
        float zs = bsum256(zss, sb);
        if (tx == 0) g_zinv[b] = rsqrtf(fmaxf(zs, 1e-12f));
    }
    gbar();

    // ---- P3: sim gemm (8 tiles x 32 ks, Kper=32, tensor) ----
    gemm_tf32(g_comb, g_emT, g_simp, 2048, 8, KS_SIM, 1024 / KS_SIM, pool);
    gbar();

    // ---- P4a: reduce simp + scale (256) ----
    for (int t = blockIdx.x; t < 256; t += G) {
        int idx = t * 256 + tx;
        int m = idx >> 5, b = idx & 31;
        float s = 0.f;
#pragma unroll
        for (int p = 0; p < KS_SIM; ++p) s += g_simp[p * (M_ * B_) + idx];
        g_sim[idx] = s * g_zinv[b] * g_rss[m] * (1.0f / 0.75f);
    }
    gbar();

    // ---- P4b: softmax (32) ----
    for (int t = blockIdx.x; t < 32; t += G) {
        int b = t;
        float s[8];
        float mx = -3.0e38f;
#pragma unroll
        for (int j = 0; j < 8; ++j) {
            int m = tx + j * 256;
            float v = g_sim[m * B_ + b];
            s[j] = v; mx = fmaxf(mx, v);
        }
        mx = bmax256(mx, sb);
        float sum = 0.f;
#pragma unroll
        for (int j = 0; j < 8; ++j) { s[j] = expf(s[j] - mx); sum += s[j]; }
        sum = bsum256(sum, sb);
        float inv = 1.0f / sum;
#pragma unroll
        for (int j = 0; j < 8; ++j) g_attn[(tx + j * 256) * B_ + b] = s[j] * inv;
    }
    gbar();

    // ---- P5: m_t gemm (4 tiles x 32 ks, Kper=64, tensor) then trace update (512 tasks) ----
    gemm_tf32(g_attn, g_em, g_mtp, 1024, 4, MS_MT, M_ / MS_MT, pool);
    for (int t = blockIdx.x; t < 512; t += G) {
        int h = (t & 3) * 256 + tx;
        int m0 = (t >> 2) * 8;
        __syncthreads();
        for (int i = tx; i < 16 * B_; i += 256) {
            int r = i >> 5, b = i & 31;
            int m = (r < 8) ? (m0 + r) : (1024 + m0 + r - 8);
            as[i] = g_attn[m * B_ + b];
        }
        __syncthreads();
        ull z2[16];
        const ull* zp = reinterpret_cast<const ull*>(&g_comb[h * B_]);
#pragma unroll
        for (int j = 0; j < 16; ++j) z2[j] = zp[j];
#pragma unroll 2
        for (int mi = 0; mi < 8; ++mi) {
            int m = m0 + mi;
            ull a0 = 0ull, a1 = 0ull;
            const ull* ap0 = reinterpret_cast<const ull*>(&as[mi * B_]);
            const ull* ap1 = reinterpret_cast<const ull*>(&as[(8 + mi) * B_]);
#pragma unroll
            for (int j = 0; j < 16; ++j) { fma2(a0, ap0[j], z2[j]); fma2(a1, ap1[j], z2[j]); }
            float s0v = hadd2(a0), s1v = hadd2(a1);
            uint32_t e0 = (uint32_t)(m * 1024 + h);
            uint32_t e1 = e0 + 1048576u;
            float n0 = bits2normal(threefry_xor(0u, e0)) * 0.001f;
            float n1 = bits2normal(threefry_xor(0u, e1)) * 0.001f;
            float t0v = trace[(size_t)m * H_ + h];
            float t1v = trace[(size_t)(m + 1024) * H_ + h];
            float r0 = t0v * 0.95f + 0.05f * (s0v * (1.0f / 32.0f) + n0);
            float r1 = t1v * 0.95f + 0.05f * (s1v * (1.0f / 32.0f) + n1);
            out[32768 + m * 1024 + h] = fminf(fmaxf(r0, -0.1f), 0.1f);
            out[32768 + (m + 1024) * 1024 + h] = fminf(fmaxf(r1, -0.1f), 0.1f);
        }
    }
    gbar();

    // ---- P6: reduce m_t partials (128) ----
    for (int t = blockIdx.x; t < 128; t += G) {
        int idx = t * 256 + tx;
        float s = 0.f;
#pragma unroll
        for (int p = 0; p < MS_MT; ++p) s += g_mtp[p * (H_ * B_) + idx];
        g_comb[H_ * B_ + idx] = s;
    }
    gbar();

    // ---- P7: int gemm (12 tiles x 32 ks, Kper=96, tensor) ----
    gemm_tf32(g_comb, W_int, g_intp, 3072, 12, KS_INT, K3_ / KS_INT, pool);
    gbar();

    // ---- P8: intfin (384) ----
    for (int t = blockIdx.x; t < 384; t += G) {
        int idx = t * 256 + tx;
        int n = idx >> 5;
        float s = b_int[n];
#pragma unroll
        for (int p = 0; p < KS_INT; ++p) s += g_intp[p * (K3_ * B_) + idx];
        g_hid[idx] = fmaxf(s, 0.f);
    }
    gbar();

    // ---- P9: out gemm (4 tiles x 48 ks, Kper=64, tensor) ----
    gemm_tf32(g_hid, W_out, g_outp, 1024, 4, KS_OUT, K3_ / KS_OUT, pool);
    gbar();

    // ---- P10a: reduce outp + bias + relu (128) ----
    for (int t = blockIdx.x; t < 128; t += G) {
        int idx = t * 256 + tx;
        int h = idx >> 5;
        float s = b_out[h];
#pragma unroll
        for (int p = 0; p < KS_OUT; ++p) s += g_outp[p * (H_ * B_) + idx];
        g_opre[idx] = fmaxf(s, 0.f);
    }
    gbar();

    // ---- P10b: LN -> h_t (32) ----
    for (int t = blockIdx.x; t < 32; t += G) {
        int b = t;
        float v[4], ls = 0.f, lss = 0.f;
#pragma unroll
        for (int j = 0; j < 4; ++j) {
            int h = tx + j * 256;
            float s = g_opre[h * B_ + b];
            v[j] = s; ls += s; lss += s * s;
        }
        float mean = bsum256(ls, sb) * (1.0f / H_);
        float msq  = bsum256(lss, sb) * (1.0f / H_);
        float rstd = rsqrtf(msq - mean * mean + 1e-6f);
#pragma unroll
        for (int j = 0; j < 4; ++j) {
            int h = tx + j * 256;
            out[b * H_ + h] = (v[j] - mean) * rstd * gamma2[h] + beta2[h];
        }
    }
}

// ---------------- launch ----------------
extern "C" void kernel_launch(void* const* d_in, const int* in_sizes, int n_in,
                              void* d_out, int out_size) {
    const float* x      = (const float*)d_in[0];
    const float* prev_h = (const float*)d_in[1];
    const float* trace  = (const float*)d_in[2];
    const float* bank   = (const float*)d_in[3];
    const float* W_enc  = (const float*)d_in[4];
    const float* b_enc  = (const float*)d_in[5];
    const float* gamma1 = (const float*)d_in[6];
    const float* beta1  = (const float*)d_in[7];
    const float* W_int  = (const float*)d_in[8];
    const float* b_int  = (const float*)d_in[9];
    const float* W_out  = (const float*)d_in[10];
    const float* b_out  = (const float*)d_in[11];
    const float* gamma2 = (const float*)d_in[12];
    const float* beta2  = (const float*)d_in[13];
    float* out = (float*)d_out;

    k_fused<<<GRID_, 256>>>(x, prev_h, trace, bank, W_enc, b_enc, gamma1, beta1,
                            W_int, b_int, W_out, b_out, gamma2, beta2, out);
}